// round 1
// baseline (speedup 1.0000x reference)
#include <cuda_runtime.h>
#include <cuda_bf16.h>

#define BB 2
#define TT 2048
#define DD 1024
#define HH 16
#define DKK 64
#define FFF 4096

// ---------------- scratch (static device memory; no allocs) ----------------
__device__ float g_q[(size_t)BB * HH * TT * DKK];        // 4M
__device__ float g_k[(size_t)BB * HH * TT * DKK];        // 4M
__device__ float g_v[(size_t)BB * HH * TT * DKK];        // 4M
__device__ float g_scores[(size_t)BB * HH * TT * TT];    // 134M (536MB)
__device__ float g_ocat[(size_t)BB * TT * DD];           // 4M
__device__ float g_tmp[(size_t)BB * TT * DD];            // 4M
__device__ float g_out1[(size_t)BB * TT * DD];           // 4M
__device__ float g_ffh[(size_t)BB * TT * FFF];           // 16M

// ---------------- generic batched SGEMM: C = alpha*A*B (+bias)(relu) -------
// 64x64 tile, BK=16, 256 threads, 4x4 per thread. Shapes assumed divisible.
template <bool TRANSB, bool BIAS, bool RELU>
__global__ void sgemm64(const float* __restrict__ A, const float* __restrict__ B,
                        float* __restrict__ C, const float* __restrict__ bias,
                        int M, int N, int K, int lda, int ldb, int ldc, float alpha,
                        long soA, long siA, long soB, long siB, long soC, long siC,
                        int inner)
{
    int z  = blockIdx.z;
    int zo = z / inner, zi = z % inner;
    A += zo * soA + zi * siA;
    B += zo * soB + zi * siB;
    C += zo * soC + zi * siC;

    __shared__ float As[16][65];
    __shared__ float Bs[16][65];

    int tid = threadIdx.x;
    int tx = tid & 15, ty = tid >> 4;
    int bm = blockIdx.y * 64, bn = blockIdx.x * 64;

    float acc[4][4] = {};

    for (int k0 = 0; k0 < K; k0 += 16) {
        #pragma unroll
        for (int i = 0; i < 4; i++) {
            int idx = tid + i * 256;
            int m = idx >> 4, kk = idx & 15;
            As[kk][m] = A[(long)(bm + m) * lda + (k0 + kk)];
        }
        #pragma unroll
        for (int i = 0; i < 4; i++) {
            int idx = tid + i * 256;
            if (TRANSB) {
                int n = idx >> 4, kk = idx & 15;
                Bs[kk][n] = B[(long)(bn + n) * ldb + (k0 + kk)];
            } else {
                int kk = idx >> 6, n = idx & 63;
                Bs[kk][n] = B[(long)(k0 + kk) * ldb + (bn + n)];
            }
        }
        __syncthreads();
        #pragma unroll
        for (int kk = 0; kk < 16; kk++) {
            float a[4], b[4];
            #pragma unroll
            for (int i = 0; i < 4; i++) a[i] = As[kk][ty * 4 + i];
            #pragma unroll
            for (int j = 0; j < 4; j++) b[j] = Bs[kk][tx * 4 + j];
            #pragma unroll
            for (int i = 0; i < 4; i++)
                #pragma unroll
                for (int j = 0; j < 4; j++)
                    acc[i][j] += a[i] * b[j];
        }
        __syncthreads();
    }

    #pragma unroll
    for (int i = 0; i < 4; i++) {
        int row = bm + ty * 4 + i;
        #pragma unroll
        for (int j = 0; j < 4; j++) {
            int col = bn + tx * 4 + j;
            float v = acc[i][j] * alpha;
            if (BIAS) v += bias[col];
            if (RELU) v = fmaxf(v, 0.f);
            C[(long)row * ldc + col] = v;
        }
    }
}

// --------- softmax over the QUERY axis (axis=-2): per (z, s) column --------
__global__ void softmax_q_kernel(float* __restrict__ s, int T)
{
    int z = blockIdx.y;
    int col = blockIdx.x * blockDim.x + threadIdx.x;
    float* base = s + (long)z * T * T + col;

    float m = -1e30f, l = 0.f;
    for (int q = 0; q < T; q++) {
        float v = base[(long)q * T];
        float nm = fmaxf(m, v);
        l = l * __expf(m - nm) + __expf(v - nm);
        m = nm;
    }
    float inv = 1.f / l;
    for (int q = 0; q < T; q++) {
        float v = base[(long)q * T];
        base[(long)q * T] = __expf(v - m) * inv;
    }
}

// --------- out = meanstd_norm(a + b), ddof=1, D=1024, one block per row ----
__global__ void add_norm_kernel(const float* __restrict__ a, const float* __restrict__ b,
                                float* __restrict__ out)
{
    const int D = DD;
    long r = blockIdx.x;
    const float* pa = a + r * D;
    const float* pb = b + r * D;
    int tid = threadIdx.x;

    float y[4];
    float sum = 0.f;
    #pragma unroll
    for (int i = 0; i < 4; i++) {
        y[i] = pa[tid + i * 256] + pb[tid + i * 256];
        sum += y[i];
    }

    __shared__ float red[8];
    #pragma unroll
    for (int o = 16; o > 0; o >>= 1) sum += __shfl_xor_sync(~0u, sum, o);
    if ((tid & 31) == 0) red[tid >> 5] = sum;
    __syncthreads();
    if (tid < 32) {
        float v = (tid < 8) ? red[tid] : 0.f;
        #pragma unroll
        for (int o = 4; o > 0; o >>= 1) v += __shfl_xor_sync(~0u, v, o);
        if (tid == 0) red[0] = v;
    }
    __syncthreads();
    float mean = red[0] / D;
    __syncthreads();  // protect red[] before reuse

    float vs = 0.f;
    #pragma unroll
    for (int i = 0; i < 4; i++) {
        float d = y[i] - mean;
        vs += d * d;
    }
    #pragma unroll
    for (int o = 16; o > 0; o >>= 1) vs += __shfl_xor_sync(~0u, vs, o);
    if ((tid & 31) == 0) red[tid >> 5] = vs;
    __syncthreads();
    if (tid < 32) {
        float v = (tid < 8) ? red[tid] : 0.f;
        #pragma unroll
        for (int o = 4; o > 0; o >>= 1) v += __shfl_xor_sync(~0u, v, o);
        if (tid == 0) red[0] = v;
    }
    __syncthreads();
    float inv = rsqrtf(red[0] / (float)(D - 1));

    #pragma unroll
    for (int i = 0; i < 4; i++)
        out[r * D + tid + i * 256] = (y[i] - mean) * inv;
}

// ---------------------------------------------------------------------------
extern "C" void kernel_launch(void* const* d_in, const int* in_sizes, int n_in,
                              void* d_out, int out_size)
{
    const float* x  = (const float*)d_in[0];
    const float* Wq = (const float*)d_in[1];
    const float* Wk = (const float*)d_in[2];
    const float* Wv = (const float*)d_in[3];
    const float* Wo = (const float*)d_in[4];
    const float* W1 = (const float*)d_in[5];
    const float* b1 = (const float*)d_in[6];
    const float* W2 = (const float*)d_in[7];
    const float* b2 = (const float*)d_in[8];
    float* out = (float*)d_out;

    void *pq, *pk, *pv, *ps, *po, *pt, *p1, *pf;
    cudaGetSymbolAddress(&pq, g_q);
    cudaGetSymbolAddress(&pk, g_k);
    cudaGetSymbolAddress(&pv, g_v);
    cudaGetSymbolAddress(&ps, g_scores);
    cudaGetSymbolAddress(&po, g_ocat);
    cudaGetSymbolAddress(&pt, g_tmp);
    cudaGetSymbolAddress(&p1, g_out1);
    cudaGetSymbolAddress(&pf, g_ffh);
    float* q  = (float*)pq;
    float* k  = (float*)pk;
    float* v  = (float*)pv;
    float* sc = (float*)ps;
    float* oc = (float*)po;
    float* tp = (float*)pt;
    float* o1 = (float*)p1;
    float* fh = (float*)pf;

    const long TD  = (long)TT * DD;          // x per-batch stride
    const long HD  = (long)DD * DKK;         // W per-head stride
    const long HT  = (long)TT * DKK;         // q/k/v per-(b,h) stride
    const long BHT = (long)HH * HT;          // q/k/v per-b stride
    const long TTl = (long)TT * TT;

    // 1) Q,K,V projections: per (b,h): [T,D] x [D,64] -> [T,64]
    dim3 gproj(1, TT / 64, BB * HH);
    sgemm64<false, false, false><<<gproj, 256>>>(x, Wq, q, nullptr,
        TT, DKK, DD, DD, DKK, DKK, 1.f, TD, 0, 0, HD, BHT, HT, HH);
    sgemm64<false, false, false><<<gproj, 256>>>(x, Wk, k, nullptr,
        TT, DKK, DD, DD, DKK, DKK, 1.f, TD, 0, 0, HD, BHT, HT, HH);
    sgemm64<false, false, false><<<gproj, 256>>>(x, Wv, v, nullptr,
        TT, DKK, DD, DD, DKK, DKK, 1.f, TD, 0, 0, HD, BHT, HT, HH);

    // 2) scores = q @ k^T / sqrt(dk): per (b,h): [T,64] x [64,T] -> [T,T]
    dim3 gsc(TT / 64, TT / 64, BB * HH);
    sgemm64<true, false, false><<<gsc, 256>>>(q, k, sc, nullptr,
        TT, TT, DKK, DKK, DKK, TT, 0.125f, HT, 0, HT, 0, TTl, 0, 1);

    // 3) softmax over query axis (column softmax)
    dim3 gsm(TT / 256, BB * HH);
    softmax_q_kernel<<<gsm, 256>>>(sc, TT);

    // 4) ocat = attn @ v, written directly into (B,T,H*DV) layout
    dim3 gav(1, TT / 64, BB * HH);
    sgemm64<false, false, false><<<gav, 256>>>(sc, v, oc, nullptr,
        TT, DKK, TT, TT, DKK, DD, 1.f,
        (long)HH * TTl, TTl, BHT, HT, TD, DKK, HH);

    // 5) tmp = ocat @ Wo : [B*T,1024] x [1024,1024]
    dim3 gwo(DD / 64, (BB * TT) / 64, 1);
    sgemm64<false, false, false><<<gwo, 256>>>(oc, Wo, tp, nullptr,
        BB * TT, DD, DD, DD, DD, DD, 1.f, 0, 0, 0, 0, 0, 0, 1);

    // 6) out1 = norm(tmp + x)
    add_norm_kernel<<<BB * TT, 256>>>(tp, x, o1);

    // 7) ffh = relu(out1 @ W1 + b1) : [B*T,1024] x [1024,4096]
    dim3 gf1(FFF / 64, (BB * TT) / 64, 1);
    sgemm64<false, true, true><<<gf1, 256>>>(o1, W1, fh, b1,
        BB * TT, FFF, DD, DD, FFF, FFF, 1.f, 0, 0, 0, 0, 0, 0, 1);

    // 8) tmp = ffh @ W2 + b2 : [B*T,4096] x [4096,1024]
    dim3 gf2(DD / 64, (BB * TT) / 64, 1);
    sgemm64<false, true, false><<<gf2, 256>>>(fh, W2, tp, b2,
        BB * TT, DD, FFF, FFF, DD, DD, 1.f, 0, 0, 0, 0, 0, 0, 1);

    // 9) out = norm(tmp + out1)
    add_norm_kernel<<<BB * TT, 256>>>(tp, o1, out);
}

// round 2
// speedup vs baseline: 1.3520x; 1.3520x over previous
#include <cuda_runtime.h>
#include <cuda_bf16.h>

#define BB 2
#define TT 2048
#define DD 1024
#define HH 16
#define DKK 64
#define FFF 4096

// ---------------- scratch (static device memory; no allocs) ----------------
__device__ __align__(256) float g_q[(size_t)BB * HH * TT * DKK];
__device__ __align__(256) float g_k[(size_t)BB * HH * TT * DKK];
__device__ __align__(256) float g_v[(size_t)BB * HH * TT * DKK];
__device__ __align__(256) float g_scores[(size_t)BB * HH * TT * TT];
__device__ __align__(256) float g_ocat[(size_t)BB * TT * DD];
__device__ __align__(256) float g_tmp[(size_t)BB * TT * DD];
__device__ __align__(256) float g_out1[(size_t)BB * TT * DD];
__device__ __align__(256) float g_ffh[(size_t)BB * TT * FFF];

// ---------------- SGEMM: C = alpha*A*B (+bias)(relu) ----------------------
// BM=128, BK=16, 256 threads. BN=128 (TN=8) or BN=64 (TN=4). TM=8.
// All M,N,K assumed divisible by tile dims (true for this problem).
template <int BN, int TN, bool TRANSB, bool BIAS, bool RELU>
__global__ __launch_bounds__(256)
void sgemm(const float* __restrict__ A, const float* __restrict__ B,
           float* __restrict__ C, const float* __restrict__ bias,
           int K, int lda, int ldb, int ldc, float alpha,
           long soA, long siA, long soB, long siB, long soC, long siC,
           int inner)
{
    constexpr int BM = 128, BK = 16, TM = 8;
    constexpr int PA = BM + 4;   // 132: pitch*4 bytes = 528, multiple of 16
    constexpr int PB = BN + 4;   // 132 or 68, both *4 multiple of 16

    int z  = blockIdx.z;
    int zo = z / inner, zi = z - zo * inner;
    A += zo * soA + zi * siA;
    B += zo * soB + zi * siB;
    C += zo * soC + zi * siC;

    __shared__ float As[BK][PA];
    __shared__ float Bs[BK][PB];

    int tid = threadIdx.x;
    int tx = tid & 15, ty = tid >> 4;
    long bm = (long)blockIdx.y * BM;
    long bn = (long)blockIdx.x * BN;

    float acc[TM][TN] = {};

    for (int k0 = 0; k0 < K; k0 += BK) {
        // ---- load A tile (transpose into As[k][m]) ----
        #pragma unroll
        for (int i = 0; i < 2; i++) {
            int f = tid + i * 256;
            int row = f >> 2, k4 = (f & 3) * 4;
            float4 v = *(const float4*)&A[(bm + row) * lda + k0 + k4];
            As[k4 + 0][row] = v.x;
            As[k4 + 1][row] = v.y;
            As[k4 + 2][row] = v.z;
            As[k4 + 3][row] = v.w;
        }
        // ---- load B tile ----
        if constexpr (TRANSB) {
            #pragma unroll
            for (int i = 0; i < BN / 64; i++) {
                int f = tid + i * 256;
                int n = f >> 2, k4 = (f & 3) * 4;
                float4 v = *(const float4*)&B[(bn + n) * ldb + k0 + k4];
                Bs[k4 + 0][n] = v.x;
                Bs[k4 + 1][n] = v.y;
                Bs[k4 + 2][n] = v.z;
                Bs[k4 + 3][n] = v.w;
            }
        } else {
            #pragma unroll
            for (int i = 0; i < BN / 64; i++) {
                int f = tid + i * 256;
                int kk = f / (BN / 4), n4 = (f % (BN / 4)) * 4;
                *(float4*)&Bs[kk][n4] =
                    *(const float4*)&B[(long)(k0 + kk) * ldb + bn + n4];
            }
        }
        __syncthreads();

        // ---- compute ----
        #pragma unroll
        for (int kk = 0; kk < BK; kk++) {
            float a[TM], b[TN];
            *(float4*)&a[0] = *(const float4*)&As[kk][ty * TM];
            *(float4*)&a[4] = *(const float4*)&As[kk][ty * TM + 4];
            *(float4*)&b[0] = *(const float4*)&Bs[kk][tx * TN];
            if constexpr (TN == 8)
                *(float4*)&b[4] = *(const float4*)&Bs[kk][tx * TN + 4];
            #pragma unroll
            for (int i = 0; i < TM; i++)
                #pragma unroll
                for (int j = 0; j < TN; j++)
                    acc[i][j] += a[i] * b[j];
        }
        __syncthreads();
    }

    // ---- epilogue ----
    float bb[TN];
    if constexpr (BIAS) {
        #pragma unroll
        for (int j = 0; j < TN; j += 4)
            *(float4*)&bb[j] = *(const float4*)&bias[bn + tx * TN + j];
    }
    #pragma unroll
    for (int i = 0; i < TM; i++) {
        long row = bm + ty * TM + i;
        #pragma unroll
        for (int j0 = 0; j0 < TN; j0 += 4) {
            float4 v;
            float t0 = acc[i][j0 + 0] * alpha;
            float t1 = acc[i][j0 + 1] * alpha;
            float t2 = acc[i][j0 + 2] * alpha;
            float t3 = acc[i][j0 + 3] * alpha;
            if constexpr (BIAS) {
                t0 += bb[j0 + 0]; t1 += bb[j0 + 1];
                t2 += bb[j0 + 2]; t3 += bb[j0 + 3];
            }
            if constexpr (RELU) {
                t0 = fmaxf(t0, 0.f); t1 = fmaxf(t1, 0.f);
                t2 = fmaxf(t2, 0.f); t3 = fmaxf(t3, 0.f);
            }
            v.x = t0; v.y = t1; v.z = t2; v.w = t3;
            *(float4*)&C[row * ldc + bn + tx * TN + j0] = v;
        }
    }
}

// --------- softmax over the QUERY axis (axis=-2): per (z, s) column --------
__global__ void softmax_q_kernel(float* __restrict__ s, int T)
{
    int z = blockIdx.y;
    int col = blockIdx.x * blockDim.x + threadIdx.x;
    float* base = s + (long)z * T * T + col;

    float m = -1e30f, l = 0.f;
    for (int q = 0; q < T; q++) {
        float v = base[(long)q * T];
        float nm = fmaxf(m, v);
        l = l * __expf(m - nm) + __expf(v - nm);
        m = nm;
    }
    float inv = 1.f / l;
    for (int q = 0; q < T; q++) {
        float v = base[(long)q * T];
        base[(long)q * T] = __expf(v - m) * inv;
    }
}

// --------- out = meanstd_norm(a + b), ddof=1, D=1024 ----------------------
__global__ void add_norm_kernel(const float* __restrict__ a, const float* __restrict__ b,
                                float* __restrict__ out)
{
    const int D = DD;
    long r = blockIdx.x;
    const float* pa = a + r * D;
    const float* pb = b + r * D;
    int tid = threadIdx.x;

    float y[4];
    float sum = 0.f;
    #pragma unroll
    for (int i = 0; i < 4; i++) {
        y[i] = pa[tid + i * 256] + pb[tid + i * 256];
        sum += y[i];
    }

    __shared__ float red[8];
    #pragma unroll
    for (int o = 16; o > 0; o >>= 1) sum += __shfl_xor_sync(~0u, sum, o);
    if ((tid & 31) == 0) red[tid >> 5] = sum;
    __syncthreads();
    if (tid < 32) {
        float v = (tid < 8) ? red[tid] : 0.f;
        #pragma unroll
        for (int o = 4; o > 0; o >>= 1) v += __shfl_xor_sync(~0u, v, o);
        if (tid == 0) red[0] = v;
    }
    __syncthreads();
    float mean = red[0] / D;
    __syncthreads();

    float vs = 0.f;
    #pragma unroll
    for (int i = 0; i < 4; i++) {
        float d = y[i] - mean;
        vs += d * d;
    }
    #pragma unroll
    for (int o = 16; o > 0; o >>= 1) vs += __shfl_xor_sync(~0u, vs, o);
    if ((tid & 31) == 0) red[tid >> 5] = vs;
    __syncthreads();
    if (tid < 32) {
        float v = (tid < 8) ? red[tid] : 0.f;
        #pragma unroll
        for (int o = 4; o > 0; o >>= 1) v += __shfl_xor_sync(~0u, v, o);
        if (tid == 0) red[0] = v;
    }
    __syncthreads();
    float inv = rsqrtf(red[0] / (float)(D - 1));

    #pragma unroll
    for (int i = 0; i < 4; i++)
        out[r * D + tid + i * 256] = (y[i] - mean) * inv;
}

// ---------------------------------------------------------------------------
extern "C" void kernel_launch(void* const* d_in, const int* in_sizes, int n_in,
                              void* d_out, int out_size)
{
    const float* x  = (const float*)d_in[0];
    const float* Wq = (const float*)d_in[1];
    const float* Wk = (const float*)d_in[2];
    const float* Wv = (const float*)d_in[3];
    const float* Wo = (const float*)d_in[4];
    const float* W1 = (const float*)d_in[5];
    const float* b1 = (const float*)d_in[6];
    const float* W2 = (const float*)d_in[7];
    const float* b2 = (const float*)d_in[8];
    float* out = (float*)d_out;

    void *pq, *pk, *pv, *ps, *po, *pt, *p1, *pf;
    cudaGetSymbolAddress(&pq, g_q);
    cudaGetSymbolAddress(&pk, g_k);
    cudaGetSymbolAddress(&pv, g_v);
    cudaGetSymbolAddress(&ps, g_scores);
    cudaGetSymbolAddress(&po, g_ocat);
    cudaGetSymbolAddress(&pt, g_tmp);
    cudaGetSymbolAddress(&p1, g_out1);
    cudaGetSymbolAddress(&pf, g_ffh);
    float* q  = (float*)pq;
    float* k  = (float*)pk;
    float* v  = (float*)pv;
    float* sc = (float*)ps;
    float* oc = (float*)po;
    float* tp = (float*)pt;
    float* o1 = (float*)p1;
    float* fh = (float*)pf;

    const long TD  = (long)TT * DD;
    const long HD  = (long)DD * DKK;
    const long HT  = (long)TT * DKK;
    const long BHT = (long)HH * HT;
    const long TTl = (long)TT * TT;

    // 1) Q,K,V projections: per (b,h): [T,D] x [D,64] -> [T,64]
    dim3 gproj(1, TT / 128, BB * HH);
    sgemm<64, 4, false, false, false><<<gproj, 256>>>(x, Wq, q, nullptr,
        DD, DD, DKK, DKK, 1.f, TD, 0, 0, HD, BHT, HT, HH);
    sgemm<64, 4, false, false, false><<<gproj, 256>>>(x, Wk, k, nullptr,
        DD, DD, DKK, DKK, 1.f, TD, 0, 0, HD, BHT, HT, HH);
    sgemm<64, 4, false, false, false><<<gproj, 256>>>(x, Wv, v, nullptr,
        DD, DD, DKK, DKK, 1.f, TD, 0, 0, HD, BHT, HT, HH);

    // 2) scores = q @ k^T / sqrt(dk): per (b,h): [T,64] x [64,T]^T -> [T,T]
    dim3 gsc(TT / 128, TT / 128, BB * HH);
    sgemm<128, 8, true, false, false><<<gsc, 256>>>(q, k, sc, nullptr,
        DKK, DKK, DKK, TT, 0.125f, HT, 0, HT, 0, TTl, 0, 1);

    // 3) softmax over query axis (column softmax)
    dim3 gsm(TT / 256, BB * HH);
    softmax_q_kernel<<<gsm, 256>>>(sc, TT);

    // 4) ocat = attn @ v, written directly into (B,T,H*DV) layout
    dim3 gav(1, TT / 128, BB * HH);
    sgemm<64, 4, false, false, false><<<gav, 256>>>(sc, v, oc, nullptr,
        TT, TT, DKK, DD, 1.f,
        (long)HH * TTl, TTl, BHT, HT, TD, DKK, HH);

    // 5) tmp = ocat @ Wo : [B*T,1024] x [1024,1024]
    dim3 gwo(DD / 128, (BB * TT) / 128, 1);
    sgemm<128, 8, false, false, false><<<gwo, 256>>>(oc, Wo, tp, nullptr,
        DD, DD, DD, DD, 1.f, 0, 0, 0, 0, 0, 0, 1);

    // 6) out1 = norm(tmp + x)
    add_norm_kernel<<<BB * TT, 256>>>(tp, x, o1);

    // 7) ffh = relu(out1 @ W1 + b1) : [B*T,1024] x [1024,4096]
    dim3 gf1(FFF / 128, (BB * TT) / 128, 1);
    sgemm<128, 8, false, true, true><<<gf1, 256>>>(o1, W1, fh, b1,
        DD, DD, FFF, FFF, 1.f, 0, 0, 0, 0, 0, 0, 1);

    // 8) tmp = ffh @ W2 + b2 : [B*T,4096] x [4096,1024]
    dim3 gf2(DD / 128, (BB * TT) / 128, 1);
    sgemm<128, 8, false, true, false><<<gf2, 256>>>(fh, W2, tp, b2,
        FFF, FFF, DD, DD, 1.f, 0, 0, 0, 0, 0, 0, 1);

    // 9) out = norm(tmp + out1)
    add_norm_kernel<<<BB * TT, 256>>>(tp, o1, out);
}

// round 3
// speedup vs baseline: 3.0345x; 2.2445x over previous
#include <cuda_runtime.h>
#include <cuda_bf16.h>
#include <cstdint>

#define BB 2
#define TT 2048
#define DD 1024
#define HH 16
#define DKK 64
#define FFF 4096

using bf = __nv_bfloat16;

// ---------------- scratch (static device memory; no allocs) ----------------
__device__ __align__(256) float g_scores[(size_t)BB * HH * TT * TT];  // 536MB
__device__ __align__(256) float g_tmp[(size_t)BB * TT * DD];
__device__ __align__(256) float g_out1[(size_t)BB * TT * DD];

__device__ __align__(256) bf g_xh[(size_t)BB * TT * DD];
__device__ __align__(256) bf g_xl[(size_t)BB * TT * DD];
__device__ __align__(256) bf g_wqh[(size_t)HH * DD * DKK];
__device__ __align__(256) bf g_wql[(size_t)HH * DD * DKK];
__device__ __align__(256) bf g_wkh[(size_t)HH * DD * DKK];
__device__ __align__(256) bf g_wkl[(size_t)HH * DD * DKK];
__device__ __align__(256) bf g_wvh[(size_t)HH * DD * DKK];
__device__ __align__(256) bf g_wvl[(size_t)HH * DD * DKK];
__device__ __align__(256) bf g_woh[(size_t)DD * DD];
__device__ __align__(256) bf g_wol[(size_t)DD * DD];
__device__ __align__(256) bf g_w1h[(size_t)DD * FFF];
__device__ __align__(256) bf g_w1l[(size_t)DD * FFF];
__device__ __align__(256) bf g_w2h[(size_t)FFF * DD];
__device__ __align__(256) bf g_w2l[(size_t)FFF * DD];
__device__ __align__(256) bf g_qh[(size_t)BB * HH * TT * DKK];
__device__ __align__(256) bf g_ql[(size_t)BB * HH * TT * DKK];
__device__ __align__(256) bf g_kh[(size_t)BB * HH * TT * DKK];
__device__ __align__(256) bf g_kl[(size_t)BB * HH * TT * DKK];
__device__ __align__(256) bf g_vh[(size_t)BB * HH * TT * DKK];
__device__ __align__(256) bf g_vl[(size_t)BB * HH * TT * DKK];
__device__ __align__(256) bf g_ah[(size_t)BB * HH * TT * TT];  // 268MB
__device__ __align__(256) bf g_al[(size_t)BB * HH * TT * TT];  // 268MB
__device__ __align__(256) bf g_och[(size_t)BB * TT * DD];
__device__ __align__(256) bf g_ocl[(size_t)BB * TT * DD];
__device__ __align__(256) bf g_o1h[(size_t)BB * TT * DD];
__device__ __align__(256) bf g_o1l[(size_t)BB * TT * DD];
__device__ __align__(256) bf g_fhh[(size_t)BB * TT * FFF];
__device__ __align__(256) bf g_fhl[(size_t)BB * TT * FFF];

// ---------------- small helpers -------------------------------------------
__device__ __forceinline__ uint32_t smaddr(const void* p) {
    return (uint32_t)__cvta_generic_to_shared(p);
}
__device__ __forceinline__ void cpa16(uint32_t s, const void* g) {
    asm volatile("cp.async.cg.shared.global [%0], [%1], 16;\n" :: "r"(s), "l"(g));
}
__device__ __forceinline__ void cp_commit() {
    asm volatile("cp.async.commit_group;\n" ::: "memory");
}
__device__ __forceinline__ void cp_wait1() {
    asm volatile("cp.async.wait_group 1;\n" ::: "memory");
}
__device__ __forceinline__ void cp_wait0() {
    asm volatile("cp.async.wait_group 0;\n" ::: "memory");
}
__device__ __forceinline__ void ldsm4(uint32_t& r0, uint32_t& r1, uint32_t& r2, uint32_t& r3, uint32_t a) {
    asm volatile("ldmatrix.sync.aligned.m8n8.x4.shared.b16 {%0,%1,%2,%3}, [%4];\n"
                 : "=r"(r0), "=r"(r1), "=r"(r2), "=r"(r3) : "r"(a));
}
__device__ __forceinline__ void ldsm4t(uint32_t& r0, uint32_t& r1, uint32_t& r2, uint32_t& r3, uint32_t a) {
    asm volatile("ldmatrix.sync.aligned.m8n8.x4.trans.shared.b16 {%0,%1,%2,%3}, [%4];\n"
                 : "=r"(r0), "=r"(r1), "=r"(r2), "=r"(r3) : "r"(a));
}
__device__ __forceinline__ void mma16816(float* d, const uint32_t* a, uint32_t b0, uint32_t b1) {
    asm volatile(
        "mma.sync.aligned.m16n8k16.row.col.f32.bf16.bf16.f32 "
        "{%0,%1,%2,%3}, {%4,%5,%6,%7}, {%8,%9}, {%0,%1,%2,%3};\n"
        : "+f"(d[0]), "+f"(d[1]), "+f"(d[2]), "+f"(d[3])
        : "r"(a[0]), "r"(a[1]), "r"(a[2]), "r"(a[3]), "r"(b0), "r"(b1));
}
__device__ __forceinline__ void split1(float v, bf& h, bf& l) {
    h = __float2bfloat16(v);
    l = __float2bfloat16(v - __bfloat162float(h));
}

// ---------------- bf16-split tensor-core GEMM ------------------------------
// C = alpha * A * B (+bias)(relu). A:[M,K] k-contig. B: TRANSB ? [N,K] : [K,N].
// A,B given as hi/lo bf16 pairs. D = Ah*Bh + Ah*Bl + Al*Bh (fp32 accum).
// BM=128, BK=32, 256 threads. BN = 128 or 64. All dims divisible.
template <int BN, bool TRANSB, bool BIAS, bool RELU, bool OF32, bool OSPLIT>
__global__ __launch_bounds__(256)
void mgemm(const bf* __restrict__ Ah, const bf* __restrict__ Al,
           const bf* __restrict__ Bh, const bf* __restrict__ Bl,
           float* __restrict__ C, bf* __restrict__ Ch, bf* __restrict__ Cl,
           const float* __restrict__ bias,
           int K, int lda, int ldb, int ldc, float alpha,
           long soA, long siA, long soB, long siB, long soC, long siC, int inner)
{
    constexpr int BM = 128, BK = 32, AP = 40;           // A pitch (bf16)
    constexpr int BP = TRANSB ? 40 : (BN + 8);          // B pitch
    constexpr int AE = BM * AP;                         // A elems / array / stage
    constexpr int BE = TRANSB ? (BN * AP) : (BK * BP);  // B elems / array / stage
    constexpr int STG = 2 * AE + 2 * BE;
    extern __shared__ bf sm[];

    int z = blockIdx.z;
    int zo = z / inner, zi = z - zo * inner;
    long aoff = zo * soA + zi * siA;
    long boff = zo * soB + zi * siB;
    long coff = zo * soC + zi * siC;
    Ah += aoff; Al += aoff;
    Bh += boff; Bl += boff;

    int tid = threadIdx.x, lane = tid & 31, wid = tid >> 5;
    constexpr int MF = (BN == 128) ? 4 : 2;  // 16-row frags per warp
    constexpr int NF = 4;                    // 8-col frags per warp (32 cols)
    int wm = (BN == 128) ? (wid >> 2) : (wid >> 1);
    int wn = (BN == 128) ? (wid & 3) : (wid & 1);
    int m0 = wm * MF * 16, n0 = wn * 32;

    long bm = (long)blockIdx.y * BM, bn = (long)blockIdx.x * BN;

    float acc[MF][NF][4] = {};

    auto copyStage = [&](int kt, int s) {
        int k0 = kt * BK;
        bf* sa_h = sm + (size_t)s * STG;
        bf* sa_l = sa_h + AE;
        bf* sb_h = sa_l + AE;
        bf* sb_l = sb_h + BE;
        #pragma unroll
        for (int i = 0; i < 2; i++) {
            int c = tid + i * 256;
            int r = c >> 2, cc = (c & 3) * 8;
            long go = (bm + r) * (long)lda + k0 + cc;
            cpa16(smaddr(sa_h + r * AP + cc), Ah + go);
            cpa16(smaddr(sa_l + r * AP + cc), Al + go);
        }
        if constexpr (TRANSB) {
            #pragma unroll
            for (int i = 0; i < BN / 64; i++) {
                int c = tid + i * 256;
                int r = c >> 2, cc = (c & 3) * 8;
                long go = (bn + r) * (long)ldb + k0 + cc;
                cpa16(smaddr(sb_h + r * AP + cc), Bh + go);
                cpa16(smaddr(sb_l + r * AP + cc), Bl + go);
            }
        } else {
            constexpr int CPR = BN / 8;
            #pragma unroll
            for (int i = 0; i < (32 * CPR) / 256; i++) {
                int c = tid + i * 256;
                int r = c / CPR, cc = (c % CPR) * 8;
                long go = (long)(k0 + r) * ldb + bn + cc;
                cpa16(smaddr(sb_h + r * BP + cc), Bh + go);
                cpa16(smaddr(sb_l + r * BP + cc), Bl + go);
            }
        }
        cp_commit();
    };

    auto compute = [&](int s) {
        const bf* sa_h = sm + (size_t)s * STG;
        const bf* sa_l = sa_h + AE;
        const bf* sb_h = sa_l + AE;
        const bf* sb_l = sb_h + BE;
        #pragma unroll
        for (int kk = 0; kk < BK; kk += 16) {
            uint32_t ah[MF][4], al[MF][4];
            #pragma unroll
            for (int mf = 0; mf < MF; mf++) {
                int row = m0 + mf * 16 + (lane & 15);
                int col = kk + (lane >> 4) * 8;
                ldsm4(ah[mf][0], ah[mf][1], ah[mf][2], ah[mf][3],
                      smaddr(sa_h + row * AP + col));
                ldsm4(al[mf][0], al[mf][1], al[mf][2], al[mf][3],
                      smaddr(sa_l + row * AP + col));
            }
            uint32_t bh[NF][2], bl[NF][2];
            #pragma unroll
            for (int g = 0; g < 2; g++) {
                if constexpr (TRANSB) {
                    int rown = n0 + g * 16 + (lane & 7) + ((lane >> 4) & 1) * 8;
                    int col = kk + ((lane >> 3) & 1) * 8;
                    ldsm4(bh[2*g][0], bh[2*g][1], bh[2*g+1][0], bh[2*g+1][1],
                          smaddr(sb_h + rown * AP + col));
                    ldsm4(bl[2*g][0], bl[2*g][1], bl[2*g+1][0], bl[2*g+1][1],
                          smaddr(sb_l + rown * AP + col));
                } else {
                    int rowk = kk + (lane & 7) + ((lane >> 3) & 1) * 8;
                    int coln = n0 + g * 16 + (lane >> 4) * 8;
                    ldsm4t(bh[2*g][0], bh[2*g][1], bh[2*g+1][0], bh[2*g+1][1],
                           smaddr(sb_h + rowk * BP + coln));
                    ldsm4t(bl[2*g][0], bl[2*g][1], bl[2*g+1][0], bl[2*g+1][1],
                           smaddr(sb_l + rowk * BP + coln));
                }
            }
            #pragma unroll
            for (int mf = 0; mf < MF; mf++)
                #pragma unroll
                for (int nf = 0; nf < NF; nf++) {
                    mma16816(acc[mf][nf], ah[mf], bh[nf][0], bh[nf][1]);
                    mma16816(acc[mf][nf], ah[mf], bl[nf][0], bl[nf][1]);
                    mma16816(acc[mf][nf], al[mf], bh[nf][0], bh[nf][1]);
                }
        }
    };

    int nk = K / BK;
    copyStage(0, 0);
    for (int kt = 0; kt < nk; kt++) {
        if (kt + 1 < nk) { copyStage(kt + 1, (kt + 1) & 1); cp_wait1(); }
        else             { cp_wait0(); }
        __syncthreads();
        compute(kt & 1);
        __syncthreads();
    }

    // ---- epilogue ----
    #pragma unroll
    for (int mf = 0; mf < MF; mf++) {
        #pragma unroll
        for (int nf = 0; nf < NF; nf++) {
            long r0 = bm + m0 + mf * 16 + (lane >> 2);
            long r1 = r0 + 8;
            long c  = bn + n0 + nf * 8 + (lane & 3) * 2;
            float v00 = acc[mf][nf][0] * alpha;
            float v01 = acc[mf][nf][1] * alpha;
            float v10 = acc[mf][nf][2] * alpha;
            float v11 = acc[mf][nf][3] * alpha;
            if constexpr (BIAS) {
                float b0v = bias[c], b1v = bias[c + 1];
                v00 += b0v; v01 += b1v; v10 += b0v; v11 += b1v;
            }
            if constexpr (RELU) {
                v00 = fmaxf(v00, 0.f); v01 = fmaxf(v01, 0.f);
                v10 = fmaxf(v10, 0.f); v11 = fmaxf(v11, 0.f);
            }
            if constexpr (OF32) {
                float2 p0 = {v00, v01}, p1 = {v10, v11};
                *(float2*)&C[coff + r0 * ldc + c] = p0;
                *(float2*)&C[coff + r1 * ldc + c] = p1;
            }
            if constexpr (OSPLIT) {
                bf h0, l0, h1, l1;
                __nv_bfloat162 ph, pl;
                split1(v00, h0, l0); split1(v01, h1, l1);
                ph.x = h0; ph.y = h1; pl.x = l0; pl.y = l1;
                *(__nv_bfloat162*)&Ch[coff + r0 * ldc + c] = ph;
                *(__nv_bfloat162*)&Cl[coff + r0 * ldc + c] = pl;
                split1(v10, h0, l0); split1(v11, h1, l1);
                ph.x = h0; ph.y = h1; pl.x = l0; pl.y = l1;
                *(__nv_bfloat162*)&Ch[coff + r1 * ldc + c] = ph;
                *(__nv_bfloat162*)&Cl[coff + r1 * ldc + c] = pl;
            }
        }
    }
}

// ---------------- fp32 -> bf16 hi/lo split ---------------------------------
__global__ void split_kernel(const float4* __restrict__ in, uint2* __restrict__ hi,
                             uint2* __restrict__ lo, long n4)
{
    long i = (long)blockIdx.x * blockDim.x + threadIdx.x;
    if (i >= n4) return;
    float4 v = in[i];
    bf h0, l0, h1, l1, h2, l2, h3, l3;
    split1(v.x, h0, l0); split1(v.y, h1, l1);
    split1(v.z, h2, l2); split1(v.w, h3, l3);
    __nv_bfloat162 a, b;
    uint2 o;
    a.x = h0; a.y = h1; b.x = h2; b.y = h3;
    o.x = *(uint32_t*)&a; o.y = *(uint32_t*)&b;
    hi[i] = o;
    a.x = l0; a.y = l1; b.x = l2; b.y = l3;
    o.x = *(uint32_t*)&a; o.y = *(uint32_t*)&b;
    lo[i] = o;
}

// --------- softmax over the QUERY axis; writes bf16 hi/lo attn -------------
__global__ void softmax_q_kernel(const float* __restrict__ s,
                                 bf* __restrict__ ph, bf* __restrict__ pl, int T)
{
    int z = blockIdx.y;
    int col = blockIdx.x * blockDim.x + threadIdx.x;
    long base = (long)z * T * T + col;

    float m = -1e30f, l = 0.f;
    for (int q = 0; q < T; q++) {
        float v = s[base + (long)q * T];
        float nm = fmaxf(m, v);
        l = l * __expf(m - nm) + __expf(v - nm);
        m = nm;
    }
    float inv = 1.f / l;
    for (int q = 0; q < T; q++) {
        float v = s[base + (long)q * T];
        float p = __expf(v - m) * inv;
        bf h, lo_;
        split1(p, h, lo_);
        ph[base + (long)q * T] = h;
        pl[base + (long)q * T] = lo_;
    }
}

// --------- out = meanstd_norm(a + b); optional bf16 hi/lo output -----------
template <bool WSPLIT>
__global__ void add_norm_kernel(const float* __restrict__ a, const float* __restrict__ b,
                                float* __restrict__ out, bf* __restrict__ oh,
                                bf* __restrict__ ol)
{
    const int D = DD;
    long r = blockIdx.x;
    const float* pa = a + r * D;
    const float* pb = b + r * D;
    int tid = threadIdx.x;

    float y[4];
    float sum = 0.f;
    #pragma unroll
    for (int i = 0; i < 4; i++) {
        y[i] = pa[tid + i * 256] + pb[tid + i * 256];
        sum += y[i];
    }

    __shared__ float red[8];
    #pragma unroll
    for (int o = 16; o > 0; o >>= 1) sum += __shfl_xor_sync(~0u, sum, o);
    if ((tid & 31) == 0) red[tid >> 5] = sum;
    __syncthreads();
    if (tid < 32) {
        float v = (tid < 8) ? red[tid] : 0.f;
        #pragma unroll
        for (int o = 4; o > 0; o >>= 1) v += __shfl_xor_sync(~0u, v, o);
        if (tid == 0) red[0] = v;
    }
    __syncthreads();
    float mean = red[0] / D;
    __syncthreads();

    float vs = 0.f;
    #pragma unroll
    for (int i = 0; i < 4; i++) {
        float d = y[i] - mean;
        vs += d * d;
    }
    #pragma unroll
    for (int o = 16; o > 0; o >>= 1) vs += __shfl_xor_sync(~0u, vs, o);
    if ((tid & 31) == 0) red[tid >> 5] = vs;
    __syncthreads();
    if (tid < 32) {
        float v = (tid < 8) ? red[tid] : 0.f;
        #pragma unroll
        for (int o = 4; o > 0; o >>= 1) v += __shfl_xor_sync(~0u, v, o);
        if (tid == 0) red[0] = v;
    }
    __syncthreads();
    float inv = rsqrtf(red[0] / (float)(D - 1));

    #pragma unroll
    for (int i = 0; i < 4; i++) {
        float v = (y[i] - mean) * inv;
        long idx = r * D + tid + i * 256;
        out[idx] = v;
        if constexpr (WSPLIT) {
            bf h, l;
            split1(v, h, l);
            oh[idx] = h;
            ol[idx] = l;
        }
    }
}

// ---------------------------------------------------------------------------
static inline void* sym(const void* s) {
    void* p = nullptr;
    cudaGetSymbolAddress(&p, s);
    return p;
}

extern "C" void kernel_launch(void* const* d_in, const int* in_sizes, int n_in,
                              void* d_out, int out_size)
{
    const float* x  = (const float*)d_in[0];
    const float* Wq = (const float*)d_in[1];
    const float* Wk = (const float*)d_in[2];
    const float* Wv = (const float*)d_in[3];
    const float* Wo = (const float*)d_in[4];
    const float* W1 = (const float*)d_in[5];
    const float* b1 = (const float*)d_in[6];
    const float* W2 = (const float*)d_in[7];
    const float* b2 = (const float*)d_in[8];
    float* out = (float*)d_out;

    float* sc = (float*)sym(g_scores);
    float* tp = (float*)sym(g_tmp);
    float* o1 = (float*)sym(g_out1);
    bf *xh = (bf*)sym(g_xh), *xl = (bf*)sym(g_xl);
    bf *wqh = (bf*)sym(g_wqh), *wql = (bf*)sym(g_wql);
    bf *wkh = (bf*)sym(g_wkh), *wkl = (bf*)sym(g_wkl);
    bf *wvh = (bf*)sym(g_wvh), *wvl = (bf*)sym(g_wvl);
    bf *woh = (bf*)sym(g_woh), *wol = (bf*)sym(g_wol);
    bf *w1h = (bf*)sym(g_w1h), *w1l = (bf*)sym(g_w1l);
    bf *w2h = (bf*)sym(g_w2h), *w2l = (bf*)sym(g_w2l);
    bf *qh = (bf*)sym(g_qh), *ql = (bf*)sym(g_ql);
    bf *kh = (bf*)sym(g_kh), *kl = (bf*)sym(g_kl);
    bf *vh = (bf*)sym(g_vh), *vl = (bf*)sym(g_vl);
    bf *ah = (bf*)sym(g_ah), *al = (bf*)sym(g_al);
    bf *och = (bf*)sym(g_och), *ocl = (bf*)sym(g_ocl);
    bf *o1h = (bf*)sym(g_o1h), *o1l = (bf*)sym(g_o1l);
    bf *fhh = (bf*)sym(g_fhh), *fhl = (bf*)sym(g_fhl);

    const long TD  = (long)TT * DD;
    const long HD  = (long)DD * DKK;
    const long HT  = (long)TT * DKK;
    const long BHT = (long)HH * HT;
    const long TTl = (long)TT * TT;

    // opt-in dynamic smem (once per call; cheap)
    constexpr int SM_T128 = (2 * 128 * 40 + 2 * 128 * 40) * 2 * 2;        // 81920
    constexpr int SM_N128 = (2 * 128 * 40 + 2 * 32 * 136) * 2 * 2;        // 75776
    constexpr int SM_N64  = (2 * 128 * 40 + 2 * 32 * 72) * 2 * 2;         // 59392
    cudaFuncSetAttribute(mgemm<64, false, false, false, false, true>,
                         cudaFuncAttributeMaxDynamicSharedMemorySize, SM_N64);
    cudaFuncSetAttribute(mgemm<128, true, false, false, true, false>,
                         cudaFuncAttributeMaxDynamicSharedMemorySize, SM_T128);
    cudaFuncSetAttribute(mgemm<128, false, false, false, true, false>,
                         cudaFuncAttributeMaxDynamicSharedMemorySize, SM_N128);
    cudaFuncSetAttribute(mgemm<128, false, true, true, false, true>,
                         cudaFuncAttributeMaxDynamicSharedMemorySize, SM_N128);
    cudaFuncSetAttribute(mgemm<128, false, true, false, true, false>,
                         cudaFuncAttributeMaxDynamicSharedMemorySize, SM_N128);

    // 0) split fp32 -> bf16 hi/lo
    auto split = [&](const float* in, bf* hi, bf* lo, long n) {
        long n4 = n / 4;
        split_kernel<<<(unsigned)((n4 + 255) / 256), 256>>>(
            (const float4*)in, (uint2*)hi, (uint2*)lo, n4);
    };
    split(x,  xh,  xl,  (long)BB * TT * DD);
    split(Wq, wqh, wql, (long)HH * DD * DKK);
    split(Wk, wkh, wkl, (long)HH * DD * DKK);
    split(Wv, wvh, wvl, (long)HH * DD * DKK);
    split(Wo, woh, wol, (long)DD * DD);
    split(W1, w1h, w1l, (long)DD * FFF);
    split(W2, w2h, w2l, (long)FFF * DD);

    // 1) Q,K,V projections: per (b,h): [T,D] x [D,64] -> [T,64] (split out)
    dim3 gproj(1, TT / 128, BB * HH);
    mgemm<64, false, false, false, false, true><<<gproj, 256, SM_N64>>>(
        xh, xl, wqh, wql, nullptr, qh, ql, nullptr,
        DD, DD, DKK, DKK, 1.f, TD, 0, 0, HD, BHT, HT, HH);
    mgemm<64, false, false, false, false, true><<<gproj, 256, SM_N64>>>(
        xh, xl, wkh, wkl, nullptr, kh, kl, nullptr,
        DD, DD, DKK, DKK, 1.f, TD, 0, 0, HD, BHT, HT, HH);
    mgemm<64, false, false, false, false, true><<<gproj, 256, SM_N64>>>(
        xh, xl, wvh, wvl, nullptr, vh, vl, nullptr,
        DD, DD, DKK, DKK, 1.f, TD, 0, 0, HD, BHT, HT, HH);

    // 2) scores = q @ k^T / 8 (f32 out)
    dim3 gsc(TT / 128, TT / 128, BB * HH);
    mgemm<128, true, false, false, true, false><<<gsc, 256, SM_T128>>>(
        qh, ql, kh, kl, sc, nullptr, nullptr, nullptr,
        DKK, DKK, DKK, TT, 0.125f, HT, 0, HT, 0, TTl, 0, 1);

    // 3) column softmax -> attn hi/lo
    dim3 gsm(TT / 256, BB * HH);
    softmax_q_kernel<<<gsm, 256>>>(sc, ah, al, TT);

    // 4) ocat = attn @ v -> (B,T,H*DV) (split out)
    dim3 gav(1, TT / 128, BB * HH);
    mgemm<64, false, false, false, false, true><<<gav, 256, SM_N64>>>(
        ah, al, vh, vl, nullptr, och, ocl, nullptr,
        TT, TT, DKK, DD, 1.f,
        (long)HH * TTl, TTl, BHT, HT, TD, DKK, HH);

    // 5) tmp = ocat @ Wo (f32)
    dim3 gwo(DD / 128, (BB * TT) / 128, 1);
    mgemm<128, false, false, false, true, false><<<gwo, 256, SM_N128>>>(
        och, ocl, woh, wol, tp, nullptr, nullptr, nullptr,
        DD, DD, DD, DD, 1.f, 0, 0, 0, 0, 0, 0, 1);

    // 6) out1 = norm(tmp + x), plus split for FFN
    add_norm_kernel<true><<<BB * TT, 256>>>(tp, x, o1, o1h, o1l);

    // 7) ffh = relu(out1 @ W1 + b1) (split out)
    dim3 gf1(FFF / 128, (BB * TT) / 128, 1);
    mgemm<128, false, true, true, false, true><<<gf1, 256, SM_N128>>>(
        o1h, o1l, w1h, w1l, nullptr, fhh, fhl, b1,
        DD, DD, FFF, FFF, 1.f, 0, 0, 0, 0, 0, 0, 1);

    // 8) tmp = ffh @ W2 + b2 (f32)
    dim3 gf2(DD / 128, (BB * TT) / 128, 1);
    mgemm<128, false, true, false, true, false><<<gf2, 256, SM_N128>>>(
        fhh, fhl, w2h, w2l, tp, nullptr, nullptr, b2,
        FFF, FFF, DD, DD, 1.f, 0, 0, 0, 0, 0, 0, 1);

    // 9) out = norm(tmp + out1)
    add_norm_kernel<false><<<BB * TT, 256>>>(tp, o1, out, nullptr, nullptr);
}

// round 5
// speedup vs baseline: 3.9060x; 1.2872x over previous
#include <cuda_runtime.h>
#include <cuda_bf16.h>
#include <cstdint>

#define BB 2
#define TT 2048
#define DD 1024
#define HH 16
#define DKK 64
#define FFF 4096

using bf = __nv_bfloat16;

// ---------------- scratch (static device memory; no allocs) ----------------
__device__ __align__(256) float g_tmp[(size_t)BB * TT * DD];
__device__ __align__(256) float g_out1[(size_t)BB * TT * DD];
__device__ __align__(256) float g_m[(size_t)BB * HH * TT];
__device__ __align__(256) float g_il[(size_t)BB * HH * TT];

__device__ __align__(256) bf g_xh[(size_t)BB * TT * DD];
__device__ __align__(256) bf g_xl[(size_t)BB * TT * DD];
__device__ __align__(256) bf g_wqh[(size_t)HH * DD * DKK];
__device__ __align__(256) bf g_wql[(size_t)HH * DD * DKK];
__device__ __align__(256) bf g_wkh[(size_t)HH * DD * DKK];
__device__ __align__(256) bf g_wkl[(size_t)HH * DD * DKK];
__device__ __align__(256) bf g_wvh[(size_t)HH * DD * DKK];
__device__ __align__(256) bf g_wvl[(size_t)HH * DD * DKK];
__device__ __align__(256) bf g_woh[(size_t)DD * DD];
__device__ __align__(256) bf g_wol[(size_t)DD * DD];
__device__ __align__(256) bf g_w1h[(size_t)DD * FFF];
__device__ __align__(256) bf g_w1l[(size_t)DD * FFF];
__device__ __align__(256) bf g_w2h[(size_t)FFF * DD];
__device__ __align__(256) bf g_w2l[(size_t)FFF * DD];
__device__ __align__(256) bf g_qh[(size_t)BB * HH * TT * DKK];
__device__ __align__(256) bf g_ql[(size_t)BB * HH * TT * DKK];
__device__ __align__(256) bf g_kh[(size_t)BB * HH * TT * DKK];
__device__ __align__(256) bf g_kl[(size_t)BB * HH * TT * DKK];
__device__ __align__(256) bf g_vh[(size_t)BB * HH * TT * DKK];
__device__ __align__(256) bf g_vl[(size_t)BB * HH * TT * DKK];
__device__ __align__(256) bf g_och[(size_t)BB * TT * DD];
__device__ __align__(256) bf g_ocl[(size_t)BB * TT * DD];
__device__ __align__(256) bf g_o1h[(size_t)BB * TT * DD];
__device__ __align__(256) bf g_o1l[(size_t)BB * TT * DD];
__device__ __align__(256) bf g_fhh[(size_t)BB * TT * FFF];
__device__ __align__(256) bf g_fhl[(size_t)BB * TT * FFF];

// ---------------- small helpers -------------------------------------------
__device__ __forceinline__ uint32_t smaddr(const void* p) {
    return (uint32_t)__cvta_generic_to_shared(p);
}
__device__ __forceinline__ void cpa16(uint32_t s, const void* g) {
    asm volatile("cp.async.cg.shared.global [%0], [%1], 16;\n" :: "r"(s), "l"(g));
}
__device__ __forceinline__ void cp_commit() {
    asm volatile("cp.async.commit_group;\n" ::: "memory");
}
__device__ __forceinline__ void cp_wait1() {
    asm volatile("cp.async.wait_group 1;\n" ::: "memory");
}
__device__ __forceinline__ void cp_wait0() {
    asm volatile("cp.async.wait_group 0;\n" ::: "memory");
}
__device__ __forceinline__ void ldsm4(uint32_t& r0, uint32_t& r1, uint32_t& r2, uint32_t& r3, uint32_t a) {
    asm volatile("ldmatrix.sync.aligned.m8n8.x4.shared.b16 {%0,%1,%2,%3}, [%4];\n"
                 : "=r"(r0), "=r"(r1), "=r"(r2), "=r"(r3) : "r"(a));
}
__device__ __forceinline__ void ldsm4t(uint32_t& r0, uint32_t& r1, uint32_t& r2, uint32_t& r3, uint32_t a) {
    asm volatile("ldmatrix.sync.aligned.m8n8.x4.trans.shared.b16 {%0,%1,%2,%3}, [%4];\n"
                 : "=r"(r0), "=r"(r1), "=r"(r2), "=r"(r3) : "r"(a));
}
__device__ __forceinline__ void mma16816(float* d, const uint32_t* a, uint32_t b0, uint32_t b1) {
    asm volatile(
        "mma.sync.aligned.m16n8k16.row.col.f32.bf16.bf16.f32 "
        "{%0,%1,%2,%3}, {%4,%5,%6,%7}, {%8,%9}, {%0,%1,%2,%3};\n"
        : "+f"(d[0]), "+f"(d[1]), "+f"(d[2]), "+f"(d[3])
        : "r"(a[0]), "r"(a[1]), "r"(a[2]), "r"(a[3]), "r"(b0), "r"(b1));
}
__device__ __forceinline__ void split1(float v, bf& h, bf& l) {
    h = __float2bfloat16(v);
    l = __float2bfloat16(v - __bfloat162float(h));
}
__device__ __forceinline__ uint32_t pack2(bf a, bf b) {
    __nv_bfloat162 p; p.x = a; p.y = b;
    return *(uint32_t*)&p;
}

// ---------------- bf16-split tensor-core GEMM ------------------------------
template <int BN, bool TRANSB, bool BIAS, bool RELU, bool OF32, bool OSPLIT>
__global__ __launch_bounds__(256)
void mgemm(const bf* __restrict__ Ah, const bf* __restrict__ Al,
           const bf* __restrict__ Bh, const bf* __restrict__ Bl,
           float* __restrict__ C, bf* __restrict__ Ch, bf* __restrict__ Cl,
           const float* __restrict__ bias,
           int K, int lda, int ldb, int ldc, float alpha,
           long soA, long siA, long soB, long siB, long soC, long siC, int inner)
{
    constexpr int BM = 128, BK = 32, AP = 40;
    constexpr int BP = TRANSB ? 40 : (BN + 8);
    constexpr int AE = BM * AP;
    constexpr int BE = TRANSB ? (BN * AP) : (BK * BP);
    constexpr int STG = 2 * AE + 2 * BE;
    extern __shared__ bf sm[];

    int z = blockIdx.z;
    int zo = z / inner, zi = z - zo * inner;
    long aoff = zo * soA + zi * siA;
    long boff = zo * soB + zi * siB;
    long coff = zo * soC + zi * siC;
    Ah += aoff; Al += aoff;
    Bh += boff; Bl += boff;

    int tid = threadIdx.x, lane = tid & 31, wid = tid >> 5;
    constexpr int MF = (BN == 128) ? 4 : 2;
    constexpr int NF = 4;
    int wm = (BN == 128) ? (wid >> 2) : (wid >> 1);
    int wn = (BN == 128) ? (wid & 3) : (wid & 1);
    int m0 = wm * MF * 16, n0 = wn * 32;

    long bm = (long)blockIdx.y * BM, bn = (long)blockIdx.x * BN;

    float acc[MF][NF][4] = {};

    auto copyStage = [&](int kt, int s) {
        int k0 = kt * BK;
        bf* sa_h = sm + (size_t)s * STG;
        bf* sa_l = sa_h + AE;
        bf* sb_h = sa_l + AE;
        bf* sb_l = sb_h + BE;
        #pragma unroll
        for (int i = 0; i < 2; i++) {
            int c = tid + i * 256;
            int r = c >> 2, cc = (c & 3) * 8;
            long go = (bm + r) * (long)lda + k0 + cc;
            cpa16(smaddr(sa_h + r * AP + cc), Ah + go);
            cpa16(smaddr(sa_l + r * AP + cc), Al + go);
        }
        if constexpr (TRANSB) {
            #pragma unroll
            for (int i = 0; i < BN / 64; i++) {
                int c = tid + i * 256;
                int r = c >> 2, cc = (c & 3) * 8;
                long go = (bn + r) * (long)ldb + k0 + cc;
                cpa16(smaddr(sb_h + r * AP + cc), Bh + go);
                cpa16(smaddr(sb_l + r * AP + cc), Bl + go);
            }
        } else {
            constexpr int CPR = BN / 8;
            #pragma unroll
            for (int i = 0; i < (32 * CPR) / 256; i++) {
                int c = tid + i * 256;
                int r = c / CPR, cc = (c % CPR) * 8;
                long go = (long)(k0 + r) * ldb + bn + cc;
                cpa16(smaddr(sb_h + r * BP + cc), Bh + go);
                cpa16(smaddr(sb_l + r * BP + cc), Bl + go);
            }
        }
        cp_commit();
    };

    auto compute = [&](int s) {
        const bf* sa_h = sm + (size_t)s * STG;
        const bf* sa_l = sa_h + AE;
        const bf* sb_h = sa_l + AE;
        const bf* sb_l = sb_h + BE;
        #pragma unroll
        for (int kk = 0; kk < BK; kk += 16) {
            uint32_t ah[MF][4], al[MF][4];
            #pragma unroll
            for (int mf = 0; mf < MF; mf++) {
                int row = m0 + mf * 16 + (lane & 15);
                int col = kk + (lane >> 4) * 8;
                ldsm4(ah[mf][0], ah[mf][1], ah[mf][2], ah[mf][3],
                      smaddr(sa_h + row * AP + col));
                ldsm4(al[mf][0], al[mf][1], al[mf][2], al[mf][3],
                      smaddr(sa_l + row * AP + col));
            }
            uint32_t bh2[NF][2], bl2[NF][2];
            #pragma unroll
            for (int g = 0; g < 2; g++) {
                if constexpr (TRANSB) {
                    int rown = n0 + g * 16 + (lane & 7) + ((lane >> 4) & 1) * 8;
                    int col = kk + ((lane >> 3) & 1) * 8;
                    ldsm4(bh2[2*g][0], bh2[2*g][1], bh2[2*g+1][0], bh2[2*g+1][1],
                          smaddr(sb_h + rown * AP + col));
                    ldsm4(bl2[2*g][0], bl2[2*g][1], bl2[2*g+1][0], bl2[2*g+1][1],
                          smaddr(sb_l + rown * AP + col));
                } else {
                    int rowk = kk + (lane & 7) + ((lane >> 3) & 1) * 8;
                    int coln = n0 + g * 16 + (lane >> 4) * 8;
                    ldsm4t(bh2[2*g][0], bh2[2*g][1], bh2[2*g+1][0], bh2[2*g+1][1],
                           smaddr(sb_h + rowk * BP + coln));
                    ldsm4t(bl2[2*g][0], bl2[2*g][1], bl2[2*g+1][0], bl2[2*g+1][1],
                           smaddr(sb_l + rowk * BP + coln));
                }
            }
            #pragma unroll
            for (int mf = 0; mf < MF; mf++)
                #pragma unroll
                for (int nf = 0; nf < NF; nf++) {
                    mma16816(acc[mf][nf], ah[mf], bh2[nf][0], bh2[nf][1]);
                    mma16816(acc[mf][nf], ah[mf], bl2[nf][0], bl2[nf][1]);
                    mma16816(acc[mf][nf], al[mf], bh2[nf][0], bh2[nf][1]);
                }
        }
    };

    int nk = K / BK;
    copyStage(0, 0);
    for (int kt = 0; kt < nk; kt++) {
        if (kt + 1 < nk) { copyStage(kt + 1, (kt + 1) & 1); cp_wait1(); }
        else             { cp_wait0(); }
        __syncthreads();
        compute(kt & 1);
        __syncthreads();
    }

    #pragma unroll
    for (int mf = 0; mf < MF; mf++) {
        #pragma unroll
        for (int nf = 0; nf < NF; nf++) {
            long r0 = bm + m0 + mf * 16 + (lane >> 2);
            long r1 = r0 + 8;
            long c  = bn + n0 + nf * 8 + (lane & 3) * 2;
            float v00 = acc[mf][nf][0] * alpha;
            float v01 = acc[mf][nf][1] * alpha;
            float v10 = acc[mf][nf][2] * alpha;
            float v11 = acc[mf][nf][3] * alpha;
            if constexpr (BIAS) {
                float b0v = bias[c], b1v = bias[c + 1];
                v00 += b0v; v01 += b1v; v10 += b0v; v11 += b1v;
            }
            if constexpr (RELU) {
                v00 = fmaxf(v00, 0.f); v01 = fmaxf(v01, 0.f);
                v10 = fmaxf(v10, 0.f); v11 = fmaxf(v11, 0.f);
            }
            if constexpr (OF32) {
                float2 p0 = {v00, v01}, p1 = {v10, v11};
                *(float2*)&C[coff + r0 * ldc + c] = p0;
                *(float2*)&C[coff + r1 * ldc + c] = p1;
            }
            if constexpr (OSPLIT) {
                bf h0, l0, h1, l1;
                split1(v00, h0, l0); split1(v01, h1, l1);
                *(uint32_t*)&Ch[coff + r0 * ldc + c] = pack2(h0, h1);
                *(uint32_t*)&Cl[coff + r0 * ldc + c] = pack2(l0, l1);
                split1(v10, h0, l0); split1(v11, h1, l1);
                *(uint32_t*)&Ch[coff + r1 * ldc + c] = pack2(h0, h1);
                *(uint32_t*)&Cl[coff + r1 * ldc + c] = pack2(l0, l1);
            }
        }
    }
}

// ---------------- fused attention pass 1: column-softmax stats --------------
// S^T = K @ Q^T per (b,h); online row-softmax over keys -> m[s], invl[s].
__global__ __launch_bounds__(256)
void attn_stats_kernel(const bf* __restrict__ qh_, const bf* __restrict__ ql_,
                       const bf* __restrict__ kh_, const bf* __restrict__ kl_,
                       float* __restrict__ gm, float* __restrict__ gil)
{
    constexpr int P = 72, TILE = 128 * P;
    extern __shared__ bf sm[];
    bf* skh = sm;
    bf* skl = sm + TILE;

    int bh = blockIdx.y;
    int s0 = blockIdx.x * 128;
    long base = (long)bh * TT * DKK;
    const bf* Kh = kh_ + base + (long)s0 * DKK;
    const bf* Kl = kl_ + base + (long)s0 * DKK;
    const bf* Qh = qh_ + base;
    const bf* Ql = ql_ + base;

    int tid = threadIdx.x, lane = tid & 31, wid = tid >> 5;
    int m0 = wid * 16;

    auto loadQ = [&](int ch, int s) {
        bf* dq_h = sm + 2 * TILE + s * (2 * TILE);
        bf* dq_l = dq_h + TILE;
        long q0 = (long)ch * 128;
        #pragma unroll
        for (int i = 0; i < 4; i++) {
            int c = tid + i * 256;
            int r = c >> 3, c8 = (c & 7) * 8;
            cpa16(smaddr(dq_h + r * P + c8), Qh + (q0 + r) * DKK + c8);
            cpa16(smaddr(dq_l + r * P + c8), Ql + (q0 + r) * DKK + c8);
        }
    };

    // prologue: K tile + q stage 0, one group
    #pragma unroll
    for (int i = 0; i < 4; i++) {
        int c = tid + i * 256;
        int r = c >> 3, c8 = (c & 7) * 8;
        cpa16(smaddr(skh + r * P + c8), Kh + (long)r * DKK + c8);
        cpa16(smaddr(skl + r * P + c8), Kl + (long)r * DKK + c8);
    }
    loadQ(0, 0);
    cp_commit();

    float mrow0 = -1e30f, mrow1 = -1e30f;
    float lrow0 = 0.f, lrow1 = 0.f;

    for (int ch = 0; ch < 16; ch++) {
        if (ch + 1 < 16) { loadQ(ch + 1, (ch + 1) & 1); cp_commit(); cp_wait1(); }
        else             { cp_wait0(); }
        __syncthreads();
        const bf* sq_h = sm + 2 * TILE + (ch & 1) * (2 * TILE);
        const bf* sq_l = sq_h + TILE;

        float acc[16][4] = {};
        #pragma unroll
        for (int kk = 0; kk < 64; kk += 16) {
            uint32_t ah[4], al[4];
            {
                int row = m0 + (lane & 15);
                int col = kk + (lane >> 4) * 8;
                ldsm4(ah[0], ah[1], ah[2], ah[3], smaddr(skh + row * P + col));
                ldsm4(al[0], al[1], al[2], al[3], smaddr(skl + row * P + col));
            }
            #pragma unroll
            for (int g = 0; g < 8; g++) {
                int rown = g * 16 + (lane & 7) + ((lane >> 4) & 1) * 8;
                int col = kk + ((lane >> 3) & 1) * 8;
                uint32_t b0, b1, b2, b3, c0, c1, c2, c3;
                ldsm4(b0, b1, b2, b3, smaddr(sq_h + rown * P + col));
                ldsm4(c0, c1, c2, c3, smaddr(sq_l + rown * P + col));
                mma16816(acc[2*g],   ah, b0, b1);
                mma16816(acc[2*g],   ah, c0, c1);
                mma16816(acc[2*g],   al, b0, b1);
                mma16816(acc[2*g+1], ah, b2, b3);
                mma16816(acc[2*g+1], ah, c2, c3);
                mma16816(acc[2*g+1], al, b2, b3);
            }
        }
        __syncthreads();

        float cm0 = -1e30f, cm1 = -1e30f;
        #pragma unroll
        for (int nf = 0; nf < 16; nf++) {
            cm0 = fmaxf(cm0, fmaxf(acc[nf][0], acc[nf][1]));
            cm1 = fmaxf(cm1, fmaxf(acc[nf][2], acc[nf][3]));
        }
        cm0 *= 0.125f; cm1 *= 0.125f;
        cm0 = fmaxf(cm0, __shfl_xor_sync(~0u, cm0, 1));
        cm0 = fmaxf(cm0, __shfl_xor_sync(~0u, cm0, 2));
        cm1 = fmaxf(cm1, __shfl_xor_sync(~0u, cm1, 1));
        cm1 = fmaxf(cm1, __shfl_xor_sync(~0u, cm1, 2));
        float mn0 = fmaxf(mrow0, cm0), mn1 = fmaxf(mrow1, cm1);
        float sv0 = 0.f, sv1 = 0.f;
        #pragma unroll
        for (int nf = 0; nf < 16; nf++) {
            sv0 += __expf(acc[nf][0] * 0.125f - mn0) + __expf(acc[nf][1] * 0.125f - mn0);
            sv1 += __expf(acc[nf][2] * 0.125f - mn1) + __expf(acc[nf][3] * 0.125f - mn1);
        }
        sv0 += __shfl_xor_sync(~0u, sv0, 1); sv0 += __shfl_xor_sync(~0u, sv0, 2);
        sv1 += __shfl_xor_sync(~0u, sv1, 1); sv1 += __shfl_xor_sync(~0u, sv1, 2);
        lrow0 = lrow0 * __expf(mrow0 - mn0) + sv0;
        lrow1 = lrow1 * __expf(mrow1 - mn1) + sv1;
        mrow0 = mn0; mrow1 = mn1;
    }

    if ((lane & 3) == 0) {
        int r = lane >> 2;
        long o = (long)bh * TT + s0 + m0;
        gm[o + r]      = mrow0;
        gm[o + r + 8]  = mrow1;
        gil[o + r]     = 1.f / lrow0;
        gil[o + r + 8] = 1.f / lrow1;
    }
}

// ---------------- fused attention pass 2: output ----------------------------
// Per q-tile: S = Q@K^T, p = exp(0.125*S - m_col)*invl_col, O += P@V.
__global__ __launch_bounds__(256)
void attn_out_kernel(const bf* __restrict__ qh_, const bf* __restrict__ ql_,
                     const bf* __restrict__ kh_, const bf* __restrict__ kl_,
                     const bf* __restrict__ vh_, const bf* __restrict__ vl_,
                     const float* __restrict__ gm, const float* __restrict__ gil,
                     bf* __restrict__ och, bf* __restrict__ ocl)
{
    constexpr int P = 72, TILE = 128 * P;
    constexpr int STG = 4 * TILE + 512;   // bf elems: k,v hi/lo + 1KB ml
    extern __shared__ bf sm[];
    bf* sqh = sm;
    bf* sql = sm + TILE;

    int bh = blockIdx.y;
    int q0b = blockIdx.x * 128;
    int b = bh >> 4, h = bh & 15;
    long base = (long)bh * TT * DKK;
    const bf* Qh = qh_ + base + (long)q0b * DKK;
    const bf* Ql = ql_ + base + (long)q0b * DKK;
    const bf* Kh = kh_ + base;
    const bf* Kl = kl_ + base;
    const bf* Vh = vh_ + base;
    const bf* Vl = vl_ + base;
    const float* Gm = gm + (long)bh * TT;
    const float* Gil = gil + (long)bh * TT;

    int tid = threadIdx.x, lane = tid & 31, wid = tid >> 5;
    int m0 = wid * 16;

    auto loadKV = [&](int ch, int s) {
        bf* st = sm + 2 * TILE + (size_t)s * STG;
        bf* dkh = st;
        bf* dkl = st + TILE;
        bf* dvh = st + 2 * TILE;
        bf* dvl = st + 3 * TILE;
        float* dml = (float*)(st + 4 * TILE);
        long r0 = (long)ch * 128;
        #pragma unroll
        for (int i = 0; i < 4; i++) {
            int c = tid + i * 256;
            int r = c >> 3, c8 = (c & 7) * 8;
            long go = (r0 + r) * DKK + c8;
            cpa16(smaddr(dkh + r * P + c8), Kh + go);
            cpa16(smaddr(dkl + r * P + c8), Kl + go);
            cpa16(smaddr(dvh + r * P + c8), Vh + go);
            cpa16(smaddr(dvl + r * P + c8), Vl + go);
        }
        if (tid < 32)      cpa16(smaddr(dml + tid * 4),        Gm  + r0 + tid * 4);
        else if (tid < 64) cpa16(smaddr(dml + 128 + (tid-32)*4), Gil + r0 + (tid - 32) * 4);
    };

    // prologue: q tile + stage 0
    #pragma unroll
    for (int i = 0; i < 4; i++) {
        int c = tid + i * 256;
        int r = c >> 3, c8 = (c & 7) * 8;
        cpa16(smaddr(sqh + r * P + c8), Qh + (long)r * DKK + c8);
        cpa16(smaddr(sql + r * P + c8), Ql + (long)r * DKK + c8);
    }
    loadKV(0, 0);
    cp_commit();

    float acc_o[8][4] = {};

    for (int ch = 0; ch < 16; ch++) {
        if (ch + 1 < 16) { loadKV(ch + 1, (ch + 1) & 1); cp_commit(); cp_wait1(); }
        else             { cp_wait0(); }
        __syncthreads();
        bf* st = sm + 2 * TILE + (size_t)(ch & 1) * STG;
        const bf* skh = st;
        const bf* skl = st + TILE;
        const bf* svh = st + 2 * TILE;
        const bf* svl = st + 3 * TILE;
        const float* sml = (const float*)(st + 4 * TILE);

        // ---- S = Q @ K^T (raw) ----
        float acc[16][4] = {};
        #pragma unroll
        for (int kk = 0; kk < 64; kk += 16) {
            uint32_t ah[4], al[4];
            {
                int row = m0 + (lane & 15);
                int col = kk + (lane >> 4) * 8;
                ldsm4(ah[0], ah[1], ah[2], ah[3], smaddr(sqh + row * P + col));
                ldsm4(al[0], al[1], al[2], al[3], smaddr(sql + row * P + col));
            }
            #pragma unroll
            for (int g = 0; g < 8; g++) {
                int rown = g * 16 + (lane & 7) + ((lane >> 4) & 1) * 8;
                int col = kk + ((lane >> 3) & 1) * 8;
                uint32_t b0, b1, b2, b3, c0, c1, c2, c3;
                ldsm4(b0, b1, b2, b3, smaddr(skh + rown * P + col));
                ldsm4(c0, c1, c2, c3, smaddr(skl + rown * P + col));
                mma16816(acc[2*g],   ah, b0, b1);
                mma16816(acc[2*g],   ah, c0, c1);
                mma16816(acc[2*g],   al, b0, b1);
                mma16816(acc[2*g+1], ah, b2, b3);
                mma16816(acc[2*g+1], ah, c2, c3);
                mma16816(acc[2*g+1], al, b2, b3);
            }
        }

        // ---- P = exp(0.125*S - m)*invl; O += P @ V ----
        #pragma unroll
        for (int j = 0; j < 8; j++) {
            int cL = j * 16 + (lane & 3) * 2;
            int cH = cL + 8;
            float mL0 = sml[cL],       mL1 = sml[cL + 1];
            float mH0 = sml[cH],       mH1 = sml[cH + 1];
            float iL0 = sml[128 + cL], iL1 = sml[128 + cL + 1];
            float iH0 = sml[128 + cH], iH1 = sml[128 + cH + 1];

            float p00 = __expf(acc[2*j][0]   * 0.125f - mL0) * iL0;
            float p01 = __expf(acc[2*j][1]   * 0.125f - mL1) * iL1;
            float p10 = __expf(acc[2*j][2]   * 0.125f - mL0) * iL0;
            float p11 = __expf(acc[2*j][3]   * 0.125f - mL1) * iL1;
            float q00 = __expf(acc[2*j+1][0] * 0.125f - mH0) * iH0;
            float q01 = __expf(acc[2*j+1][1] * 0.125f - mH1) * iH1;
            float q10 = __expf(acc[2*j+1][2] * 0.125f - mH0) * iH0;
            float q11 = __expf(acc[2*j+1][3] * 0.125f - mH1) * iH1;

            bf h0, l0, h1, l1;
            uint32_t pa_h[4], pa_l[4];
            split1(p00, h0, l0); split1(p01, h1, l1);
            pa_h[0] = pack2(h0, h1); pa_l[0] = pack2(l0, l1);
            split1(p10, h0, l0); split1(p11, h1, l1);
            pa_h[1] = pack2(h0, h1); pa_l[1] = pack2(l0, l1);
            split1(q00, h0, l0); split1(q01, h1, l1);
            pa_h[2] = pack2(h0, h1); pa_l[2] = pack2(l0, l1);
            split1(q10, h0, l0); split1(q11, h1, l1);
            pa_h[3] = pack2(h0, h1); pa_l[3] = pack2(l0, l1);

            #pragma unroll
            for (int g2 = 0; g2 < 4; g2++) {
                int rowk = j * 16 + (lane & 7) + ((lane >> 3) & 1) * 8;
                int coln = g2 * 16 + (lane >> 4) * 8;
                uint32_t b0, b1, b2, b3, c0, c1, c2, c3;
                ldsm4t(b0, b1, b2, b3, smaddr(svh + rowk * P + coln));
                ldsm4t(c0, c1, c2, c3, smaddr(svl + rowk * P + coln));
                mma16816(acc_o[2*g2],   pa_h, b0, b1);
                mma16816(acc_o[2*g2],   pa_l, b0, b1);
                mma16816(acc_o[2*g2],   pa_h, c0, c1);
                mma16816(acc_o[2*g2+1], pa_h, b2, b3);
                mma16816(acc_o[2*g2+1], pa_l, b2, b3);
                mma16816(acc_o[2*g2+1], pa_h, c2, c3);
            }
        }
        __syncthreads();
    }

    // ---- epilogue: write (B,T,H*DV) split bf16 ----
    #pragma unroll
    for (int nf = 0; nf < 8; nf++) {
        long r0 = (long)b * TT + q0b + m0 + (lane >> 2);
        long r1 = r0 + 8;
        long c = (long)h * 64 + nf * 8 + (lane & 3) * 2;
        bf h0, l0, h1, l1;
        split1(acc_o[nf][0], h0, l0); split1(acc_o[nf][1], h1, l1);
        *(uint32_t*)&och[r0 * DD + c] = pack2(h0, h1);
        *(uint32_t*)&ocl[r0 * DD + c] = pack2(l0, l1);
        split1(acc_o[nf][2], h0, l0); split1(acc_o[nf][3], h1, l1);
        *(uint32_t*)&och[r1 * DD + c] = pack2(h0, h1);
        *(uint32_t*)&ocl[r1 * DD + c] = pack2(l0, l1);
    }
}

// ---------------- fp32 -> bf16 hi/lo split ---------------------------------
__global__ void split_kernel(const float4* __restrict__ in, uint2* __restrict__ hi,
                             uint2* __restrict__ lo, long n4)
{
    long i = (long)blockIdx.x * blockDim.x + threadIdx.x;
    if (i >= n4) return;
    float4 v = in[i];
    bf h0, l0, h1, l1, h2, l2, h3, l3;
    split1(v.x, h0, l0); split1(v.y, h1, l1);
    split1(v.z, h2, l2); split1(v.w, h3, l3);
    uint2 o;
    o.x = pack2(h0, h1); o.y = pack2(h2, h3);
    hi[i] = o;
    o.x = pack2(l0, l1); o.y = pack2(l2, l3);
    lo[i] = o;
}

// --------- out = meanstd_norm(a + b); optional bf16 hi/lo output -----------
template <bool WSPLIT>
__global__ void add_norm_kernel(const float* __restrict__ a, const float* __restrict__ b,
                                float* __restrict__ out, bf* __restrict__ oh,
                                bf* __restrict__ ol)
{
    const int D = DD;
    long r = blockIdx.x;
    const float* pa = a + r * D;
    const float* pb = b + r * D;
    int tid = threadIdx.x;

    float y[4];
    float sum = 0.f;
    #pragma unroll
    for (int i = 0; i < 4; i++) {
        y[i] = pa[tid + i * 256] + pb[tid + i * 256];
        sum += y[i];
    }

    __shared__ float red[8];
    #pragma unroll
    for (int o = 16; o > 0; o >>= 1) sum += __shfl_xor_sync(~0u, sum, o);
    if ((tid & 31) == 0) red[tid >> 5] = sum;
    __syncthreads();
    if (tid < 32) {
        float v = (tid < 8) ? red[tid] : 0.f;
        #pragma unroll
        for (int o = 4; o > 0; o >>= 1) v += __shfl_xor_sync(~0u, v, o);
        if (tid == 0) red[0] = v;
    }
    __syncthreads();
    float mean = red[0] / D;
    __syncthreads();

    float vs = 0.f;
    #pragma unroll
    for (int i = 0; i < 4; i++) {
        float d = y[i] - mean;
        vs += d * d;
    }
    #pragma unroll
    for (int o = 16; o > 0; o >>= 1) vs += __shfl_xor_sync(~0u, vs, o);
    if ((tid & 31) == 0) red[tid >> 5] = vs;
    __syncthreads();
    if (tid < 32) {
        float v = (tid < 8) ? red[tid] : 0.f;
        #pragma unroll
        for (int o = 4; o > 0; o >>= 1) v += __shfl_xor_sync(~0u, v, o);
        if (tid == 0) red[0] = v;
    }
    __syncthreads();
    float inv = rsqrtf(red[0] / (float)(D - 1));

    #pragma unroll
    for (int i = 0; i < 4; i++) {
        float v = (y[i] - mean) * inv;
        long idx = r * D + tid + i * 256;
        out[idx] = v;
        if constexpr (WSPLIT) {
            bf h, l;
            split1(v, h, l);
            oh[idx] = h;
            ol[idx] = l;
        }
    }
}

// ---------------------------------------------------------------------------
static inline void* sym(const void* s) {
    void* p = nullptr;
    cudaGetSymbolAddress(&p, s);
    return p;
}

extern "C" void kernel_launch(void* const* d_in, const int* in_sizes, int n_in,
                              void* d_out, int out_size)
{
    const float* x  = (const float*)d_in[0];
    const float* Wq = (const float*)d_in[1];
    const float* Wk = (const float*)d_in[2];
    const float* Wv = (const float*)d_in[3];
    const float* Wo = (const float*)d_in[4];
    const float* W1 = (const float*)d_in[5];
    const float* b1 = (const float*)d_in[6];
    const float* W2 = (const float*)d_in[7];
    const float* b2 = (const float*)d_in[8];
    float* out = (float*)d_out;

    float* tp = (float*)sym(g_tmp);
    float* o1 = (float*)sym(g_out1);
    float* gm = (float*)sym(g_m);
    float* gil = (float*)sym(g_il);
    bf *xh = (bf*)sym(g_xh), *xl = (bf*)sym(g_xl);
    bf *wqh = (bf*)sym(g_wqh), *wql = (bf*)sym(g_wql);
    bf *wkh = (bf*)sym(g_wkh), *wkl = (bf*)sym(g_wkl);
    bf *wvh = (bf*)sym(g_wvh), *wvl = (bf*)sym(g_wvl);
    bf *woh = (bf*)sym(g_woh), *wol = (bf*)sym(g_wol);
    bf *w1h = (bf*)sym(g_w1h), *w1l = (bf*)sym(g_w1l);
    bf *w2h = (bf*)sym(g_w2h), *w2l = (bf*)sym(g_w2l);
    bf *qh = (bf*)sym(g_qh), *ql = (bf*)sym(g_ql);
    bf *kh = (bf*)sym(g_kh), *kl = (bf*)sym(g_kl);
    bf *vh = (bf*)sym(g_vh), *vl = (bf*)sym(g_vl);
    bf *och = (bf*)sym(g_och), *ocl = (bf*)sym(g_ocl);
    bf *o1h = (bf*)sym(g_o1h), *o1l = (bf*)sym(g_o1l);
    bf *fhh = (bf*)sym(g_fhh), *fhl = (bf*)sym(g_fhl);

    const long TD  = (long)TT * DD;
    const long HD  = (long)DD * DKK;
    const long HT  = (long)TT * DKK;
    const long BHT = (long)HH * HT;

    constexpr int SM_N128 = (2 * 128 * 40 + 2 * 32 * 136) * 2 * 2;
    constexpr int SM_N64  = (2 * 128 * 40 + 2 * 32 * 72) * 2 * 2;
    constexpr int SM_AT1  = 3 * (2 * 128 * 72) * 2;                   // 110592
    constexpr int SM_AT2  = (2 * 128 * 72 + 2 * (4 * 128 * 72 + 512)) * 2;  // 186368
    cudaFuncSetAttribute(mgemm<64, false, false, false, false, true>,
                         cudaFuncAttributeMaxDynamicSharedMemorySize, SM_N64);
    cudaFuncSetAttribute(mgemm<128, false, false, false, true, false>,
                         cudaFuncAttributeMaxDynamicSharedMemorySize, SM_N128);
    cudaFuncSetAttribute(mgemm<128, false, true, true, false, true>,
                         cudaFuncAttributeMaxDynamicSharedMemorySize, SM_N128);
    cudaFuncSetAttribute(mgemm<128, false, true, false, true, false>,
                         cudaFuncAttributeMaxDynamicSharedMemorySize, SM_N128);
    cudaFuncSetAttribute(attn_stats_kernel,
                         cudaFuncAttributeMaxDynamicSharedMemorySize, SM_AT1);
    cudaFuncSetAttribute(attn_out_kernel,
                         cudaFuncAttributeMaxDynamicSharedMemorySize, SM_AT2);

    // 0) split fp32 -> bf16 hi/lo
    auto split = [&](const float* in, bf* hi, bf* lo, long n) {
        long n4 = n / 4;
        split_kernel<<<(unsigned)((n4 + 255) / 256), 256>>>(
            (const float4*)in, (uint2*)hi, (uint2*)lo, n4);
    };
    split(x,  xh,  xl,  (long)BB * TT * DD);
    split(Wq, wqh, wql, (long)HH * DD * DKK);
    split(Wk, wkh, wkl, (long)HH * DD * DKK);
    split(Wv, wvh, wvl, (long)HH * DD * DKK);
    split(Wo, woh, wol, (long)DD * DD);
    split(W1, w1h, w1l, (long)DD * FFF);
    split(W2, w2h, w2l, (long)FFF * DD);

    // 1) Q,K,V projections
    dim3 gproj(1, TT / 128, BB * HH);
    mgemm<64, false, false, false, false, true><<<gproj, 256, SM_N64>>>(
        xh, xl, wqh, wql, nullptr, qh, ql, nullptr,
        DD, DD, DKK, DKK, 1.f, TD, 0, 0, HD, BHT, HT, HH);
    mgemm<64, false, false, false, false, true><<<gproj, 256, SM_N64>>>(
        xh, xl, wkh, wkl, nullptr, kh, kl, nullptr,
        DD, DD, DKK, DKK, 1.f, TD, 0, 0, HD, BHT, HT, HH);
    mgemm<64, false, false, false, false, true><<<gproj, 256, SM_N64>>>(
        xh, xl, wvh, wvl, nullptr, vh, vl, nullptr,
        DD, DD, DKK, DKK, 1.f, TD, 0, 0, HD, BHT, HT, HH);

    // 2) fused attention: stats, then output (no T*T materialization)
    dim3 gat(TT / 128, BB * HH);
    attn_stats_kernel<<<gat, 256, SM_AT1>>>(qh, ql, kh, kl, gm, gil);
    attn_out_kernel<<<gat, 256, SM_AT2>>>(qh, ql, kh, kl, vh, vl, gm, gil, och, ocl);

    // 3) tmp = ocat @ Wo
    dim3 gwo(DD / 128, (BB * TT) / 128, 1);
    mgemm<128, false, false, false, true, false><<<gwo, 256, SM_N128>>>(
        och, ocl, woh, wol, tp, nullptr, nullptr, nullptr,
        DD, DD, DD, DD, 1.f, 0, 0, 0, 0, 0, 0, 1);

    // 4) out1 = norm(tmp + x), plus split for FFN
    add_norm_kernel<true><<<BB * TT, 256>>>(tp, x, o1, o1h, o1l);

    // 5) ffh = relu(out1 @ W1 + b1)
    dim3 gf1(FFF / 128, (BB * TT) / 128, 1);
    mgemm<128, false, true, true, false, true><<<gf1, 256, SM_N128>>>(
        o1h, o1l, w1h, w1l, nullptr, fhh, fhl, b1,
        DD, DD, FFF, FFF, 1.f, 0, 0, 0, 0, 0, 0, 1);

    // 6) tmp = ffh @ W2 + b2
    dim3 gf2(DD / 128, (BB * TT) / 128, 1);
    mgemm<128, false, true, false, true, false><<<gf2, 256, SM_N128>>>(
        fhh, fhl, w2h, w2l, tp, nullptr, nullptr, b2,
        FFF, FFF, DD, DD, 1.f, 0, 0, 0, 0, 0, 0, 1);

    // 7) out = norm(tmp + out1)
    add_norm_kernel<false><<<BB * TT, 256>>>(tp, o1, out, nullptr, nullptr);
}

// round 6
// speedup vs baseline: 5.5535x; 1.4218x over previous
#include <cuda_runtime.h>
#include <cuda_bf16.h>
#include <cstdint>

#define BB 2
#define TT 2048
#define DD 1024
#define HH 16
#define DKK 64
#define FFF 4096

using bf = __nv_bfloat16;

// ---------------- scratch (static device memory; no allocs) ----------------
__device__ __align__(256) float g_tmp[(size_t)BB * TT * DD];
__device__ __align__(256) float g_out1[(size_t)BB * TT * DD];
__device__ __align__(256) float g_m[(size_t)BB * HH * TT];
__device__ __align__(256) float g_il[(size_t)BB * HH * TT];

__device__ __align__(256) bf g_xb[(size_t)BB * TT * DD];
__device__ __align__(256) bf g_wq[(size_t)HH * DD * DKK];
__device__ __align__(256) bf g_wk[(size_t)HH * DD * DKK];
__device__ __align__(256) bf g_wv[(size_t)HH * DD * DKK];
__device__ __align__(256) bf g_wo[(size_t)DD * DD];
__device__ __align__(256) bf g_w1h[(size_t)DD * FFF];
__device__ __align__(256) bf g_w1l[(size_t)DD * FFF];
__device__ __align__(256) bf g_w2h[(size_t)FFF * DD];
__device__ __align__(256) bf g_w2l[(size_t)FFF * DD];
__device__ __align__(256) bf g_q[(size_t)BB * HH * TT * DKK];
__device__ __align__(256) bf g_k[(size_t)BB * HH * TT * DKK];
__device__ __align__(256) bf g_v[(size_t)BB * HH * TT * DKK];
__device__ __align__(256) bf g_oc[(size_t)BB * TT * DD];
__device__ __align__(256) bf g_o1h[(size_t)BB * TT * DD];
__device__ __align__(256) bf g_o1l[(size_t)BB * TT * DD];
__device__ __align__(256) bf g_fhh[(size_t)BB * TT * FFF];
__device__ __align__(256) bf g_fhl[(size_t)BB * TT * FFF];

// ---------------- small helpers -------------------------------------------
__device__ __forceinline__ uint32_t smaddr(const void* p) {
    return (uint32_t)__cvta_generic_to_shared(p);
}
__device__ __forceinline__ void cpa16(uint32_t s, const void* g) {
    asm volatile("cp.async.cg.shared.global [%0], [%1], 16;\n" :: "r"(s), "l"(g));
}
__device__ __forceinline__ void cp_commit() {
    asm volatile("cp.async.commit_group;\n" ::: "memory");
}
__device__ __forceinline__ void cp_wait1() {
    asm volatile("cp.async.wait_group 1;\n" ::: "memory");
}
__device__ __forceinline__ void cp_wait0() {
    asm volatile("cp.async.wait_group 0;\n" ::: "memory");
}
__device__ __forceinline__ void ldsm4(uint32_t& r0, uint32_t& r1, uint32_t& r2, uint32_t& r3, uint32_t a) {
    asm volatile("ldmatrix.sync.aligned.m8n8.x4.shared.b16 {%0,%1,%2,%3}, [%4];\n"
                 : "=r"(r0), "=r"(r1), "=r"(r2), "=r"(r3) : "r"(a));
}
__device__ __forceinline__ void ldsm4t(uint32_t& r0, uint32_t& r1, uint32_t& r2, uint32_t& r3, uint32_t a) {
    asm volatile("ldmatrix.sync.aligned.m8n8.x4.trans.shared.b16 {%0,%1,%2,%3}, [%4];\n"
                 : "=r"(r0), "=r"(r1), "=r"(r2), "=r"(r3) : "r"(a));
}
__device__ __forceinline__ void mma16816(float* d, const uint32_t* a, uint32_t b0, uint32_t b1) {
    asm volatile(
        "mma.sync.aligned.m16n8k16.row.col.f32.bf16.bf16.f32 "
        "{%0,%1,%2,%3}, {%4,%5,%6,%7}, {%8,%9}, {%0,%1,%2,%3};\n"
        : "+f"(d[0]), "+f"(d[1]), "+f"(d[2]), "+f"(d[3])
        : "r"(a[0]), "r"(a[1]), "r"(a[2]), "r"(a[3]), "r"(b0), "r"(b1));
}
__device__ __forceinline__ void split1(float v, bf& h, bf& l) {
    h = __float2bfloat16(v);
    l = __float2bfloat16(v - __bfloat162float(h));
}
__device__ __forceinline__ uint32_t pack2(bf a, bf b) {
    __nv_bfloat162 p; p.x = a; p.y = b;
    return *(uint32_t*)&p;
}

// ---------------- bf16-split tensor-core GEMM (FFN path) -------------------
template <int BN, bool TRANSB, bool BIAS, bool RELU, bool OF32, bool OSPLIT>
__global__ __launch_bounds__(256)
void mgemm(const bf* __restrict__ Ah, const bf* __restrict__ Al,
           const bf* __restrict__ Bh, const bf* __restrict__ Bl,
           float* __restrict__ C, bf* __restrict__ Ch, bf* __restrict__ Cl,
           const float* __restrict__ bias,
           int K, int lda, int ldb, int ldc, float alpha,
           long soA, long siA, long soB, long siB, long soC, long siC, int inner)
{
    constexpr int BM = 128, BK = 32, AP = 40;
    constexpr int BP = TRANSB ? 40 : (BN + 8);
    constexpr int AE = BM * AP;
    constexpr int BE = TRANSB ? (BN * AP) : (BK * BP);
    constexpr int STG = 2 * AE + 2 * BE;
    extern __shared__ bf sm[];

    int z = blockIdx.z;
    int zo = z / inner, zi = z - zo * inner;
    long aoff = zo * soA + zi * siA;
    long boff = zo * soB + zi * siB;
    long coff = zo * soC + zi * siC;
    Ah += aoff; Al += aoff;
    Bh += boff; Bl += boff;

    int tid = threadIdx.x, lane = tid & 31, wid = tid >> 5;
    constexpr int MF = (BN == 128) ? 4 : 2;
    constexpr int NF = 4;
    int wm = (BN == 128) ? (wid >> 2) : (wid >> 1);
    int wn = (BN == 128) ? (wid & 3) : (wid & 1);
    int m0 = wm * MF * 16, n0 = wn * 32;

    long bm = (long)blockIdx.y * BM, bn = (long)blockIdx.x * BN;

    float acc[MF][NF][4] = {};

    auto copyStage = [&](int kt, int s) {
        int k0 = kt * BK;
        bf* sa_h = sm + (size_t)s * STG;
        bf* sa_l = sa_h + AE;
        bf* sb_h = sa_l + AE;
        bf* sb_l = sb_h + BE;
        #pragma unroll
        for (int i = 0; i < 2; i++) {
            int c = tid + i * 256;
            int r = c >> 2, cc = (c & 3) * 8;
            long go = (bm + r) * (long)lda + k0 + cc;
            cpa16(smaddr(sa_h + r * AP + cc), Ah + go);
            cpa16(smaddr(sa_l + r * AP + cc), Al + go);
        }
        if constexpr (TRANSB) {
            #pragma unroll
            for (int i = 0; i < BN / 64; i++) {
                int c = tid + i * 256;
                int r = c >> 2, cc = (c & 3) * 8;
                long go = (bn + r) * (long)ldb + k0 + cc;
                cpa16(smaddr(sb_h + r * AP + cc), Bh + go);
                cpa16(smaddr(sb_l + r * AP + cc), Bl + go);
            }
        } else {
            constexpr int CPR = BN / 8;
            #pragma unroll
            for (int i = 0; i < (32 * CPR) / 256; i++) {
                int c = tid + i * 256;
                int r = c / CPR, cc = (c % CPR) * 8;
                long go = (long)(k0 + r) * ldb + bn + cc;
                cpa16(smaddr(sb_h + r * BP + cc), Bh + go);
                cpa16(smaddr(sb_l + r * BP + cc), Bl + go);
            }
        }
        cp_commit();
    };

    auto compute = [&](int s) {
        const bf* sa_h = sm + (size_t)s * STG;
        const bf* sa_l = sa_h + AE;
        const bf* sb_h = sa_l + AE;
        const bf* sb_l = sb_h + BE;
        #pragma unroll
        for (int kk = 0; kk < BK; kk += 16) {
            uint32_t ah[MF][4], al[MF][4];
            #pragma unroll
            for (int mf = 0; mf < MF; mf++) {
                int row = m0 + mf * 16 + (lane & 15);
                int col = kk + (lane >> 4) * 8;
                ldsm4(ah[mf][0], ah[mf][1], ah[mf][2], ah[mf][3],
                      smaddr(sa_h + row * AP + col));
                ldsm4(al[mf][0], al[mf][1], al[mf][2], al[mf][3],
                      smaddr(sa_l + row * AP + col));
            }
            uint32_t bh2[NF][2], bl2[NF][2];
            #pragma unroll
            for (int g = 0; g < 2; g++) {
                if constexpr (TRANSB) {
                    int rown = n0 + g * 16 + (lane & 7) + ((lane >> 4) & 1) * 8;
                    int col = kk + ((lane >> 3) & 1) * 8;
                    ldsm4(bh2[2*g][0], bh2[2*g][1], bh2[2*g+1][0], bh2[2*g+1][1],
                          smaddr(sb_h + rown * AP + col));
                    ldsm4(bl2[2*g][0], bl2[2*g][1], bl2[2*g+1][0], bl2[2*g+1][1],
                          smaddr(sb_l + rown * AP + col));
                } else {
                    int rowk = kk + (lane & 7) + ((lane >> 3) & 1) * 8;
                    int coln = n0 + g * 16 + (lane >> 4) * 8;
                    ldsm4t(bh2[2*g][0], bh2[2*g][1], bh2[2*g+1][0], bh2[2*g+1][1],
                           smaddr(sb_h + rowk * BP + coln));
                    ldsm4t(bl2[2*g][0], bl2[2*g][1], bl2[2*g+1][0], bl2[2*g+1][1],
                           smaddr(sb_l + rowk * BP + coln));
                }
            }
            #pragma unroll
            for (int mf = 0; mf < MF; mf++)
                #pragma unroll
                for (int nf = 0; nf < NF; nf++) {
                    mma16816(acc[mf][nf], ah[mf], bh2[nf][0], bh2[nf][1]);
                    mma16816(acc[mf][nf], ah[mf], bl2[nf][0], bl2[nf][1]);
                    mma16816(acc[mf][nf], al[mf], bh2[nf][0], bh2[nf][1]);
                }
        }
    };

    int nk = K / BK;
    copyStage(0, 0);
    for (int kt = 0; kt < nk; kt++) {
        if (kt + 1 < nk) { copyStage(kt + 1, (kt + 1) & 1); cp_wait1(); }
        else             { cp_wait0(); }
        __syncthreads();
        compute(kt & 1);
        __syncthreads();
    }

    #pragma unroll
    for (int mf = 0; mf < MF; mf++) {
        #pragma unroll
        for (int nf = 0; nf < NF; nf++) {
            long r0 = bm + m0 + mf * 16 + (lane >> 2);
            long r1 = r0 + 8;
            long c  = bn + n0 + nf * 8 + (lane & 3) * 2;
            float v00 = acc[mf][nf][0] * alpha;
            float v01 = acc[mf][nf][1] * alpha;
            float v10 = acc[mf][nf][2] * alpha;
            float v11 = acc[mf][nf][3] * alpha;
            if constexpr (BIAS) {
                float b0v = bias[c], b1v = bias[c + 1];
                v00 += b0v; v01 += b1v; v10 += b0v; v11 += b1v;
            }
            if constexpr (RELU) {
                v00 = fmaxf(v00, 0.f); v01 = fmaxf(v01, 0.f);
                v10 = fmaxf(v10, 0.f); v11 = fmaxf(v11, 0.f);
            }
            if constexpr (OF32) {
                float2 p0 = {v00, v01}, p1 = {v10, v11};
                *(float2*)&C[coff + r0 * ldc + c] = p0;
                *(float2*)&C[coff + r1 * ldc + c] = p1;
            }
            if constexpr (OSPLIT) {
                bf h0, l0, h1, l1;
                split1(v00, h0, l0); split1(v01, h1, l1);
                *(uint32_t*)&Ch[coff + r0 * ldc + c] = pack2(h0, h1);
                *(uint32_t*)&Cl[coff + r0 * ldc + c] = pack2(l0, l1);
                split1(v10, h0, l0); split1(v11, h1, l1);
                *(uint32_t*)&Ch[coff + r1 * ldc + c] = pack2(h0, h1);
                *(uint32_t*)&Cl[coff + r1 * ldc + c] = pack2(l0, l1);
            }
        }
    }
}

// ---------------- plain-bf16 tensor-core GEMM (attention branch) -----------
// C = A * B. A:[M,K] k-contig. B:[K,N] row-major. 1 MMA per tile product.
template <int BN, bool OF32>
__global__ __launch_bounds__(256, 2)
void bgemm(const bf* __restrict__ A, const bf* __restrict__ B,
           float* __restrict__ C, bf* __restrict__ Cb,
           int K, int lda, int ldb, int ldc,
           long soA, long siA, long soB, long siB, long soC, long siC, int inner)
{
    constexpr int BM = 128, BK = 32, AP = 40, BP = BN + 8;
    constexpr int AE = BM * AP, BE = BK * BP, STG = AE + BE;
    extern __shared__ bf sm[];

    int z = blockIdx.z;
    int zo = z / inner, zi = z - zo * inner;
    A += zo * soA + zi * siA;
    B += zo * soB + zi * siB;
    long coff = zo * soC + zi * siC;

    int tid = threadIdx.x, lane = tid & 31, wid = tid >> 5;
    constexpr int MF = (BN == 128) ? 4 : 2;
    constexpr int NF = 4;
    int wm = (BN == 128) ? (wid >> 2) : (wid >> 1);
    int wn = (BN == 128) ? (wid & 3) : (wid & 1);
    int m0 = wm * MF * 16, n0 = wn * 32;

    long bm = (long)blockIdx.y * BM, bn = (long)blockIdx.x * BN;

    float acc[MF][NF][4] = {};

    auto copyStage = [&](int kt, int s) {
        int k0 = kt * BK;
        bf* sa = sm + (size_t)s * STG;
        bf* sb = sa + AE;
        #pragma unroll
        for (int i = 0; i < 2; i++) {
            int c = tid + i * 256;
            int r = c >> 2, cc = (c & 3) * 8;
            cpa16(smaddr(sa + r * AP + cc), A + (bm + r) * (long)lda + k0 + cc);
        }
        constexpr int CPR = BN / 8;
        #pragma unroll
        for (int i = 0; i < (32 * CPR) / 256; i++) {
            int c = tid + i * 256;
            int r = c / CPR, cc = (c % CPR) * 8;
            cpa16(smaddr(sb + r * BP + cc), B + (long)(k0 + r) * ldb + bn + cc);
        }
        cp_commit();
    };

    auto compute = [&](int s) {
        const bf* sa = sm + (size_t)s * STG;
        const bf* sb = sa + AE;
        #pragma unroll
        for (int kk = 0; kk < BK; kk += 16) {
            uint32_t a[MF][4];
            #pragma unroll
            for (int mf = 0; mf < MF; mf++) {
                int row = m0 + mf * 16 + (lane & 15);
                int col = kk + (lane >> 4) * 8;
                ldsm4(a[mf][0], a[mf][1], a[mf][2], a[mf][3],
                      smaddr(sa + row * AP + col));
            }
            uint32_t b2[NF][2];
            #pragma unroll
            for (int g = 0; g < 2; g++) {
                int rowk = kk + (lane & 7) + ((lane >> 3) & 1) * 8;
                int coln = n0 + g * 16 + (lane >> 4) * 8;
                ldsm4t(b2[2*g][0], b2[2*g][1], b2[2*g+1][0], b2[2*g+1][1],
                       smaddr(sb + rowk * BP + coln));
            }
            #pragma unroll
            for (int mf = 0; mf < MF; mf++)
                #pragma unroll
                for (int nf = 0; nf < NF; nf++)
                    mma16816(acc[mf][nf], a[mf], b2[nf][0], b2[nf][1]);
        }
    };

    int nk = K / BK;
    copyStage(0, 0);
    for (int kt = 0; kt < nk; kt++) {
        if (kt + 1 < nk) { copyStage(kt + 1, (kt + 1) & 1); cp_wait1(); }
        else             { cp_wait0(); }
        __syncthreads();
        compute(kt & 1);
        __syncthreads();
    }

    #pragma unroll
    for (int mf = 0; mf < MF; mf++) {
        #pragma unroll
        for (int nf = 0; nf < NF; nf++) {
            long r0 = bm + m0 + mf * 16 + (lane >> 2);
            long r1 = r0 + 8;
            long c  = bn + n0 + nf * 8 + (lane & 3) * 2;
            if constexpr (OF32) {
                float2 p0 = {acc[mf][nf][0], acc[mf][nf][1]};
                float2 p1 = {acc[mf][nf][2], acc[mf][nf][3]};
                *(float2*)&C[coff + r0 * ldc + c] = p0;
                *(float2*)&C[coff + r1 * ldc + c] = p1;
            } else {
                *(uint32_t*)&Cb[coff + r0 * ldc + c] =
                    pack2(__float2bfloat16(acc[mf][nf][0]), __float2bfloat16(acc[mf][nf][1]));
                *(uint32_t*)&Cb[coff + r1 * ldc + c] =
                    pack2(__float2bfloat16(acc[mf][nf][2]), __float2bfloat16(acc[mf][nf][3]));
            }
        }
    }
}

// ---------------- fused attention pass 1: column-softmax stats --------------
__global__ __launch_bounds__(256, 2)
void attn_stats_kernel(const bf* __restrict__ q_, const bf* __restrict__ k_,
                       float* __restrict__ gm, float* __restrict__ gil)
{
    constexpr int P = 72, TILE = 128 * P;
    extern __shared__ bf sm[];
    bf* sk = sm;

    int bh = blockIdx.y;
    int s0 = blockIdx.x * 128;
    long base = (long)bh * TT * DKK;
    const bf* Kp = k_ + base + (long)s0 * DKK;
    const bf* Qp = q_ + base;

    int tid = threadIdx.x, lane = tid & 31, wid = tid >> 5;
    int m0 = wid * 16;

    auto loadQ = [&](int ch, int s) {
        bf* dq = sm + TILE + (size_t)s * TILE;
        long q0 = (long)ch * 128;
        #pragma unroll
        for (int i = 0; i < 4; i++) {
            int c = tid + i * 256;
            int r = c >> 3, c8 = (c & 7) * 8;
            cpa16(smaddr(dq + r * P + c8), Qp + (q0 + r) * DKK + c8);
        }
    };

    #pragma unroll
    for (int i = 0; i < 4; i++) {
        int c = tid + i * 256;
        int r = c >> 3, c8 = (c & 7) * 8;
        cpa16(smaddr(sk + r * P + c8), Kp + (long)r * DKK + c8);
    }
    loadQ(0, 0);
    cp_commit();

    float mrow0 = -1e30f, mrow1 = -1e30f;
    float lrow0 = 0.f, lrow1 = 0.f;

    for (int ch = 0; ch < 16; ch++) {
        if (ch + 1 < 16) { loadQ(ch + 1, (ch + 1) & 1); cp_commit(); cp_wait1(); }
        else             { cp_wait0(); }
        __syncthreads();
        const bf* sq = sm + TILE + (size_t)(ch & 1) * TILE;

        float acc[16][4] = {};
        #pragma unroll
        for (int kk = 0; kk < 64; kk += 16) {
            uint32_t a[4];
            {
                int row = m0 + (lane & 15);
                int col = kk + (lane >> 4) * 8;
                ldsm4(a[0], a[1], a[2], a[3], smaddr(sk + row * P + col));
            }
            #pragma unroll
            for (int g = 0; g < 8; g++) {
                int rown = g * 16 + (lane & 7) + ((lane >> 4) & 1) * 8;
                int col = kk + ((lane >> 3) & 1) * 8;
                uint32_t b0, b1, b2, b3;
                ldsm4(b0, b1, b2, b3, smaddr(sq + rown * P + col));
                mma16816(acc[2*g],   a, b0, b1);
                mma16816(acc[2*g+1], a, b2, b3);
            }
        }
        __syncthreads();

        float cm0 = -1e30f, cm1 = -1e30f;
        #pragma unroll
        for (int nf = 0; nf < 16; nf++) {
            cm0 = fmaxf(cm0, fmaxf(acc[nf][0], acc[nf][1]));
            cm1 = fmaxf(cm1, fmaxf(acc[nf][2], acc[nf][3]));
        }
        cm0 *= 0.125f; cm1 *= 0.125f;
        cm0 = fmaxf(cm0, __shfl_xor_sync(~0u, cm0, 1));
        cm0 = fmaxf(cm0, __shfl_xor_sync(~0u, cm0, 2));
        cm1 = fmaxf(cm1, __shfl_xor_sync(~0u, cm1, 1));
        cm1 = fmaxf(cm1, __shfl_xor_sync(~0u, cm1, 2));
        float mn0 = fmaxf(mrow0, cm0), mn1 = fmaxf(mrow1, cm1);
        float sv0 = 0.f, sv1 = 0.f;
        #pragma unroll
        for (int nf = 0; nf < 16; nf++) {
            sv0 += __expf(acc[nf][0] * 0.125f - mn0) + __expf(acc[nf][1] * 0.125f - mn0);
            sv1 += __expf(acc[nf][2] * 0.125f - mn1) + __expf(acc[nf][3] * 0.125f - mn1);
        }
        sv0 += __shfl_xor_sync(~0u, sv0, 1); sv0 += __shfl_xor_sync(~0u, sv0, 2);
        sv1 += __shfl_xor_sync(~0u, sv1, 1); sv1 += __shfl_xor_sync(~0u, sv1, 2);
        lrow0 = lrow0 * __expf(mrow0 - mn0) + sv0;
        lrow1 = lrow1 * __expf(mrow1 - mn1) + sv1;
        mrow0 = mn0; mrow1 = mn1;
    }

    if ((lane & 3) == 0) {
        int r = lane >> 2;
        long o = (long)bh * TT + s0 + m0;
        gm[o + r]      = mrow0;
        gm[o + r + 8]  = mrow1;
        gil[o + r]     = 1.f / lrow0;
        gil[o + r + 8] = 1.f / lrow1;
    }
}

// ---------------- fused attention pass 2: output ----------------------------
__global__ __launch_bounds__(256)
void attn_out_kernel(const bf* __restrict__ q_, const bf* __restrict__ k_,
                     const bf* __restrict__ v_,
                     const float* __restrict__ gm, const float* __restrict__ gil,
                     bf* __restrict__ oc)
{
    constexpr int P = 72, TILE = 128 * P;
    constexpr int STG = 2 * TILE + 512;   // K + V + 1KB stats (bf elems)
    extern __shared__ bf sm[];
    bf* sq = sm;

    int bh = blockIdx.y;
    int q0b = blockIdx.x * 128;
    int b = bh >> 4, h = bh & 15;
    long base = (long)bh * TT * DKK;
    const bf* Qp = q_ + base + (long)q0b * DKK;
    const bf* Kp = k_ + base;
    const bf* Vp = v_ + base;
    const float* Gm = gm + (long)bh * TT;
    const float* Gil = gil + (long)bh * TT;

    int tid = threadIdx.x, lane = tid & 31, wid = tid >> 5;
    int m0 = wid * 16;

    auto loadKV = [&](int ch, int s) {
        bf* st = sm + TILE + (size_t)s * STG;
        bf* dk = st;
        bf* dv = st + TILE;
        float* dml = (float*)(st + 2 * TILE);
        long r0 = (long)ch * 128;
        #pragma unroll
        for (int i = 0; i < 4; i++) {
            int c = tid + i * 256;
            int r = c >> 3, c8 = (c & 7) * 8;
            long go = (r0 + r) * DKK + c8;
            cpa16(smaddr(dk + r * P + c8), Kp + go);
            cpa16(smaddr(dv + r * P + c8), Vp + go);
        }
        if (tid < 32)      cpa16(smaddr(dml + tid * 4),          Gm  + r0 + tid * 4);
        else if (tid < 64) cpa16(smaddr(dml + 128 + (tid-32)*4), Gil + r0 + (tid - 32) * 4);
    };

    #pragma unroll
    for (int i = 0; i < 4; i++) {
        int c = tid + i * 256;
        int r = c >> 3, c8 = (c & 7) * 8;
        cpa16(smaddr(sq + r * P + c8), Qp + (long)r * DKK + c8);
    }
    loadKV(0, 0);
    cp_commit();

    float acc_o[8][4] = {};

    for (int ch = 0; ch < 16; ch++) {
        if (ch + 1 < 16) { loadKV(ch + 1, (ch + 1) & 1); cp_commit(); cp_wait1(); }
        else             { cp_wait0(); }
        __syncthreads();
        bf* st = sm + TILE + (size_t)(ch & 1) * STG;
        const bf* sk = st;
        const bf* sv = st + TILE;
        const float* sml = (const float*)(st + 2 * TILE);

        // ---- S = Q @ K^T (raw) ----
        float acc[16][4] = {};
        #pragma unroll
        for (int kk = 0; kk < 64; kk += 16) {
            uint32_t a[4];
            {
                int row = m0 + (lane & 15);
                int col = kk + (lane >> 4) * 8;
                ldsm4(a[0], a[1], a[2], a[3], smaddr(sq + row * P + col));
            }
            #pragma unroll
            for (int g = 0; g < 8; g++) {
                int rown = g * 16 + (lane & 7) + ((lane >> 4) & 1) * 8;
                int col = kk + ((lane >> 3) & 1) * 8;
                uint32_t b0, b1, b2, b3;
                ldsm4(b0, b1, b2, b3, smaddr(sk + rown * P + col));
                mma16816(acc[2*g],   a, b0, b1);
                mma16816(acc[2*g+1], a, b2, b3);
            }
        }

        // ---- P = exp(0.125*S - m)*invl; O += P @ V ----
        #pragma unroll
        for (int j = 0; j < 8; j++) {
            int cL = j * 16 + (lane & 3) * 2;
            int cH = cL + 8;
            float mL0 = sml[cL],       mL1 = sml[cL + 1];
            float mH0 = sml[cH],       mH1 = sml[cH + 1];
            float iL0 = sml[128 + cL], iL1 = sml[128 + cL + 1];
            float iH0 = sml[128 + cH], iH1 = sml[128 + cH + 1];

            float p00 = __expf(acc[2*j][0]   * 0.125f - mL0) * iL0;
            float p01 = __expf(acc[2*j][1]   * 0.125f - mL1) * iL1;
            float p10 = __expf(acc[2*j][2]   * 0.125f - mL0) * iL0;
            float p11 = __expf(acc[2*j][3]   * 0.125f - mL1) * iL1;
            float q00 = __expf(acc[2*j+1][0] * 0.125f - mH0) * iH0;
            float q01 = __expf(acc[2*j+1][1] * 0.125f - mH1) * iH1;
            float q10 = __expf(acc[2*j+1][2] * 0.125f - mH0) * iH0;
            float q11 = __expf(acc[2*j+1][3] * 0.125f - mH1) * iH1;

            uint32_t pa[4];
            pa[0] = pack2(__float2bfloat16(p00), __float2bfloat16(p01));
            pa[1] = pack2(__float2bfloat16(p10), __float2bfloat16(p11));
            pa[2] = pack2(__float2bfloat16(q00), __float2bfloat16(q01));
            pa[3] = pack2(__float2bfloat16(q10), __float2bfloat16(q11));

            #pragma unroll
            for (int g2 = 0; g2 < 4; g2++) {
                int rowk = j * 16 + (lane & 7) + ((lane >> 3) & 1) * 8;
                int coln = g2 * 16 + (lane >> 4) * 8;
                uint32_t b0, b1, b2, b3;
                ldsm4t(b0, b1, b2, b3, smaddr(sv + rowk * P + coln));
                mma16816(acc_o[2*g2],   pa, b0, b1);
                mma16816(acc_o[2*g2+1], pa, b2, b3);
            }
        }
        __syncthreads();
    }

    // ---- epilogue: write (B,T,H*DV) bf16 ----
    #pragma unroll
    for (int nf = 0; nf < 8; nf++) {
        long r0 = (long)b * TT + q0b + m0 + (lane >> 2);
        long r1 = r0 + 8;
        long c = (long)h * 64 + nf * 8 + (lane & 3) * 2;
        *(uint32_t*)&oc[r0 * DD + c] =
            pack2(__float2bfloat16(acc_o[nf][0]), __float2bfloat16(acc_o[nf][1]));
        *(uint32_t*)&oc[r1 * DD + c] =
            pack2(__float2bfloat16(acc_o[nf][2]), __float2bfloat16(acc_o[nf][3]));
    }
}

// ---------------- conversions ----------------------------------------------
__global__ void cvt_kernel(const float4* __restrict__ in, uint2* __restrict__ out, long n4)
{
    long i = (long)blockIdx.x * blockDim.x + threadIdx.x;
    if (i >= n4) return;
    float4 v = in[i];
    uint2 o;
    o.x = pack2(__float2bfloat16(v.x), __float2bfloat16(v.y));
    o.y = pack2(__float2bfloat16(v.z), __float2bfloat16(v.w));
    out[i] = o;
}

__global__ void split_kernel(const float4* __restrict__ in, uint2* __restrict__ hi,
                             uint2* __restrict__ lo, long n4)
{
    long i = (long)blockIdx.x * blockDim.x + threadIdx.x;
    if (i >= n4) return;
    float4 v = in[i];
    bf h0, l0, h1, l1, h2, l2, h3, l3;
    split1(v.x, h0, l0); split1(v.y, h1, l1);
    split1(v.z, h2, l2); split1(v.w, h3, l3);
    uint2 o;
    o.x = pack2(h0, h1); o.y = pack2(h2, h3);
    hi[i] = o;
    o.x = pack2(l0, l1); o.y = pack2(l2, l3);
    lo[i] = o;
}

// --------- out = meanstd_norm(a + b); optional bf16 hi/lo output -----------
template <bool WSPLIT>
__global__ void add_norm_kernel(const float* __restrict__ a, const float* __restrict__ b,
                                float* __restrict__ out, bf* __restrict__ oh,
                                bf* __restrict__ ol)
{
    const int D = DD;
    long r = blockIdx.x;
    const float* pa = a + r * D;
    const float* pb = b + r * D;
    int tid = threadIdx.x;

    float y[4];
    float sum = 0.f;
    #pragma unroll
    for (int i = 0; i < 4; i++) {
        y[i] = pa[tid + i * 256] + pb[tid + i * 256];
        sum += y[i];
    }

    __shared__ float red[8];
    #pragma unroll
    for (int o = 16; o > 0; o >>= 1) sum += __shfl_xor_sync(~0u, sum, o);
    if ((tid & 31) == 0) red[tid >> 5] = sum;
    __syncthreads();
    if (tid < 32) {
        float v = (tid < 8) ? red[tid] : 0.f;
        #pragma unroll
        for (int o = 4; o > 0; o >>= 1) v += __shfl_xor_sync(~0u, v, o);
        if (tid == 0) red[0] = v;
    }
    __syncthreads();
    float mean = red[0] / D;
    __syncthreads();

    float vs = 0.f;
    #pragma unroll
    for (int i = 0; i < 4; i++) {
        float d = y[i] - mean;
        vs += d * d;
    }
    #pragma unroll
    for (int o = 16; o > 0; o >>= 1) vs += __shfl_xor_sync(~0u, vs, o);
    if ((tid & 31) == 0) red[tid >> 5] = vs;
    __syncthreads();
    if (tid < 32) {
        float v = (tid < 8) ? red[tid] : 0.f;
        #pragma unroll
        for (int o = 4; o > 0; o >>= 1) v += __shfl_xor_sync(~0u, v, o);
        if (tid == 0) red[0] = v;
    }
    __syncthreads();
    float inv = rsqrtf(red[0] / (float)(D - 1));

    #pragma unroll
    for (int i = 0; i < 4; i++) {
        float v = (y[i] - mean) * inv;
        long idx = r * D + tid + i * 256;
        out[idx] = v;
        if constexpr (WSPLIT) {
            bf h, l;
            split1(v, h, l);
            oh[idx] = h;
            ol[idx] = l;
        }
    }
}

// ---------------------------------------------------------------------------
static inline void* sym(const void* s) {
    void* p = nullptr;
    cudaGetSymbolAddress(&p, s);
    return p;
}

extern "C" void kernel_launch(void* const* d_in, const int* in_sizes, int n_in,
                              void* d_out, int out_size)
{
    const float* x  = (const float*)d_in[0];
    const float* Wq = (const float*)d_in[1];
    const float* Wk = (const float*)d_in[2];
    const float* Wv = (const float*)d_in[3];
    const float* Wo = (const float*)d_in[4];
    const float* W1 = (const float*)d_in[5];
    const float* b1 = (const float*)d_in[6];
    const float* W2 = (const float*)d_in[7];
    const float* b2 = (const float*)d_in[8];
    float* out = (float*)d_out;

    float* tp = (float*)sym(g_tmp);
    float* o1 = (float*)sym(g_out1);
    float* gm = (float*)sym(g_m);
    float* gil = (float*)sym(g_il);
    bf *xb = (bf*)sym(g_xb);
    bf *wq = (bf*)sym(g_wq), *wk = (bf*)sym(g_wk), *wv = (bf*)sym(g_wv), *wo = (bf*)sym(g_wo);
    bf *w1h = (bf*)sym(g_w1h), *w1l = (bf*)sym(g_w1l);
    bf *w2h = (bf*)sym(g_w2h), *w2l = (bf*)sym(g_w2l);
    bf *q = (bf*)sym(g_q), *k = (bf*)sym(g_k), *v = (bf*)sym(g_v);
    bf *oc = (bf*)sym(g_oc);
    bf *o1h = (bf*)sym(g_o1h), *o1l = (bf*)sym(g_o1l);
    bf *fhh = (bf*)sym(g_fhh), *fhl = (bf*)sym(g_fhl);

    const long TD  = (long)TT * DD;
    const long HD  = (long)DD * DKK;
    const long HT  = (long)TT * DKK;
    const long BHT = (long)HH * HT;

    constexpr int SM_N128 = (2 * 128 * 40 + 2 * 32 * 136) * 2 * 2;   // 75776
    constexpr int SM_B64  = (128 * 40 + 32 * 72) * 2 * 2;            // 29696
    constexpr int SM_B128 = (128 * 40 + 32 * 136) * 2 * 2;           // 37888
    constexpr int SM_AT1  = 3 * (128 * 72) * 2;                      // 55296
    constexpr int SM_AT2  = (128 * 72 + 2 * (2 * 128 * 72 + 512)) * 2;  // 94208
    cudaFuncSetAttribute(mgemm<128, false, true, true, false, true>,
                         cudaFuncAttributeMaxDynamicSharedMemorySize, SM_N128);
    cudaFuncSetAttribute(mgemm<128, false, true, false, true, false>,
                         cudaFuncAttributeMaxDynamicSharedMemorySize, SM_N128);
    cudaFuncSetAttribute(attn_stats_kernel,
                         cudaFuncAttributeMaxDynamicSharedMemorySize, SM_AT1);
    cudaFuncSetAttribute(attn_out_kernel,
                         cudaFuncAttributeMaxDynamicSharedMemorySize, SM_AT2);

    // 0) conversions: bf16 for attention branch, hi/lo split for FFN weights
    auto cvt = [&](const float* in, bf* o, long n) {
        long n4 = n / 4;
        cvt_kernel<<<(unsigned)((n4 + 255) / 256), 256>>>(
            (const float4*)in, (uint2*)o, n4);
    };
    auto split = [&](const float* in, bf* hi, bf* lo, long n) {
        long n4 = n / 4;
        split_kernel<<<(unsigned)((n4 + 255) / 256), 256>>>(
            (const float4*)in, (uint2*)hi, (uint2*)lo, n4);
    };
    cvt(x,  xb, (long)BB * TT * DD);
    cvt(Wq, wq, (long)HH * DD * DKK);
    cvt(Wk, wk, (long)HH * DD * DKK);
    cvt(Wv, wv, (long)HH * DD * DKK);
    cvt(Wo, wo, (long)DD * DD);
    split(W1, w1h, w1l, (long)DD * FFF);
    split(W2, w2h, w2l, (long)FFF * DD);

    // 1) Q,K,V projections (plain bf16)
    dim3 gproj(1, TT / 128, BB * HH);
    bgemm<64, false><<<gproj, 256, SM_B64>>>(xb, wq, nullptr, q,
        DD, DD, DKK, DKK, TD, 0, 0, HD, BHT, HT, HH);
    bgemm<64, false><<<gproj, 256, SM_B64>>>(xb, wk, nullptr, k,
        DD, DD, DKK, DKK, TD, 0, 0, HD, BHT, HT, HH);
    bgemm<64, false><<<gproj, 256, SM_B64>>>(xb, wv, nullptr, v,
        DD, DD, DKK, DKK, TD, 0, 0, HD, BHT, HT, HH);

    // 2) fused attention (no T*T materialization, plain bf16 MMA)
    dim3 gat(TT / 128, BB * HH);
    attn_stats_kernel<<<gat, 256, SM_AT1>>>(q, k, gm, gil);
    attn_out_kernel<<<gat, 256, SM_AT2>>>(q, k, v, gm, gil, oc);

    // 3) tmp = ocat @ Wo (plain bf16)
    dim3 gwo(DD / 128, (BB * TT) / 128, 1);
    bgemm<128, true><<<gwo, 256, SM_B128>>>(oc, wo, tp, nullptr,
        DD, DD, DD, DD, 0, 0, 0, 0, 0, 0, 1);

    // 4) out1 = norm(tmp + x), plus hi/lo split for FFN
    add_norm_kernel<true><<<BB * TT, 256>>>(tp, x, o1, o1h, o1l);

    // 5) ffh = relu(out1 @ W1 + b1) (split, 3-MMA)
    dim3 gf1(FFF / 128, (BB * TT) / 128, 1);
    mgemm<128, false, true, true, false, true><<<gf1, 256, SM_N128>>>(
        o1h, o1l, w1h, w1l, nullptr, fhh, fhl, b1,
        DD, DD, FFF, FFF, 1.f, 0, 0, 0, 0, 0, 0, 1);

    // 6) tmp = ffh @ W2 + b2 (split, 3-MMA)
    dim3 gf2(DD / 128, (BB * TT) / 128, 1);
    mgemm<128, false, true, false, true, false><<<gf2, 256, SM_N128>>>(
        fhh, fhl, w2h, w2l, tp, nullptr, nullptr, b2,
        FFF, FFF, DD, DD, 1.f, 0, 0, 0, 0, 0, 0, 1);

    // 7) out = norm(tmp + out1)
    add_norm_kernel<false><<<BB * TT, 256>>>(tp, o1, out, nullptr, nullptr);
}

// round 8
// speedup vs baseline: 6.0736x; 1.0937x over previous
#include <cuda_runtime.h>
#include <cuda_bf16.h>
#include <cstdint>

#define BB 2
#define TT 2048
#define DD 1024
#define HH 16
#define DKK 64
#define FFF 4096

using bf = __nv_bfloat16;

// ---------------- scratch (static device memory; no allocs) ----------------
__device__ __align__(256) float g_tmp[(size_t)BB * TT * DD];
__device__ __align__(256) float g_out1[(size_t)BB * TT * DD];
__device__ __align__(256) float g_m[(size_t)BB * HH * TT];
__device__ __align__(256) float g_il[(size_t)BB * HH * TT];

__device__ __align__(256) bf g_xb[(size_t)BB * TT * DD];
__device__ __align__(256) bf g_wq[(size_t)HH * DD * DKK];
__device__ __align__(256) bf g_wk[(size_t)HH * DD * DKK];
__device__ __align__(256) bf g_wv[(size_t)HH * DD * DKK];
__device__ __align__(256) bf g_wo[(size_t)DD * DD];
__device__ __align__(256) bf g_w1h[(size_t)DD * FFF];
__device__ __align__(256) bf g_w1l[(size_t)DD * FFF];
__device__ __align__(256) bf g_w2h[(size_t)FFF * DD];
__device__ __align__(256) bf g_w2l[(size_t)FFF * DD];
__device__ __align__(256) bf g_q[(size_t)BB * HH * TT * DKK];
__device__ __align__(256) bf g_k[(size_t)BB * HH * TT * DKK];
__device__ __align__(256) bf g_v[(size_t)BB * HH * TT * DKK];
__device__ __align__(256) bf g_oc[(size_t)BB * TT * DD];
__device__ __align__(256) bf g_o1h[(size_t)BB * TT * DD];
__device__ __align__(256) bf g_o1l[(size_t)BB * TT * DD];
__device__ __align__(256) bf g_fhh[(size_t)BB * TT * FFF];
__device__ __align__(256) bf g_fhl[(size_t)BB * TT * FFF];

// ---------------- small helpers -------------------------------------------
__device__ __forceinline__ uint32_t smaddr(const void* p) {
    return (uint32_t)__cvta_generic_to_shared(p);
}
__device__ __forceinline__ void cpa16(uint32_t s, const void* g) {
    asm volatile("cp.async.cg.shared.global [%0], [%1], 16;\n" :: "r"(s), "l"(g));
}
__device__ __forceinline__ void cp_commit() {
    asm volatile("cp.async.commit_group;\n" ::: "memory");
}
__device__ __forceinline__ void cp_wait1() {
    asm volatile("cp.async.wait_group 1;\n" ::: "memory");
}
__device__ __forceinline__ void cp_wait0() {
    asm volatile("cp.async.wait_group 0;\n" ::: "memory");
}
__device__ __forceinline__ void ldsm4(uint32_t& r0, uint32_t& r1, uint32_t& r2, uint32_t& r3, uint32_t a) {
    asm volatile("ldmatrix.sync.aligned.m8n8.x4.shared.b16 {%0,%1,%2,%3}, [%4];\n"
                 : "=r"(r0), "=r"(r1), "=r"(r2), "=r"(r3) : "r"(a));
}
__device__ __forceinline__ void ldsm4t(uint32_t& r0, uint32_t& r1, uint32_t& r2, uint32_t& r3, uint32_t a) {
    asm volatile("ldmatrix.sync.aligned.m8n8.x4.trans.shared.b16 {%0,%1,%2,%3}, [%4];\n"
                 : "=r"(r0), "=r"(r1), "=r"(r2), "=r"(r3) : "r"(a));
}
__device__ __forceinline__ void mma16816(float* d, const uint32_t* a, uint32_t b0, uint32_t b1) {
    asm volatile(
        "mma.sync.aligned.m16n8k16.row.col.f32.bf16.bf16.f32 "
        "{%0,%1,%2,%3}, {%4,%5,%6,%7}, {%8,%9}, {%0,%1,%2,%3};\n"
        : "+f"(d[0]), "+f"(d[1]), "+f"(d[2]), "+f"(d[3])
        : "r"(a[0]), "r"(a[1]), "r"(a[2]), "r"(a[3]), "r"(b0), "r"(b1));
}
__device__ __forceinline__ void split1(float v, bf& h, bf& l) {
    h = __float2bfloat16(v);
    l = __float2bfloat16(v - __bfloat162float(h));
}
__device__ __forceinline__ uint32_t pack2(bf a, bf b) {
    __nv_bfloat162 p; p.x = a; p.y = b;
    return *(uint32_t*)&p;
}

// ---------------- bf16-split tensor-core GEMM (FFN path) -------------------
// 2 CTAs/SM: register-lean inner loop (B frags resident, A frags streamed).
template <int BN, bool TRANSB, bool BIAS, bool RELU, bool OF32, bool OSPLIT>
__global__ __launch_bounds__(256, 2)
void mgemm(const bf* __restrict__ Ah, const bf* __restrict__ Al,
           const bf* __restrict__ Bh, const bf* __restrict__ Bl,
           float* __restrict__ C, bf* __restrict__ Ch, bf* __restrict__ Cl,
           const float* __restrict__ bias,
           int K, int lda, int ldb, int ldc, float alpha,
           long soA, long siA, long soB, long siB, long soC, long siC, int inner)
{
    constexpr int BM = 128, BK = 32, AP = 40;
    constexpr int BP = TRANSB ? 40 : (BN + 8);
    constexpr int AE = BM * AP;
    constexpr int BE = TRANSB ? (BN * AP) : (BK * BP);
    constexpr int STG = 2 * AE + 2 * BE;
    extern __shared__ bf sm[];

    int z = blockIdx.z;
    int zo = z / inner, zi = z - zo * inner;
    long aoff = zo * soA + zi * siA;
    long boff = zo * soB + zi * siB;
    long coff = zo * soC + zi * siC;
    Ah += aoff; Al += aoff;
    Bh += boff; Bl += boff;

    int tid = threadIdx.x, lane = tid & 31, wid = tid >> 5;
    constexpr int MF = (BN == 128) ? 4 : 2;
    constexpr int NF = 4;
    int wm = (BN == 128) ? (wid >> 2) : (wid >> 1);
    int wn = (BN == 128) ? (wid & 3) : (wid & 1);
    int m0 = wm * MF * 16, n0 = wn * 32;

    long bm = (long)blockIdx.y * BM, bn = (long)blockIdx.x * BN;

    float acc[MF][NF][4] = {};

    auto copyStage = [&](int kt, int s) {
        int k0 = kt * BK;
        bf* sa_h = sm + (size_t)s * STG;
        bf* sa_l = sa_h + AE;
        bf* sb_h = sa_l + AE;
        bf* sb_l = sb_h + BE;
        #pragma unroll
        for (int i = 0; i < 2; i++) {
            int c = tid + i * 256;
            int r = c >> 2, cc = (c & 3) * 8;
            long go = (bm + r) * (long)lda + k0 + cc;
            cpa16(smaddr(sa_h + r * AP + cc), Ah + go);
            cpa16(smaddr(sa_l + r * AP + cc), Al + go);
        }
        if constexpr (TRANSB) {
            #pragma unroll
            for (int i = 0; i < BN / 64; i++) {
                int c = tid + i * 256;
                int r = c >> 2, cc = (c & 3) * 8;
                long go = (bn + r) * (long)ldb + k0 + cc;
                cpa16(smaddr(sb_h + r * AP + cc), Bh + go);
                cpa16(smaddr(sb_l + r * AP + cc), Bl + go);
            }
        } else {
            constexpr int CPR = BN / 8;
            #pragma unroll
            for (int i = 0; i < (32 * CPR) / 256; i++) {
                int c = tid + i * 256;
                int r = c / CPR, cc = (c % CPR) * 8;
                long go = (long)(k0 + r) * ldb + bn + cc;
                cpa16(smaddr(sb_h + r * BP + cc), Bh + go);
                cpa16(smaddr(sb_l + r * BP + cc), Bl + go);
            }
        }
        cp_commit();
    };

    auto compute = [&](int s) {
        const bf* sa_h = sm + (size_t)s * STG;
        const bf* sa_l = sa_h + AE;
        const bf* sb_h = sa_l + AE;
        const bf* sb_l = sb_h + BE;
        #pragma unroll
        for (int kk = 0; kk < BK; kk += 16) {
            // ---- B fragments resident for this kk ----
            uint32_t bh2[NF][2], bl2[NF][2];
            #pragma unroll
            for (int g = 0; g < 2; g++) {
                if constexpr (TRANSB) {
                    int rown = n0 + g * 16 + (lane & 7) + ((lane >> 4) & 1) * 8;
                    int col = kk + ((lane >> 3) & 1) * 8;
                    ldsm4(bh2[2*g][0], bh2[2*g][1], bh2[2*g+1][0], bh2[2*g+1][1],
                          smaddr(sb_h + rown * AP + col));
                    ldsm4(bl2[2*g][0], bl2[2*g][1], bl2[2*g+1][0], bl2[2*g+1][1],
                          smaddr(sb_l + rown * AP + col));
                } else {
                    int rowk = kk + (lane & 7) + ((lane >> 3) & 1) * 8;
                    int coln = n0 + g * 16 + (lane >> 4) * 8;
                    ldsm4t(bh2[2*g][0], bh2[2*g][1], bh2[2*g+1][0], bh2[2*g+1][1],
                           smaddr(sb_h + rowk * BP + coln));
                    ldsm4t(bl2[2*g][0], bl2[2*g][1], bl2[2*g+1][0], bl2[2*g+1][1],
                           smaddr(sb_l + rowk * BP + coln));
                }
            }
            // ---- stream A fragments per mf ----
            #pragma unroll
            for (int mf = 0; mf < MF; mf++) {
                uint32_t ah[4], al[4];
                int row = m0 + mf * 16 + (lane & 15);
                int col = kk + (lane >> 4) * 8;
                ldsm4(ah[0], ah[1], ah[2], ah[3], smaddr(sa_h + row * AP + col));
                ldsm4(al[0], al[1], al[2], al[3], smaddr(sa_l + row * AP + col));
                #pragma unroll
                for (int nf = 0; nf < NF; nf++) {
                    mma16816(acc[mf][nf], ah, bh2[nf][0], bh2[nf][1]);
                    mma16816(acc[mf][nf], ah, bl2[nf][0], bl2[nf][1]);
                    mma16816(acc[mf][nf], al, bh2[nf][0], bh2[nf][1]);
                }
            }
        }
    };

    int nk = K / BK;
    copyStage(0, 0);
    for (int kt = 0; kt < nk; kt++) {
        if (kt + 1 < nk) { copyStage(kt + 1, (kt + 1) & 1); cp_wait1(); }
        else             { cp_wait0(); }
        __syncthreads();
        compute(kt & 1);
        __syncthreads();
    }

    #pragma unroll
    for (int mf = 0; mf < MF; mf++) {
        #pragma unroll
        for (int nf = 0; nf < NF; nf++) {
            long r0 = bm + m0 + mf * 16 + (lane >> 2);
            long r1 = r0 + 8;
            long c  = bn + n0 + nf * 8 + (lane & 3) * 2;
            float v00 = acc[mf][nf][0] * alpha;
            float v01 = acc[mf][nf][1] * alpha;
            float v10 = acc[mf][nf][2] * alpha;
            float v11 = acc[mf][nf][3] * alpha;
            if constexpr (BIAS) {
                float b0v = bias[c], b1v = bias[c + 1];
                v00 += b0v; v01 += b1v; v10 += b0v; v11 += b1v;
            }
            if constexpr (RELU) {
                v00 = fmaxf(v00, 0.f); v01 = fmaxf(v01, 0.f);
                v10 = fmaxf(v10, 0.f); v11 = fmaxf(v11, 0.f);
            }
            if constexpr (OF32) {
                float2 p0 = {v00, v01}, p1 = {v10, v11};
                *(float2*)&C[coff + r0 * ldc + c] = p0;
                *(float2*)&C[coff + r1 * ldc + c] = p1;
            }
            if constexpr (OSPLIT) {
                bf h0, l0, h1, l1;
                split1(v00, h0, l0); split1(v01, h1, l1);
                *(uint32_t*)&Ch[coff + r0 * ldc + c] = pack2(h0, h1);
                *(uint32_t*)&Cl[coff + r0 * ldc + c] = pack2(l0, l1);
                split1(v10, h0, l0); split1(v11, h1, l1);
                *(uint32_t*)&Ch[coff + r1 * ldc + c] = pack2(h0, h1);
                *(uint32_t*)&Cl[coff + r1 * ldc + c] = pack2(l0, l1);
            }
        }
    }
}

// ---------------- plain-bf16 tensor-core GEMM (attention branch) -----------
template <int BN, bool OF32>
__global__ __launch_bounds__(256, 2)
void bgemm(const bf* __restrict__ A, const bf* __restrict__ B,
           float* __restrict__ C, bf* __restrict__ Cb,
           int K, int lda, int ldb, int ldc,
           long soA, long siA, long soB, long siB, long soC, long siC, int inner)
{
    constexpr int BM = 128, BK = 32, AP = 40, BP = BN + 8;
    constexpr int AE = BM * AP, BE = BK * BP, STG = AE + BE;
    extern __shared__ bf sm[];

    int z = blockIdx.z;
    int zo = z / inner, zi = z - zo * inner;
    A += zo * soA + zi * siA;
    B += zo * soB + zi * siB;
    long coff = zo * soC + zi * siC;

    int tid = threadIdx.x, lane = tid & 31, wid = tid >> 5;
    constexpr int MF = (BN == 128) ? 4 : 2;
    constexpr int NF = 4;
    int wm = (BN == 128) ? (wid >> 2) : (wid >> 1);
    int wn = (BN == 128) ? (wid & 3) : (wid & 1);
    int m0 = wm * MF * 16, n0 = wn * 32;

    long bm = (long)blockIdx.y * BM, bn = (long)blockIdx.x * BN;

    float acc[MF][NF][4] = {};

    auto copyStage = [&](int kt, int s) {
        int k0 = kt * BK;
        bf* sa = sm + (size_t)s * STG;
        bf* sb = sa + AE;
        #pragma unroll
        for (int i = 0; i < 2; i++) {
            int c = tid + i * 256;
            int r = c >> 2, cc = (c & 3) * 8;
            cpa16(smaddr(sa + r * AP + cc), A + (bm + r) * (long)lda + k0 + cc);
        }
        constexpr int CPR = BN / 8;
        #pragma unroll
        for (int i = 0; i < (32 * CPR) / 256; i++) {
            int c = tid + i * 256;
            int r = c / CPR, cc = (c % CPR) * 8;
            cpa16(smaddr(sb + r * BP + cc), B + (long)(k0 + r) * ldb + bn + cc);
        }
        cp_commit();
    };

    auto compute = [&](int s) {
        const bf* sa = sm + (size_t)s * STG;
        const bf* sb = sa + AE;
        #pragma unroll
        for (int kk = 0; kk < BK; kk += 16) {
            uint32_t b2[NF][2];
            #pragma unroll
            for (int g = 0; g < 2; g++) {
                int rowk = kk + (lane & 7) + ((lane >> 3) & 1) * 8;
                int coln = n0 + g * 16 + (lane >> 4) * 8;
                ldsm4t(b2[2*g][0], b2[2*g][1], b2[2*g+1][0], b2[2*g+1][1],
                       smaddr(sb + rowk * BP + coln));
            }
            #pragma unroll
            for (int mf = 0; mf < MF; mf++) {
                uint32_t a[4];
                int row = m0 + mf * 16 + (lane & 15);
                int col = kk + (lane >> 4) * 8;
                ldsm4(a[0], a[1], a[2], a[3], smaddr(sa + row * AP + col));
                #pragma unroll
                for (int nf = 0; nf < NF; nf++)
                    mma16816(acc[mf][nf], a, b2[nf][0], b2[nf][1]);
            }
        }
    };

    int nk = K / BK;
    copyStage(0, 0);
    for (int kt = 0; kt < nk; kt++) {
        if (kt + 1 < nk) { copyStage(kt + 1, (kt + 1) & 1); cp_wait1(); }
        else             { cp_wait0(); }
        __syncthreads();
        compute(kt & 1);
        __syncthreads();
    }

    #pragma unroll
    for (int mf = 0; mf < MF; mf++) {
        #pragma unroll
        for (int nf = 0; nf < NF; nf++) {
            long r0 = bm + m0 + mf * 16 + (lane >> 2);
            long r1 = r0 + 8;
            long c  = bn + n0 + nf * 8 + (lane & 3) * 2;
            if constexpr (OF32) {
                float2 p0 = {acc[mf][nf][0], acc[mf][nf][1]};
                float2 p1 = {acc[mf][nf][2], acc[mf][nf][3]};
                *(float2*)&C[coff + r0 * ldc + c] = p0;
                *(float2*)&C[coff + r1 * ldc + c] = p1;
            } else {
                *(uint32_t*)&Cb[coff + r0 * ldc + c] =
                    pack2(__float2bfloat16(acc[mf][nf][0]), __float2bfloat16(acc[mf][nf][1]));
                *(uint32_t*)&Cb[coff + r1 * ldc + c] =
                    pack2(__float2bfloat16(acc[mf][nf][2]), __float2bfloat16(acc[mf][nf][3]));
            }
        }
    }
}

// ---------------- fused attention pass 1: column-softmax stats --------------
__global__ __launch_bounds__(256, 2)
void attn_stats_kernel(const bf* __restrict__ q_, const bf* __restrict__ k_,
                       float* __restrict__ gm, float* __restrict__ gil)
{
    constexpr int P = 72, TILE = 128 * P;
    extern __shared__ bf sm[];
    bf* sk = sm;

    int bh = blockIdx.y;
    int s0 = blockIdx.x * 128;
    long base = (long)bh * TT * DKK;
    const bf* Kp = k_ + base + (long)s0 * DKK;
    const bf* Qp = q_ + base;

    int tid = threadIdx.x, lane = tid & 31, wid = tid >> 5;
    int m0 = wid * 16;

    auto loadQ = [&](int ch, int s) {
        bf* dq = sm + TILE + (size_t)s * TILE;
        long q0 = (long)ch * 128;
        #pragma unroll
        for (int i = 0; i < 4; i++) {
            int c = tid + i * 256;
            int r = c >> 3, c8 = (c & 7) * 8;
            cpa16(smaddr(dq + r * P + c8), Qp + (q0 + r) * DKK + c8);
        }
    };

    #pragma unroll
    for (int i = 0; i < 4; i++) {
        int c = tid + i * 256;
        int r = c >> 3, c8 = (c & 7) * 8;
        cpa16(smaddr(sk + r * P + c8), Kp + (long)r * DKK + c8);
    }
    loadQ(0, 0);
    cp_commit();

    float mrow0 = -1e30f, mrow1 = -1e30f;
    float lrow0 = 0.f, lrow1 = 0.f;

    for (int ch = 0; ch < 16; ch++) {
        if (ch + 1 < 16) { loadQ(ch + 1, (ch + 1) & 1); cp_commit(); cp_wait1(); }
        else             { cp_wait0(); }
        __syncthreads();
        const bf* sq = sm + TILE + (size_t)(ch & 1) * TILE;

        float acc[16][4] = {};
        #pragma unroll
        for (int kk = 0; kk < 64; kk += 16) {
            uint32_t a[4];
            {
                int row = m0 + (lane & 15);
                int col = kk + (lane >> 4) * 8;
                ldsm4(a[0], a[1], a[2], a[3], smaddr(sk + row * P + col));
            }
            #pragma unroll
            for (int g = 0; g < 8; g++) {
                int rown = g * 16 + (lane & 7) + ((lane >> 4) & 1) * 8;
                int col = kk + ((lane >> 3) & 1) * 8;
                uint32_t b0, b1, b2, b3;
                ldsm4(b0, b1, b2, b3, smaddr(sq + rown * P + col));
                mma16816(acc[2*g],   a, b0, b1);
                mma16816(acc[2*g+1], a, b2, b3);
            }
        }
        __syncthreads();

        float cm0 = -1e30f, cm1 = -1e30f;
        #pragma unroll
        for (int nf = 0; nf < 16; nf++) {
            cm0 = fmaxf(cm0, fmaxf(acc[nf][0], acc[nf][1]));
            cm1 = fmaxf(cm1, fmaxf(acc[nf][2], acc[nf][3]));
        }
        cm0 *= 0.125f; cm1 *= 0.125f;
        cm0 = fmaxf(cm0, __shfl_xor_sync(~0u, cm0, 1));
        cm0 = fmaxf(cm0, __shfl_xor_sync(~0u, cm0, 2));
        cm1 = fmaxf(cm1, __shfl_xor_sync(~0u, cm1, 1));
        cm1 = fmaxf(cm1, __shfl_xor_sync(~0u, cm1, 2));
        float mn0 = fmaxf(mrow0, cm0), mn1 = fmaxf(mrow1, cm1);
        float sv0 = 0.f, sv1 = 0.f;
        #pragma unroll
        for (int nf = 0; nf < 16; nf++) {
            sv0 += __expf(acc[nf][0] * 0.125f - mn0) + __expf(acc[nf][1] * 0.125f - mn0);
            sv1 += __expf(acc[nf][2] * 0.125f - mn1) + __expf(acc[nf][3] * 0.125f - mn1);
        }
        sv0 += __shfl_xor_sync(~0u, sv0, 1); sv0 += __shfl_xor_sync(~0u, sv0, 2);
        sv1 += __shfl_xor_sync(~0u, sv1, 1); sv1 += __shfl_xor_sync(~0u, sv1, 2);
        lrow0 = lrow0 * __expf(mrow0 - mn0) + sv0;
        lrow1 = lrow1 * __expf(mrow1 - mn1) + sv1;
        mrow0 = mn0; mrow1 = mn1;
    }

    if ((lane & 3) == 0) {
        int r = lane >> 2;
        long o = (long)bh * TT + s0 + m0;
        gm[o + r]      = mrow0;
        gm[o + r + 8]  = mrow1;
        gil[o + r]     = 1.f / lrow0;
        gil[o + r + 8] = 1.f / lrow1;
    }
}

// ---------------- fused attention pass 2: output ----------------------------
// S computed in two 64-column halves to cut register peak -> 2 CTAs/SM.
__global__ __launch_bounds__(256, 2)
void attn_out_kernel(const bf* __restrict__ q_, const bf* __restrict__ k_,
                     const bf* __restrict__ v_,
                     const float* __restrict__ gm, const float* __restrict__ gil,
                     bf* __restrict__ oc)
{
    constexpr int P = 72, TILE = 128 * P;
    constexpr int STG = 2 * TILE + 512;   // K + V + 1KB stats (bf elems)
    extern __shared__ bf sm[];
    bf* sq = sm;

    int bh = blockIdx.y;
    int q0b = blockIdx.x * 128;
    int b = bh >> 4, h = bh & 15;
    long base = (long)bh * TT * DKK;
    const bf* Qp = q_ + base + (long)q0b * DKK;
    const bf* Kp = k_ + base;
    const bf* Vp = v_ + base;
    const float* Gm = gm + (long)bh * TT;
    const float* Gil = gil + (long)bh * TT;

    int tid = threadIdx.x, lane = tid & 31, wid = tid >> 5;
    int m0 = wid * 16;

    auto loadKV = [&](int ch, int s) {
        bf* st = sm + TILE + (size_t)s * STG;
        bf* dk = st;
        bf* dv = st + TILE;
        float* dml = (float*)(st + 2 * TILE);
        long r0 = (long)ch * 128;
        #pragma unroll
        for (int i = 0; i < 4; i++) {
            int c = tid + i * 256;
            int r = c >> 3, c8 = (c & 7) * 8;
            long go = (r0 + r) * DKK + c8;
            cpa16(smaddr(dk + r * P + c8), Kp + go);
            cpa16(smaddr(dv + r * P + c8), Vp + go);
        }
        if (tid < 32)      cpa16(smaddr(dml + tid * 4),          Gm  + r0 + tid * 4);
        else if (tid < 64) cpa16(smaddr(dml + 128 + (tid-32)*4), Gil + r0 + (tid - 32) * 4);
    };

    #pragma unroll
    for (int i = 0; i < 4; i++) {
        int c = tid + i * 256;
        int r = c >> 3, c8 = (c & 7) * 8;
        cpa16(smaddr(sq + r * P + c8), Qp + (long)r * DKK + c8);
    }
    loadKV(0, 0);
    cp_commit();

    float acc_o[8][4] = {};

    for (int ch = 0; ch < 16; ch++) {
        if (ch + 1 < 16) { loadKV(ch + 1, (ch + 1) & 1); cp_commit(); cp_wait1(); }
        else             { cp_wait0(); }
        __syncthreads();
        bf* st = sm + TILE + (size_t)(ch & 1) * STG;
        const bf* sk = st;
        const bf* sv = st + TILE;
        const float* sml = (const float*)(st + 2 * TILE);

        #pragma unroll
        for (int half = 0; half < 2; half++) {
            // ---- S half: Q @ K[64*half .. 64*half+63]^T ----
            float acc8[8][4] = {};
            #pragma unroll
            for (int kk = 0; kk < 64; kk += 16) {
                uint32_t a[4];
                {
                    int row = m0 + (lane & 15);
                    int col = kk + (lane >> 4) * 8;
                    ldsm4(a[0], a[1], a[2], a[3], smaddr(sq + row * P + col));
                }
                #pragma unroll
                for (int g = 0; g < 4; g++) {
                    int rown = half * 64 + g * 16 + (lane & 7) + ((lane >> 4) & 1) * 8;
                    int col = kk + ((lane >> 3) & 1) * 8;
                    uint32_t b0, b1, b2, b3;
                    ldsm4(b0, b1, b2, b3, smaddr(sk + rown * P + col));
                    mma16816(acc8[2*g],   a, b0, b1);
                    mma16816(acc8[2*g+1], a, b2, b3);
                }
            }

            // ---- P = exp(0.125*S - m)*invl; O += P @ V (rows of this half) --
            #pragma unroll
            for (int j = 0; j < 4; j++) {
                int cL = half * 64 + j * 16 + (lane & 3) * 2;
                int cH = cL + 8;
                float mL0 = sml[cL],       mL1 = sml[cL + 1];
                float mH0 = sml[cH],       mH1 = sml[cH + 1];
                float iL0 = sml[128 + cL], iL1 = sml[128 + cL + 1];
                float iH0 = sml[128 + cH], iH1 = sml[128 + cH + 1];

                float p00 = __expf(acc8[2*j][0]   * 0.125f - mL0) * iL0;
                float p01 = __expf(acc8[2*j][1]   * 0.125f - mL1) * iL1;
                float p10 = __expf(acc8[2*j][2]   * 0.125f - mL0) * iL0;
                float p11 = __expf(acc8[2*j][3]   * 0.125f - mL1) * iL1;
                float q00 = __expf(acc8[2*j+1][0] * 0.125f - mH0) * iH0;
                float q01 = __expf(acc8[2*j+1][1] * 0.125f - mH1) * iH1;
                float q10 = __expf(acc8[2*j+1][2] * 0.125f - mH0) * iH0;
                float q11 = __expf(acc8[2*j+1][3] * 0.125f - mH1) * iH1;

                uint32_t pa[4];
                pa[0] = pack2(__float2bfloat16(p00), __float2bfloat16(p01));
                pa[1] = pack2(__float2bfloat16(p10), __float2bfloat16(p11));
                pa[2] = pack2(__float2bfloat16(q00), __float2bfloat16(q01));
                pa[3] = pack2(__float2bfloat16(q10), __float2bfloat16(q11));

                #pragma unroll
                for (int g2 = 0; g2 < 4; g2++) {
                    int rowk = half * 64 + j * 16 + (lane & 7) + ((lane >> 3) & 1) * 8;
                    int coln = g2 * 16 + (lane >> 4) * 8;
                    uint32_t b0, b1, b2, b3;
                    ldsm4t(b0, b1, b2, b3, smaddr(sv + rowk * P + coln));
                    mma16816(acc_o[2*g2],   pa, b0, b1);
                    mma16816(acc_o[2*g2+1], pa, b2, b3);
                }
            }
        }
        __syncthreads();
    }

    // ---- epilogue: write (B,T,H*DV) bf16 ----
    #pragma unroll
    for (int nf = 0; nf < 8; nf++) {
        long r0 = (long)b * TT + q0b + m0 + (lane >> 2);
        long r1 = r0 + 8;
        long c = (long)h * 64 + nf * 8 + (lane & 3) * 2;
        *(uint32_t*)&oc[r0 * DD + c] =
            pack2(__float2bfloat16(acc_o[nf][0]), __float2bfloat16(acc_o[nf][1]));
        *(uint32_t*)&oc[r1 * DD + c] =
            pack2(__float2bfloat16(acc_o[nf][2]), __float2bfloat16(acc_o[nf][3]));
    }
}

// ---------------- conversions ----------------------------------------------
__global__ void cvt_kernel(const float4* __restrict__ in, uint2* __restrict__ out, long n4)
{
    long i = (long)blockIdx.x * blockDim.x + threadIdx.x;
    if (i >= n4) return;
    float4 v = in[i];
    uint2 o;
    o.x = pack2(__float2bfloat16(v.x), __float2bfloat16(v.y));
    o.y = pack2(__float2bfloat16(v.z), __float2bfloat16(v.w));
    out[i] = o;
}

__global__ void split_kernel(const float4* __restrict__ in, uint2* __restrict__ hi,
                             uint2* __restrict__ lo, long n4)
{
    long i = (long)blockIdx.x * blockDim.x + threadIdx.x;
    if (i >= n4) return;
    float4 v = in[i];
    bf h0, l0, h1, l1, h2, l2, h3, l3;
    split1(v.x, h0, l0); split1(v.y, h1, l1);
    split1(v.z, h2, l2); split1(v.w, h3, l3);
    uint2 o;
    o.x = pack2(h0, h1); o.y = pack2(h2, h3);
    hi[i] = o;
    o.x = pack2(l0, l1); o.y = pack2(l2, l3);
    lo[i] = o;
}

// --------- out = meanstd_norm(a + b); optional bf16 hi/lo output -----------
template <bool WSPLIT>
__global__ void add_norm_kernel(const float* __restrict__ a, const float* __restrict__ b,
                                float* __restrict__ out, bf* __restrict__ oh,
                                bf* __restrict__ ol)
{
    const int D = DD;
    long r = blockIdx.x;
    const float* pa = a + r * D;
    const float* pb = b + r * D;
    int tid = threadIdx.x;

    float y[4];
    float sum = 0.f;
    #pragma unroll
    for (int i = 0; i < 4; i++) {
        y[i] = pa[tid + i * 256] + pb[tid + i * 256];
        sum += y[i];
    }

    __shared__ float red[8];
    #pragma unroll
    for (int o = 16; o > 0; o >>= 1) sum += __shfl_xor_sync(~0u, sum, o);
    if ((tid & 31) == 0) red[tid >> 5] = sum;
    __syncthreads();
    if (tid < 32) {
        float v = (tid < 8) ? red[tid] : 0.f;
        #pragma unroll
        for (int o = 4; o > 0; o >>= 1) v += __shfl_xor_sync(~0u, v, o);
        if (tid == 0) red[0] = v;
    }
    __syncthreads();
    float mean = red[0] / D;
    __syncthreads();

    float vs = 0.f;
    #pragma unroll
    for (int i = 0; i < 4; i++) {
        float d = y[i] - mean;
        vs += d * d;
    }
    #pragma unroll
    for (int o = 16; o > 0; o >>= 1) vs += __shfl_xor_sync(~0u, vs, o);
    if ((tid & 31) == 0) red[tid >> 5] = vs;
    __syncthreads();
    if (tid < 32) {
        float v = (tid < 8) ? red[tid] : 0.f;
        #pragma unroll
        for (int o = 4; o > 0; o >>= 1) v += __shfl_xor_sync(~0u, v, o);
        if (tid == 0) red[0] = v;
    }
    __syncthreads();
    float inv = rsqrtf(red[0] / (float)(D - 1));

    #pragma unroll
    for (int i = 0; i < 4; i++) {
        float v = (y[i] - mean) * inv;
        long idx = r * D + tid + i * 256;
        out[idx] = v;
        if constexpr (WSPLIT) {
            bf h, l;
            split1(v, h, l);
            oh[idx] = h;
            ol[idx] = l;
        }
    }
}

// ---------------------------------------------------------------------------
static inline void* sym(const void* s) {
    void* p = nullptr;
    cudaGetSymbolAddress(&p, s);
    return p;
}

extern "C" void kernel_launch(void* const* d_in, const int* in_sizes, int n_in,
                              void* d_out, int out_size)
{
    const float* x  = (const float*)d_in[0];
    const float* Wq = (const float*)d_in[1];
    const float* Wk = (const float*)d_in[2];
    const float* Wv = (const float*)d_in[3];
    const float* Wo = (const float*)d_in[4];
    const float* W1 = (const float*)d_in[5];
    const float* b1 = (const float*)d_in[6];
    const float* W2 = (const float*)d_in[7];
    const float* b2 = (const float*)d_in[8];
    float* out = (float*)d_out;

    float* tp = (float*)sym(g_tmp);
    float* o1 = (float*)sym(g_out1);
    float* gm = (float*)sym(g_m);
    float* gil = (float*)sym(g_il);
    bf *xb = (bf*)sym(g_xb);
    bf *wq = (bf*)sym(g_wq), *wk = (bf*)sym(g_wk), *wv = (bf*)sym(g_wv), *wo = (bf*)sym(g_wo);
    bf *w1h = (bf*)sym(g_w1h), *w1l = (bf*)sym(g_w1l);
    bf *w2h = (bf*)sym(g_w2h), *w2l = (bf*)sym(g_w2l);
    bf *q = (bf*)sym(g_q), *k = (bf*)sym(g_k), *v = (bf*)sym(g_v);
    bf *oc = (bf*)sym(g_oc);
    bf *o1h = (bf*)sym(g_o1h), *o1l = (bf*)sym(g_o1l);
    bf *fhh = (bf*)sym(g_fhh), *fhl = (bf*)sym(g_fhl);

    const long TD  = (long)TT * DD;
    const long HD  = (long)DD * DKK;
    const long HT  = (long)TT * DKK;
    const long BHT = (long)HH * HT;

    constexpr int SM_N128 = (2 * 128 * 40 + 2 * 32 * 136) * 2 * 2;   // 75776
    constexpr int SM_B64  = (128 * 40 + 32 * 72) * 2 * 2;            // 29696
    constexpr int SM_B128 = (128 * 40 + 32 * 136) * 2 * 2;           // 37888
    constexpr int SM_AT1  = 3 * (128 * 72) * 2;                      // 55296
    constexpr int SM_AT2  = (128 * 72 + 2 * (2 * 128 * 72 + 512)) * 2;  // 94208
    cudaFuncSetAttribute(mgemm<128, false, true, true, false, true>,
                         cudaFuncAttributeMaxDynamicSharedMemorySize, SM_N128);
    cudaFuncSetAttribute(mgemm<128, false, true, false, true, false>,
                         cudaFuncAttributeMaxDynamicSharedMemorySize, SM_N128);
    cudaFuncSetAttribute(attn_stats_kernel,
                         cudaFuncAttributeMaxDynamicSharedMemorySize, SM_AT1);
    cudaFuncSetAttribute(attn_out_kernel,
                         cudaFuncAttributeMaxDynamicSharedMemorySize, SM_AT2);

    // 0) conversions
    auto cvt = [&](const float* in, bf* o, long n) {
        long n4 = n / 4;
        cvt_kernel<<<(unsigned)((n4 + 255) / 256), 256>>>(
            (const float4*)in, (uint2*)o, n4);
    };
    auto split = [&](const float* in, bf* hi, bf* lo, long n) {
        long n4 = n / 4;
        split_kernel<<<(unsigned)((n4 + 255) / 256), 256>>>(
            (const float4*)in, (uint2*)hi, (uint2*)lo, n4);
    };
    cvt(x,  xb, (long)BB * TT * DD);
    cvt(Wq, wq, (long)HH * DD * DKK);
    cvt(Wk, wk, (long)HH * DD * DKK);
    cvt(Wv, wv, (long)HH * DD * DKK);
    cvt(Wo, wo, (long)DD * DD);
    split(W1, w1h, w1l, (long)DD * FFF);
    split(W2, w2h, w2l, (long)FFF * DD);

    // 1) Q,K,V projections (plain bf16)
    dim3 gproj(1, TT / 128, BB * HH);
    bgemm<64, false><<<gproj, 256, SM_B64>>>(xb, wq, nullptr, q,
        DD, DD, DKK, DKK, TD, 0, 0, HD, BHT, HT, HH);
    bgemm<64, false><<<gproj, 256, SM_B64>>>(xb, wk, nullptr, k,
        DD, DD, DKK, DKK, TD, 0, 0, HD, BHT, HT, HH);
    bgemm<64, false><<<gproj, 256, SM_B64>>>(xb, wv, nullptr, v,
        DD, DD, DKK, DKK, TD, 0, 0, HD, BHT, HT, HH);

    // 2) fused attention
    dim3 gat(TT / 128, BB * HH);
    attn_stats_kernel<<<gat, 256, SM_AT1>>>(q, k, gm, gil);
    attn_out_kernel<<<gat, 256, SM_AT2>>>(q, k, v, gm, gil, oc);

    // 3) tmp = ocat @ Wo (plain bf16)
    dim3 gwo(DD / 128, (BB * TT) / 128, 1);
    bgemm<128, true><<<gwo, 256, SM_B128>>>(oc, wo, tp, nullptr,
        DD, DD, DD, DD, 0, 0, 0, 0, 0, 0, 1);

    // 4) out1 = norm(tmp + x), plus hi/lo split for FFN
    add_norm_kernel<true><<<BB * TT, 256>>>(tp, x, o1, o1h, o1l);

    // 5) ffh = relu(out1 @ W1 + b1) (split, 3-MMA)
    dim3 gf1(FFF / 128, (BB * TT) / 128, 1);
    mgemm<128, false, true, true, false, true><<<gf1, 256, SM_N128>>>(
        o1h, o1l, w1h, w1l, nullptr, fhh, fhl, b1,
        DD, DD, FFF, FFF, 1.f, 0, 0, 0, 0, 0, 0, 1);

    // 6) tmp = ffh @ W2 + b2 (split, 3-MMA)
    dim3 gf2(DD / 128, (BB * TT) / 128, 1);
    mgemm<128, false, true, false, true, false><<<gf2, 256, SM_N128>>>(
        fhh, fhl, w2h, w2l, tp, nullptr, nullptr, b2,
        FFF, FFF, DD, DD, 1.f, 0, 0, 0, 0, 0, 0, 1);

    // 7) out = norm(tmp + out1)
    add_norm_kernel<false><<<BB * TT, 256>>>(tp, o1, out, nullptr, nullptr);
}

// round 9
// speedup vs baseline: 9.0974x; 1.4979x over previous
#include <cuda_runtime.h>
#include <cuda_bf16.h>
#include <cuda_fp16.h>
#include <cstdint>

#define BB 2
#define TT 2048
#define DD 1024
#define HH 16
#define DKK 64
#define FFF 4096

using bf = __nv_bfloat16;
using hf = __half;

// ---------------- scratch (static device memory; no allocs) ----------------
__device__ __align__(256) float g_tmp[(size_t)BB * TT * DD];
__device__ __align__(256) float g_out1[(size_t)BB * TT * DD];
__device__ __align__(256) float g_m[(size_t)BB * HH * TT];
__device__ __align__(256) float g_il[(size_t)BB * HH * TT];

__device__ __align__(256) bf g_xb[(size_t)BB * TT * DD];
__device__ __align__(256) bf g_wq[(size_t)HH * DD * DKK];
__device__ __align__(256) bf g_wk[(size_t)HH * DD * DKK];
__device__ __align__(256) bf g_wv[(size_t)HH * DD * DKK];
__device__ __align__(256) bf g_wo[(size_t)DD * DD];
__device__ __align__(256) bf g_q[(size_t)BB * HH * TT * DKK];
__device__ __align__(256) bf g_k[(size_t)BB * HH * TT * DKK];
__device__ __align__(256) bf g_v[(size_t)BB * HH * TT * DKK];
__device__ __align__(256) bf g_oc[(size_t)BB * TT * DD];

__device__ __align__(256) hf g_w1f[(size_t)DD * FFF];
__device__ __align__(256) hf g_w2f[(size_t)FFF * DD];
__device__ __align__(256) hf g_o1f[(size_t)BB * TT * DD];
__device__ __align__(256) hf g_fhf[(size_t)BB * TT * FFF];

// ---------------- small helpers -------------------------------------------
__device__ __forceinline__ uint32_t smaddr(const void* p) {
    return (uint32_t)__cvta_generic_to_shared(p);
}
__device__ __forceinline__ void cpa16(uint32_t s, const void* g) {
    asm volatile("cp.async.cg.shared.global [%0], [%1], 16;\n" :: "r"(s), "l"(g));
}
__device__ __forceinline__ void cp_commit() {
    asm volatile("cp.async.commit_group;\n" ::: "memory");
}
__device__ __forceinline__ void cp_wait1() {
    asm volatile("cp.async.wait_group 1;\n" ::: "memory");
}
__device__ __forceinline__ void cp_wait0() {
    asm volatile("cp.async.wait_group 0;\n" ::: "memory");
}
__device__ __forceinline__ void ldsm4(uint32_t& r0, uint32_t& r1, uint32_t& r2, uint32_t& r3, uint32_t a) {
    asm volatile("ldmatrix.sync.aligned.m8n8.x4.shared.b16 {%0,%1,%2,%3}, [%4];\n"
                 : "=r"(r0), "=r"(r1), "=r"(r2), "=r"(r3) : "r"(a));
}
__device__ __forceinline__ void ldsm4t(uint32_t& r0, uint32_t& r1, uint32_t& r2, uint32_t& r3, uint32_t a) {
    asm volatile("ldmatrix.sync.aligned.m8n8.x4.trans.shared.b16 {%0,%1,%2,%3}, [%4];\n"
                 : "=r"(r0), "=r"(r1), "=r"(r2), "=r"(r3) : "r"(a));
}
__device__ __forceinline__ void mma16816(float* d, const uint32_t* a, uint32_t b0, uint32_t b1) {
    asm volatile(
        "mma.sync.aligned.m16n8k16.row.col.f32.bf16.bf16.f32 "
        "{%0,%1,%2,%3}, {%4,%5,%6,%7}, {%8,%9}, {%0,%1,%2,%3};\n"
        : "+f"(d[0]), "+f"(d[1]), "+f"(d[2]), "+f"(d[3])
        : "r"(a[0]), "r"(a[1]), "r"(a[2]), "r"(a[3]), "r"(b0), "r"(b1));
}
__device__ __forceinline__ void mma16816h(float* d, const uint32_t* a, uint32_t b0, uint32_t b1) {
    asm volatile(
        "mma.sync.aligned.m16n8k16.row.col.f32.f16.f16.f32 "
        "{%0,%1,%2,%3}, {%4,%5,%6,%7}, {%8,%9}, {%0,%1,%2,%3};\n"
        : "+f"(d[0]), "+f"(d[1]), "+f"(d[2]), "+f"(d[3])
        : "r"(a[0]), "r"(a[1]), "r"(a[2]), "r"(a[3]), "r"(b0), "r"(b1));
}
__device__ __forceinline__ uint32_t pack2(bf a, bf b) {
    __nv_bfloat162 p; p.x = a; p.y = b;
    return *(uint32_t*)&p;
}
__device__ __forceinline__ uint32_t pack2h(hf a, hf b) {
    __half2 p; p.x = a; p.y = b;
    return *(uint32_t*)&p;
}

// ---------------- plain-bf16 tensor-core GEMM (attention branch) -----------
template <int BN, bool OF32>
__global__ __launch_bounds__(256, 2)
void bgemm(const bf* __restrict__ A, const bf* __restrict__ B,
           float* __restrict__ C, bf* __restrict__ Cb,
           int K, int lda, int ldb, int ldc,
           long soA, long siA, long soB, long siB, long soC, long siC, int inner)
{
    constexpr int BM = 128, BK = 32, AP = 40, BP = BN + 8;
    constexpr int AE = BM * AP, BE = BK * BP, STG = AE + BE;
    extern __shared__ bf sm[];

    int z = blockIdx.z;
    int zo = z / inner, zi = z - zo * inner;
    A += zo * soA + zi * siA;
    B += zo * soB + zi * siB;
    long coff = zo * soC + zi * siC;

    int tid = threadIdx.x, lane = tid & 31, wid = tid >> 5;
    constexpr int MF = (BN == 128) ? 4 : 2;
    constexpr int NF = 4;
    int wm = (BN == 128) ? (wid >> 2) : (wid >> 1);
    int wn = (BN == 128) ? (wid & 3) : (wid & 1);
    int m0 = wm * MF * 16, n0 = wn * 32;

    long bm = (long)blockIdx.y * BM, bn = (long)blockIdx.x * BN;

    float acc[MF][NF][4] = {};

    auto copyStage = [&](int kt, int s) {
        int k0 = kt * BK;
        bf* sa = sm + (size_t)s * STG;
        bf* sb = sa + AE;
        #pragma unroll
        for (int i = 0; i < 2; i++) {
            int c = tid + i * 256;
            int r = c >> 2, cc = (c & 3) * 8;
            cpa16(smaddr(sa + r * AP + cc), A + (bm + r) * (long)lda + k0 + cc);
        }
        constexpr int CPR = BN / 8;
        #pragma unroll
        for (int i = 0; i < (32 * CPR) / 256; i++) {
            int c = tid + i * 256;
            int r = c / CPR, cc = (c % CPR) * 8;
            cpa16(smaddr(sb + r * BP + cc), B + (long)(k0 + r) * ldb + bn + cc);
        }
        cp_commit();
    };

    auto compute = [&](int s) {
        const bf* sa = sm + (size_t)s * STG;
        const bf* sb = sa + AE;
        #pragma unroll
        for (int kk = 0; kk < BK; kk += 16) {
            uint32_t b2[NF][2];
            #pragma unroll
            for (int g = 0; g < 2; g++) {
                int rowk = kk + (lane & 7) + ((lane >> 3) & 1) * 8;
                int coln = n0 + g * 16 + (lane >> 4) * 8;
                ldsm4t(b2[2*g][0], b2[2*g][1], b2[2*g+1][0], b2[2*g+1][1],
                       smaddr(sb + rowk * BP + coln));
            }
            #pragma unroll
            for (int mf = 0; mf < MF; mf++) {
                uint32_t a[4];
                int row = m0 + mf * 16 + (lane & 15);
                int col = kk + (lane >> 4) * 8;
                ldsm4(a[0], a[1], a[2], a[3], smaddr(sa + row * AP + col));
                #pragma unroll
                for (int nf = 0; nf < NF; nf++)
                    mma16816(acc[mf][nf], a, b2[nf][0], b2[nf][1]);
            }
        }
    };

    int nk = K / BK;
    copyStage(0, 0);
    for (int kt = 0; kt < nk; kt++) {
        if (kt + 1 < nk) { copyStage(kt + 1, (kt + 1) & 1); cp_wait1(); }
        else             { cp_wait0(); }
        __syncthreads();
        compute(kt & 1);
        __syncthreads();
    }

    #pragma unroll
    for (int mf = 0; mf < MF; mf++) {
        #pragma unroll
        for (int nf = 0; nf < NF; nf++) {
            long r0 = bm + m0 + mf * 16 + (lane >> 2);
            long r1 = r0 + 8;
            long c  = bn + n0 + nf * 8 + (lane & 3) * 2;
            if constexpr (OF32) {
                float2 p0 = {acc[mf][nf][0], acc[mf][nf][1]};
                float2 p1 = {acc[mf][nf][2], acc[mf][nf][3]};
                *(float2*)&C[coff + r0 * ldc + c] = p0;
                *(float2*)&C[coff + r1 * ldc + c] = p1;
            } else {
                *(uint32_t*)&Cb[coff + r0 * ldc + c] =
                    pack2(__float2bfloat16(acc[mf][nf][0]), __float2bfloat16(acc[mf][nf][1]));
                *(uint32_t*)&Cb[coff + r1 * ldc + c] =
                    pack2(__float2bfloat16(acc[mf][nf][2]), __float2bfloat16(acc[mf][nf][3]));
            }
        }
    }
}

// ---------------- fp16 tensor-core GEMM (FFN path, 1 MMA) ------------------
// C = A*B (+bias)(relu). A:[M,K] fp16 k-contig. B:[K,N] fp16 row-major.
template <bool BIAS, bool RELU, bool OF32>
__global__ __launch_bounds__(256, 2)
void hgemm(const hf* __restrict__ A, const hf* __restrict__ B,
           float* __restrict__ C, hf* __restrict__ Ch,
           const float* __restrict__ bias,
           int K, int lda, int ldb, int ldc)
{
    constexpr int BM = 128, BN = 128, BK = 32, AP = 40, BP = BN + 8;
    constexpr int AE = BM * AP, BE = BK * BP, STG = AE + BE;
    extern __shared__ hf smh[];

    int tid = threadIdx.x, lane = tid & 31, wid = tid >> 5;
    constexpr int MF = 4, NF = 4;
    int wm = wid >> 2, wn = wid & 3;
    int m0 = wm * MF * 16, n0 = wn * 32;

    long bm = (long)blockIdx.y * BM, bn = (long)blockIdx.x * BN;

    float acc[MF][NF][4] = {};

    auto copyStage = [&](int kt, int s) {
        int k0 = kt * BK;
        hf* sa = smh + (size_t)s * STG;
        hf* sb = sa + AE;
        #pragma unroll
        for (int i = 0; i < 2; i++) {
            int c = tid + i * 256;
            int r = c >> 2, cc = (c & 3) * 8;
            cpa16(smaddr(sa + r * AP + cc), A + (bm + r) * (long)lda + k0 + cc);
        }
        #pragma unroll
        for (int i = 0; i < 2; i++) {
            int c = tid + i * 256;
            int r = c >> 4, cc = (c & 15) * 8;
            cpa16(smaddr(sb + r * BP + cc), B + (long)(k0 + r) * ldb + bn + cc);
        }
        cp_commit();
    };

    auto compute = [&](int s) {
        const hf* sa = smh + (size_t)s * STG;
        const hf* sb = sa + AE;
        #pragma unroll
        for (int kk = 0; kk < BK; kk += 16) {
            uint32_t b2[NF][2];
            #pragma unroll
            for (int g = 0; g < 2; g++) {
                int rowk = kk + (lane & 7) + ((lane >> 3) & 1) * 8;
                int coln = n0 + g * 16 + (lane >> 4) * 8;
                ldsm4t(b2[2*g][0], b2[2*g][1], b2[2*g+1][0], b2[2*g+1][1],
                       smaddr(sb + rowk * BP + coln));
            }
            #pragma unroll
            for (int mf = 0; mf < MF; mf++) {
                uint32_t a[4];
                int row = m0 + mf * 16 + (lane & 15);
                int col = kk + (lane >> 4) * 8;
                ldsm4(a[0], a[1], a[2], a[3], smaddr(sa + row * AP + col));
                #pragma unroll
                for (int nf = 0; nf < NF; nf++)
                    mma16816h(acc[mf][nf], a, b2[nf][0], b2[nf][1]);
            }
        }
    };

    int nk = K / BK;
    copyStage(0, 0);
    for (int kt = 0; kt < nk; kt++) {
        if (kt + 1 < nk) { copyStage(kt + 1, (kt + 1) & 1); cp_wait1(); }
        else             { cp_wait0(); }
        __syncthreads();
        compute(kt & 1);
        __syncthreads();
    }

    #pragma unroll
    for (int mf = 0; mf < MF; mf++) {
        #pragma unroll
        for (int nf = 0; nf < NF; nf++) {
            long r0 = bm + m0 + mf * 16 + (lane >> 2);
            long r1 = r0 + 8;
            long c  = bn + n0 + nf * 8 + (lane & 3) * 2;
            float v00 = acc[mf][nf][0];
            float v01 = acc[mf][nf][1];
            float v10 = acc[mf][nf][2];
            float v11 = acc[mf][nf][3];
            if constexpr (BIAS) {
                float b0v = bias[c], b1v = bias[c + 1];
                v00 += b0v; v01 += b1v; v10 += b0v; v11 += b1v;
            }
            if constexpr (RELU) {
                v00 = fmaxf(v00, 0.f); v01 = fmaxf(v01, 0.f);
                v10 = fmaxf(v10, 0.f); v11 = fmaxf(v11, 0.f);
            }
            if constexpr (OF32) {
                float2 p0 = {v00, v01}, p1 = {v10, v11};
                *(float2*)&C[r0 * ldc + c] = p0;
                *(float2*)&C[r1 * ldc + c] = p1;
            } else {
                *(uint32_t*)&Ch[r0 * ldc + c] = pack2h(__float2half_rn(v00), __float2half_rn(v01));
                *(uint32_t*)&Ch[r1 * ldc + c] = pack2h(__float2half_rn(v10), __float2half_rn(v11));
            }
        }
    }
}

// ---------------- fused attention pass 1: column-softmax stats --------------
__global__ __launch_bounds__(256, 2)
void attn_stats_kernel(const bf* __restrict__ q_, const bf* __restrict__ k_,
                       float* __restrict__ gm, float* __restrict__ gil)
{
    constexpr int P = 72, TILE = 128 * P;
    extern __shared__ bf sm[];
    bf* sk = sm;

    int bh = blockIdx.y;
    int s0 = blockIdx.x * 128;
    long base = (long)bh * TT * DKK;
    const bf* Kp = k_ + base + (long)s0 * DKK;
    const bf* Qp = q_ + base;

    int tid = threadIdx.x, lane = tid & 31, wid = tid >> 5;
    int m0 = wid * 16;

    auto loadQ = [&](int ch, int s) {
        bf* dq = sm + TILE + (size_t)s * TILE;
        long q0 = (long)ch * 128;
        #pragma unroll
        for (int i = 0; i < 4; i++) {
            int c = tid + i * 256;
            int r = c >> 3, c8 = (c & 7) * 8;
            cpa16(smaddr(dq + r * P + c8), Qp + (q0 + r) * DKK + c8);
        }
    };

    #pragma unroll
    for (int i = 0; i < 4; i++) {
        int c = tid + i * 256;
        int r = c >> 3, c8 = (c & 7) * 8;
        cpa16(smaddr(sk + r * P + c8), Kp + (long)r * DKK + c8);
    }
    loadQ(0, 0);
    cp_commit();

    float mrow0 = -1e30f, mrow1 = -1e30f;
    float lrow0 = 0.f, lrow1 = 0.f;

    for (int ch = 0; ch < 16; ch++) {
        if (ch + 1 < 16) { loadQ(ch + 1, (ch + 1) & 1); cp_commit(); cp_wait1(); }
        else             { cp_wait0(); }
        __syncthreads();
        const bf* sq = sm + TILE + (size_t)(ch & 1) * TILE;

        float acc[16][4] = {};
        #pragma unroll
        for (int kk = 0; kk < 64; kk += 16) {
            uint32_t a[4];
            {
                int row = m0 + (lane & 15);
                int col = kk + (lane >> 4) * 8;
                ldsm4(a[0], a[1], a[2], a[3], smaddr(sk + row * P + col));
            }
            #pragma unroll
            for (int g = 0; g < 8; g++) {
                int rown = g * 16 + (lane & 7) + ((lane >> 4) & 1) * 8;
                int col = kk + ((lane >> 3) & 1) * 8;
                uint32_t b0, b1, b2, b3;
                ldsm4(b0, b1, b2, b3, smaddr(sq + rown * P + col));
                mma16816(acc[2*g],   a, b0, b1);
                mma16816(acc[2*g+1], a, b2, b3);
            }
        }
        __syncthreads();

        float cm0 = -1e30f, cm1 = -1e30f;
        #pragma unroll
        for (int nf = 0; nf < 16; nf++) {
            cm0 = fmaxf(cm0, fmaxf(acc[nf][0], acc[nf][1]));
            cm1 = fmaxf(cm1, fmaxf(acc[nf][2], acc[nf][3]));
        }
        cm0 *= 0.125f; cm1 *= 0.125f;
        cm0 = fmaxf(cm0, __shfl_xor_sync(~0u, cm0, 1));
        cm0 = fmaxf(cm0, __shfl_xor_sync(~0u, cm0, 2));
        cm1 = fmaxf(cm1, __shfl_xor_sync(~0u, cm1, 1));
        cm1 = fmaxf(cm1, __shfl_xor_sync(~0u, cm1, 2));
        float mn0 = fmaxf(mrow0, cm0), mn1 = fmaxf(mrow1, cm1);
        float sv0 = 0.f, sv1 = 0.f;
        #pragma unroll
        for (int nf = 0; nf < 16; nf++) {
            sv0 += __expf(acc[nf][0] * 0.125f - mn0) + __expf(acc[nf][1] * 0.125f - mn0);
            sv1 += __expf(acc[nf][2] * 0.125f - mn1) + __expf(acc[nf][3] * 0.125f - mn1);
        }
        sv0 += __shfl_xor_sync(~0u, sv0, 1); sv0 += __shfl_xor_sync(~0u, sv0, 2);
        sv1 += __shfl_xor_sync(~0u, sv1, 1); sv1 += __shfl_xor_sync(~0u, sv1, 2);
        lrow0 = lrow0 * __expf(mrow0 - mn0) + sv0;
        lrow1 = lrow1 * __expf(mrow1 - mn1) + sv1;
        mrow0 = mn0; mrow1 = mn1;
    }

    if ((lane & 3) == 0) {
        int r = lane >> 2;
        long o = (long)bh * TT + s0 + m0;
        gm[o + r]      = mrow0;
        gm[o + r + 8]  = mrow1;
        gil[o + r]     = 1.f / lrow0;
        gil[o + r + 8] = 1.f / lrow1;
    }
}

// ---------------- fused attention pass 2: output ----------------------------
__global__ __launch_bounds__(256, 2)
void attn_out_kernel(const bf* __restrict__ q_, const bf* __restrict__ k_,
                     const bf* __restrict__ v_,
                     const float* __restrict__ gm, const float* __restrict__ gil,
                     bf* __restrict__ oc)
{
    constexpr int P = 72, TILE = 128 * P;
    constexpr int STG = 2 * TILE + 512;
    extern __shared__ bf sm[];
    bf* sq = sm;

    int bh = blockIdx.y;
    int q0b = blockIdx.x * 128;
    int b = bh >> 4, h = bh & 15;
    long base = (long)bh * TT * DKK;
    const bf* Qp = q_ + base + (long)q0b * DKK;
    const bf* Kp = k_ + base;
    const bf* Vp = v_ + base;
    const float* Gm = gm + (long)bh * TT;
    const float* Gil = gil + (long)bh * TT;

    int tid = threadIdx.x, lane = tid & 31, wid = tid >> 5;
    int m0 = wid * 16;

    auto loadKV = [&](int ch, int s) {
        bf* st = sm + TILE + (size_t)s * STG;
        bf* dk = st;
        bf* dv = st + TILE;
        float* dml = (float*)(st + 2 * TILE);
        long r0 = (long)ch * 128;
        #pragma unroll
        for (int i = 0; i < 4; i++) {
            int c = tid + i * 256;
            int r = c >> 3, c8 = (c & 7) * 8;
            long go = (r0 + r) * DKK + c8;
            cpa16(smaddr(dk + r * P + c8), Kp + go);
            cpa16(smaddr(dv + r * P + c8), Vp + go);
        }
        if (tid < 32)      cpa16(smaddr(dml + tid * 4),          Gm  + r0 + tid * 4);
        else if (tid < 64) cpa16(smaddr(dml + 128 + (tid-32)*4), Gil + r0 + (tid - 32) * 4);
    };

    #pragma unroll
    for (int i = 0; i < 4; i++) {
        int c = tid + i * 256;
        int r = c >> 3, c8 = (c & 7) * 8;
        cpa16(smaddr(sq + r * P + c8), Qp + (long)r * DKK + c8);
    }
    loadKV(0, 0);
    cp_commit();

    float acc_o[8][4] = {};

    for (int ch = 0; ch < 16; ch++) {
        if (ch + 1 < 16) { loadKV(ch + 1, (ch + 1) & 1); cp_commit(); cp_wait1(); }
        else             { cp_wait0(); }
        __syncthreads();
        bf* st = sm + TILE + (size_t)(ch & 1) * STG;
        const bf* sk = st;
        const bf* sv = st + TILE;
        const float* sml = (const float*)(st + 2 * TILE);

        #pragma unroll
        for (int half = 0; half < 2; half++) {
            float acc8[8][4] = {};
            #pragma unroll
            for (int kk = 0; kk < 64; kk += 16) {
                uint32_t a[4];
                {
                    int row = m0 + (lane & 15);
                    int col = kk + (lane >> 4) * 8;
                    ldsm4(a[0], a[1], a[2], a[3], smaddr(sq + row * P + col));
                }
                #pragma unroll
                for (int g = 0; g < 4; g++) {
                    int rown = half * 64 + g * 16 + (lane & 7) + ((lane >> 4) & 1) * 8;
                    int col = kk + ((lane >> 3) & 1) * 8;
                    uint32_t b0, b1, b2, b3;
                    ldsm4(b0, b1, b2, b3, smaddr(sk + rown * P + col));
                    mma16816(acc8[2*g],   a, b0, b1);
                    mma16816(acc8[2*g+1], a, b2, b3);
                }
            }

            #pragma unroll
            for (int j = 0; j < 4; j++) {
                int cL = half * 64 + j * 16 + (lane & 3) * 2;
                int cH = cL + 8;
                float mL0 = sml[cL],       mL1 = sml[cL + 1];
                float mH0 = sml[cH],       mH1 = sml[cH + 1];
                float iL0 = sml[128 + cL], iL1 = sml[128 + cL + 1];
                float iH0 = sml[128 + cH], iH1 = sml[128 + cH + 1];

                float p00 = __expf(acc8[2*j][0]   * 0.125f - mL0) * iL0;
                float p01 = __expf(acc8[2*j][1]   * 0.125f - mL1) * iL1;
                float p10 = __expf(acc8[2*j][2]   * 0.125f - mL0) * iL0;
                float p11 = __expf(acc8[2*j][3]   * 0.125f - mL1) * iL1;
                float q00 = __expf(acc8[2*j+1][0] * 0.125f - mH0) * iH0;
                float q01 = __expf(acc8[2*j+1][1] * 0.125f - mH1) * iH1;
                float q10 = __expf(acc8[2*j+1][2] * 0.125f - mH0) * iH0;
                float q11 = __expf(acc8[2*j+1][3] * 0.125f - mH1) * iH1;

                uint32_t pa[4];
                pa[0] = pack2(__float2bfloat16(p00), __float2bfloat16(p01));
                pa[1] = pack2(__float2bfloat16(p10), __float2bfloat16(p11));
                pa[2] = pack2(__float2bfloat16(q00), __float2bfloat16(q01));
                pa[3] = pack2(__float2bfloat16(q10), __float2bfloat16(q11));

                #pragma unroll
                for (int g2 = 0; g2 < 4; g2++) {
                    int rowk = half * 64 + j * 16 + (lane & 7) + ((lane >> 3) & 1) * 8;
                    int coln = g2 * 16 + (lane >> 4) * 8;
                    uint32_t b0, b1, b2, b3;
                    ldsm4t(b0, b1, b2, b3, smaddr(sv + rowk * P + coln));
                    mma16816(acc_o[2*g2],   pa, b0, b1);
                    mma16816(acc_o[2*g2+1], pa, b2, b3);
                }
            }
        }
        __syncthreads();
    }

    #pragma unroll
    for (int nf = 0; nf < 8; nf++) {
        long r0 = (long)b * TT + q0b + m0 + (lane >> 2);
        long r1 = r0 + 8;
        long c = (long)h * 64 + nf * 8 + (lane & 3) * 2;
        *(uint32_t*)&oc[r0 * DD + c] =
            pack2(__float2bfloat16(acc_o[nf][0]), __float2bfloat16(acc_o[nf][1]));
        *(uint32_t*)&oc[r1 * DD + c] =
            pack2(__float2bfloat16(acc_o[nf][2]), __float2bfloat16(acc_o[nf][3]));
    }
}

// ---------------- conversions ----------------------------------------------
__global__ void cvt_kernel(const float4* __restrict__ in, uint2* __restrict__ out, long n4)
{
    long i = (long)blockIdx.x * blockDim.x + threadIdx.x;
    if (i >= n4) return;
    float4 v = in[i];
    uint2 o;
    o.x = pack2(__float2bfloat16(v.x), __float2bfloat16(v.y));
    o.y = pack2(__float2bfloat16(v.z), __float2bfloat16(v.w));
    out[i] = o;
}

__global__ void cvth_kernel(const float4* __restrict__ in, uint2* __restrict__ out, long n4)
{
    long i = (long)blockIdx.x * blockDim.x + threadIdx.x;
    if (i >= n4) return;
    float4 v = in[i];
    uint2 o;
    o.x = pack2h(__float2half_rn(v.x), __float2half_rn(v.y));
    o.y = pack2h(__float2half_rn(v.z), __float2half_rn(v.w));
    out[i] = o;
}

// --------- out = meanstd_norm(a + b); optional fp16 copy --------------------
template <bool WHALF>
__global__ void add_norm_kernel(const float* __restrict__ a, const float* __restrict__ b,
                                float* __restrict__ out, hf* __restrict__ oh)
{
    const int D = DD;
    long r = blockIdx.x;
    const float* pa = a + r * D;
    const float* pb = b + r * D;
    int tid = threadIdx.x;

    float y[4];
    float sum = 0.f;
    #pragma unroll
    for (int i = 0; i < 4; i++) {
        y[i] = pa[tid + i * 256] + pb[tid + i * 256];
        sum += y[i];
    }

    __shared__ float red[8];
    #pragma unroll
    for (int o = 16; o > 0; o >>= 1) sum += __shfl_xor_sync(~0u, sum, o);
    if ((tid & 31) == 0) red[tid >> 5] = sum;
    __syncthreads();
    if (tid < 32) {
        float v = (tid < 8) ? red[tid] : 0.f;
        #pragma unroll
        for (int o = 4; o > 0; o >>= 1) v += __shfl_xor_sync(~0u, v, o);
        if (tid == 0) red[0] = v;
    }
    __syncthreads();
    float mean = red[0] / D;
    __syncthreads();

    float vs = 0.f;
    #pragma unroll
    for (int i = 0; i < 4; i++) {
        float d = y[i] - mean;
        vs += d * d;
    }
    #pragma unroll
    for (int o = 16; o > 0; o >>= 1) vs += __shfl_xor_sync(~0u, vs, o);
    if ((tid & 31) == 0) red[tid >> 5] = vs;
    __syncthreads();
    if (tid < 32) {
        float v = (tid < 8) ? red[tid] : 0.f;
        #pragma unroll
        for (int o = 4; o > 0; o >>= 1) v += __shfl_xor_sync(~0u, v, o);
        if (tid == 0) red[0] = v;
    }
    __syncthreads();
    float inv = rsqrtf(red[0] / (float)(D - 1));

    #pragma unroll
    for (int i = 0; i < 4; i++) {
        float v = (y[i] - mean) * inv;
        long idx = r * D + tid + i * 256;
        out[idx] = v;
        if constexpr (WHALF)
            oh[idx] = __float2half_rn(v);
    }
}

// ---------------------------------------------------------------------------
static inline void* sym(const void* s) {
    void* p = nullptr;
    cudaGetSymbolAddress(&p, s);
    return p;
}

extern "C" void kernel_launch(void* const* d_in, const int* in_sizes, int n_in,
                              void* d_out, int out_size)
{
    const float* x  = (const float*)d_in[0];
    const float* Wq = (const float*)d_in[1];
    const float* Wk = (const float*)d_in[2];
    const float* Wv = (const float*)d_in[3];
    const float* Wo = (const float*)d_in[4];
    const float* W1 = (const float*)d_in[5];
    const float* b1 = (const float*)d_in[6];
    const float* W2 = (const float*)d_in[7];
    const float* b2 = (const float*)d_in[8];
    float* out = (float*)d_out;

    float* tp = (float*)sym(g_tmp);
    float* o1 = (float*)sym(g_out1);
    float* gm = (float*)sym(g_m);
    float* gil = (float*)sym(g_il);
    bf *xb = (bf*)sym(g_xb);
    bf *wq = (bf*)sym(g_wq), *wk = (bf*)sym(g_wk), *wv = (bf*)sym(g_wv), *wo = (bf*)sym(g_wo);
    bf *q = (bf*)sym(g_q), *k = (bf*)sym(g_k), *v = (bf*)sym(g_v);
    bf *oc = (bf*)sym(g_oc);
    hf *w1f = (hf*)sym(g_w1f), *w2f = (hf*)sym(g_w2f);
    hf *o1f = (hf*)sym(g_o1f), *fhf = (hf*)sym(g_fhf);

    const long TD  = (long)TT * DD;
    const long HD  = (long)DD * DKK;
    const long HT  = (long)TT * DKK;
    const long BHT = (long)HH * HT;

    constexpr int SM_B64  = (128 * 40 + 32 * 72) * 2 * 2;            // 29696
    constexpr int SM_B128 = (128 * 40 + 32 * 136) * 2 * 2;           // 37888
    constexpr int SM_AT1  = 3 * (128 * 72) * 2;                      // 55296
    constexpr int SM_AT2  = (128 * 72 + 2 * (2 * 128 * 72 + 512)) * 2;  // 94208
    cudaFuncSetAttribute(attn_stats_kernel,
                         cudaFuncAttributeMaxDynamicSharedMemorySize, SM_AT1);
    cudaFuncSetAttribute(attn_out_kernel,
                         cudaFuncAttributeMaxDynamicSharedMemorySize, SM_AT2);

    // 0) conversions
    auto cvt = [&](const float* in, bf* o, long n) {
        long n4 = n / 4;
        cvt_kernel<<<(unsigned)((n4 + 255) / 256), 256>>>(
            (const float4*)in, (uint2*)o, n4);
    };
    auto cvth = [&](const float* in, hf* o, long n) {
        long n4 = n / 4;
        cvth_kernel<<<(unsigned)((n4 + 255) / 256), 256>>>(
            (const float4*)in, (uint2*)o, n4);
    };
    cvt(x,  xb, (long)BB * TT * DD);
    cvt(Wq, wq, (long)HH * DD * DKK);
    cvt(Wk, wk, (long)HH * DD * DKK);
    cvt(Wv, wv, (long)HH * DD * DKK);
    cvt(Wo, wo, (long)DD * DD);
    cvth(W1, w1f, (long)DD * FFF);
    cvth(W2, w2f, (long)FFF * DD);

    // 1) Q,K,V projections (plain bf16)
    dim3 gproj(1, TT / 128, BB * HH);
    bgemm<64, false><<<gproj, 256, SM_B64>>>(xb, wq, nullptr, q,
        DD, DD, DKK, DKK, TD, 0, 0, HD, BHT, HT, HH);
    bgemm<64, false><<<gproj, 256, SM_B64>>>(xb, wk, nullptr, k,
        DD, DD, DKK, DKK, TD, 0, 0, HD, BHT, HT, HH);
    bgemm<64, false><<<gproj, 256, SM_B64>>>(xb, wv, nullptr, v,
        DD, DD, DKK, DKK, TD, 0, 0, HD, BHT, HT, HH);

    // 2) fused attention
    dim3 gat(TT / 128, BB * HH);
    attn_stats_kernel<<<gat, 256, SM_AT1>>>(q, k, gm, gil);
    attn_out_kernel<<<gat, 256, SM_AT2>>>(q, k, v, gm, gil, oc);

    // 3) tmp = ocat @ Wo (plain bf16)
    dim3 gwo(DD / 128, (BB * TT) / 128, 1);
    bgemm<128, true><<<gwo, 256, SM_B128>>>(oc, wo, tp, nullptr,
        DD, DD, DD, DD, 0, 0, 0, 0, 0, 0, 1);

    // 4) out1 = norm(tmp + x), plus fp16 copy for FFN
    add_norm_kernel<true><<<BB * TT, 256>>>(tp, x, o1, o1f);

    // 5) ffh = relu(out1 @ W1 + b1) (fp16, 1 MMA)
    dim3 gf1(FFF / 128, (BB * TT) / 128, 1);
    hgemm<true, true, false><<<gf1, 256, SM_B128>>>(
        o1f, w1f, nullptr, fhf, b1, DD, DD, FFF, FFF);

    // 6) tmp = ffh @ W2 + b2 (fp16, 1 MMA)
    dim3 gf2(DD / 128, (BB * TT) / 128, 1);
    hgemm<true, false, true><<<gf2, 256, SM_B128>>>(
        fhf, w2f, tp, nullptr, b2, FFF, FFF, DD, DD);

    // 7) out = norm(tmp + out1)
    add_norm_kernel<false><<<BB * TT, 256>>>(tp, o1, out, nullptr);
}

// round 11
// speedup vs baseline: 9.9394x; 1.0926x over previous
#include <cuda_runtime.h>
#include <cuda_bf16.h>
#include <cuda_fp16.h>
#include <cstdint>

#define BB 2
#define TT 2048
#define DD 1024
#define HH 16
#define DKK 64
#define FFF 4096

using bf = __nv_bfloat16;
using hf = __half;

// ---------------- scratch (static device memory; no allocs) ----------------
__device__ __align__(256) float g_tmp[(size_t)BB * TT * DD];
__device__ __align__(256) float g_out1[(size_t)BB * TT * DD];
__device__ __align__(256) float g_m[(size_t)BB * HH * TT];
__device__ __align__(256) float g_il[(size_t)BB * HH * TT];

__device__ __align__(256) bf g_xb[(size_t)BB * TT * DD];
__device__ __align__(256) bf g_wq[(size_t)HH * DD * DKK];
__device__ __align__(256) bf g_wk[(size_t)HH * DD * DKK];
__device__ __align__(256) bf g_wv[(size_t)HH * DD * DKK];
__device__ __align__(256) bf g_wo[(size_t)DD * DD];
__device__ __align__(256) bf g_q[(size_t)BB * HH * TT * DKK];
__device__ __align__(256) bf g_k[(size_t)BB * HH * TT * DKK];
__device__ __align__(256) bf g_v[(size_t)BB * HH * TT * DKK];
__device__ __align__(256) bf g_oc[(size_t)BB * TT * DD];

__device__ __align__(256) hf g_w1f[(size_t)DD * FFF];
__device__ __align__(256) hf g_w2f[(size_t)FFF * DD];
__device__ __align__(256) hf g_o1f[(size_t)BB * TT * DD];
__device__ __align__(256) hf g_fhf[(size_t)BB * TT * FFF];

// ---------------- small helpers -------------------------------------------
__device__ __forceinline__ uint32_t smaddr(const void* p) {
    return (uint32_t)__cvta_generic_to_shared(p);
}
__device__ __forceinline__ void cpa16(uint32_t s, const void* g) {
    asm volatile("cp.async.cg.shared.global [%0], [%1], 16;\n" :: "r"(s), "l"(g));
}
__device__ __forceinline__ void cp_commit() {
    asm volatile("cp.async.commit_group;\n" ::: "memory");
}
__device__ __forceinline__ void cp_wait1() {
    asm volatile("cp.async.wait_group 1;\n" ::: "memory");
}
__device__ __forceinline__ void cp_wait0() {
    asm volatile("cp.async.wait_group 0;\n" ::: "memory");
}
__device__ __forceinline__ void ldsm4(uint32_t& r0, uint32_t& r1, uint32_t& r2, uint32_t& r3, uint32_t a) {
    asm volatile("ldmatrix.sync.aligned.m8n8.x4.shared.b16 {%0,%1,%2,%3}, [%4];\n"
                 : "=r"(r0), "=r"(r1), "=r"(r2), "=r"(r3) : "r"(a));
}
__device__ __forceinline__ void ldsm4t(uint32_t& r0, uint32_t& r1, uint32_t& r2, uint32_t& r3, uint32_t a) {
    asm volatile("ldmatrix.sync.aligned.m8n8.x4.trans.shared.b16 {%0,%1,%2,%3}, [%4];\n"
                 : "=r"(r0), "=r"(r1), "=r"(r2), "=r"(r3) : "r"(a));
}
__device__ __forceinline__ void mma16816(float* d, const uint32_t* a, uint32_t b0, uint32_t b1) {
    asm volatile(
        "mma.sync.aligned.m16n8k16.row.col.f32.bf16.bf16.f32 "
        "{%0,%1,%2,%3}, {%4,%5,%6,%7}, {%8,%9}, {%0,%1,%2,%3};\n"
        : "+f"(d[0]), "+f"(d[1]), "+f"(d[2]), "+f"(d[3])
        : "r"(a[0]), "r"(a[1]), "r"(a[2]), "r"(a[3]), "r"(b0), "r"(b1));
}
__device__ __forceinline__ void mma16816h(float* d, const uint32_t* a, uint32_t b0, uint32_t b1) {
    asm volatile(
        "mma.sync.aligned.m16n8k16.row.col.f32.f16.f16.f32 "
        "{%0,%1,%2,%3}, {%4,%5,%6,%7}, {%8,%9}, {%0,%1,%2,%3};\n"
        : "+f"(d[0]), "+f"(d[1]), "+f"(d[2]), "+f"(d[3])
        : "r"(a[0]), "r"(a[1]), "r"(a[2]), "r"(a[3]), "r"(b0), "r"(b1));
}
__device__ __forceinline__ uint32_t pack2(bf a, bf b) {
    __nv_bfloat162 p; p.x = a; p.y = b;
    return *(uint32_t*)&p;
}
__device__ __forceinline__ uint32_t pack2h(hf a, hf b) {
    __half2 p; p.x = a; p.y = b;
    return *(uint32_t*)&p;
}

// ---------------- plain-bf16 tensor-core GEMM (attention branch) -----------
// BK=64 double-buffered; accumulation order identical to BK=32 version.
template <int BN, bool OF32>
__global__ __launch_bounds__(256, 2)
void bgemm(const bf* __restrict__ A, const bf* __restrict__ B,
           float* __restrict__ C, bf* __restrict__ Cb,
           int K, int lda, int ldb, int ldc,
           long soA, long siA, long soB, long siB, long soC, long siC, int inner)
{
    constexpr int BM = 128, BK = 64, AP = 72, BP = BN + 8;
    constexpr int AE = BM * AP, BE = BK * BP, STG = AE + BE;
    extern __shared__ bf sm[];

    int z = blockIdx.z;
    int zo = z / inner, zi = z - zo * inner;
    A += zo * soA + zi * siA;
    B += zo * soB + zi * siB;
    long coff = zo * soC + zi * siC;

    int tid = threadIdx.x, lane = tid & 31, wid = tid >> 5;
    constexpr int MF = (BN == 128) ? 4 : 2;
    constexpr int NF = 4;
    int wm = (BN == 128) ? (wid >> 2) : (wid >> 1);
    int wn = (BN == 128) ? (wid & 3) : (wid & 1);
    int m0 = wm * MF * 16, n0 = wn * 32;

    long bm = (long)blockIdx.y * BM, bn = (long)blockIdx.x * BN;

    float acc[MF][NF][4] = {};

    auto copyStage = [&](int kt, int s) {
        int k0 = kt * BK;
        bf* sa = sm + (size_t)s * STG;
        bf* sb = sa + AE;
        #pragma unroll
        for (int i = 0; i < 4; i++) {
            int c = tid + i * 256;
            int r = c >> 3, cc = (c & 7) * 8;
            cpa16(smaddr(sa + r * AP + cc), A + (bm + r) * (long)lda + k0 + cc);
        }
        constexpr int CPR = BN / 8;
        #pragma unroll
        for (int i = 0; i < (64 * CPR) / 256; i++) {
            int c = tid + i * 256;
            int r = c / CPR, cc = (c % CPR) * 8;
            cpa16(smaddr(sb + r * BP + cc), B + (long)(k0 + r) * ldb + bn + cc);
        }
        cp_commit();
    };

    auto compute = [&](int s) {
        const bf* sa = sm + (size_t)s * STG;
        const bf* sb = sa + AE;
        #pragma unroll
        for (int kk = 0; kk < BK; kk += 16) {
            uint32_t b2[NF][2];
            #pragma unroll
            for (int g = 0; g < 2; g++) {
                int rowk = kk + (lane & 7) + ((lane >> 3) & 1) * 8;
                int coln = n0 + g * 16 + (lane >> 4) * 8;
                ldsm4t(b2[2*g][0], b2[2*g][1], b2[2*g+1][0], b2[2*g+1][1],
                       smaddr(sb + rowk * BP + coln));
            }
            #pragma unroll
            for (int mf = 0; mf < MF; mf++) {
                uint32_t a[4];
                int row = m0 + mf * 16 + (lane & 15);
                int col = kk + (lane >> 4) * 8;
                ldsm4(a[0], a[1], a[2], a[3], smaddr(sa + row * AP + col));
                #pragma unroll
                for (int nf = 0; nf < NF; nf++)
                    mma16816(acc[mf][nf], a, b2[nf][0], b2[nf][1]);
            }
        }
    };

    int nk = K / BK;
    copyStage(0, 0);
    for (int kt = 0; kt < nk; kt++) {
        if (kt + 1 < nk) { copyStage(kt + 1, (kt + 1) & 1); cp_wait1(); }
        else             { cp_wait0(); }
        __syncthreads();
        compute(kt & 1);
        __syncthreads();
    }

    #pragma unroll
    for (int mf = 0; mf < MF; mf++) {
        #pragma unroll
        for (int nf = 0; nf < NF; nf++) {
            long r0 = bm + m0 + mf * 16 + (lane >> 2);
            long r1 = r0 + 8;
            long c  = bn + n0 + nf * 8 + (lane & 3) * 2;
            if constexpr (OF32) {
                float2 p0 = {acc[mf][nf][0], acc[mf][nf][1]};
                float2 p1 = {acc[mf][nf][2], acc[mf][nf][3]};
                *(float2*)&C[coff + r0 * ldc + c] = p0;
                *(float2*)&C[coff + r1 * ldc + c] = p1;
            } else {
                *(uint32_t*)&Cb[coff + r0 * ldc + c] =
                    pack2(__float2bfloat16(acc[mf][nf][0]), __float2bfloat16(acc[mf][nf][1]));
                *(uint32_t*)&Cb[coff + r1 * ldc + c] =
                    pack2(__float2bfloat16(acc[mf][nf][2]), __float2bfloat16(acc[mf][nf][3]));
            }
        }
    }
}

// ---------------- fp16 tensor-core GEMM (FFN path, 1 MMA, BK=64) -----------
template <bool BIAS, bool RELU, bool OF32>
__global__ __launch_bounds__(256, 2)
void hgemm(const hf* __restrict__ A, const hf* __restrict__ B,
           float* __restrict__ C, hf* __restrict__ Ch,
           const float* __restrict__ bias,
           int K, int lda, int ldb, int ldc)
{
    constexpr int BM = 128, BN = 128, BK = 64, AP = 72, BP = BN + 8;
    constexpr int AE = BM * AP, BE = BK * BP, STG = AE + BE;
    extern __shared__ hf smh[];

    int tid = threadIdx.x, lane = tid & 31, wid = tid >> 5;
    constexpr int MF = 4, NF = 4;
    int wm = wid >> 2, wn = wid & 3;
    int m0 = wm * MF * 16, n0 = wn * 32;

    long bm = (long)blockIdx.y * BM, bn = (long)blockIdx.x * BN;

    float acc[MF][NF][4] = {};

    auto copyStage = [&](int kt, int s) {
        int k0 = kt * BK;
        hf* sa = smh + (size_t)s * STG;
        hf* sb = sa + AE;
        #pragma unroll
        for (int i = 0; i < 4; i++) {
            int c = tid + i * 256;
            int r = c >> 3, cc = (c & 7) * 8;
            cpa16(smaddr(sa + r * AP + cc), A + (bm + r) * (long)lda + k0 + cc);
        }
        #pragma unroll
        for (int i = 0; i < 4; i++) {
            int c = tid + i * 256;
            int r = c >> 4, cc = (c & 15) * 8;
            cpa16(smaddr(sb + r * BP + cc), B + (long)(k0 + r) * ldb + bn + cc);
        }
        cp_commit();
    };

    auto compute = [&](int s) {
        const hf* sa = smh + (size_t)s * STG;
        const hf* sb = sa + AE;
        #pragma unroll
        for (int kk = 0; kk < BK; kk += 16) {
            uint32_t b2[NF][2];
            #pragma unroll
            for (int g = 0; g < 2; g++) {
                int rowk = kk + (lane & 7) + ((lane >> 3) & 1) * 8;
                int coln = n0 + g * 16 + (lane >> 4) * 8;
                ldsm4t(b2[2*g][0], b2[2*g][1], b2[2*g+1][0], b2[2*g+1][1],
                       smaddr(sb + rowk * BP + coln));
            }
            #pragma unroll
            for (int mf = 0; mf < MF; mf++) {
                uint32_t a[4];
                int row = m0 + mf * 16 + (lane & 15);
                int col = kk + (lane >> 4) * 8;
                ldsm4(a[0], a[1], a[2], a[3], smaddr(sa + row * AP + col));
                #pragma unroll
                for (int nf = 0; nf < NF; nf++)
                    mma16816h(acc[mf][nf], a, b2[nf][0], b2[nf][1]);
            }
        }
    };

    int nk = K / BK;
    copyStage(0, 0);
    for (int kt = 0; kt < nk; kt++) {
        if (kt + 1 < nk) { copyStage(kt + 1, (kt + 1) & 1); cp_wait1(); }
        else             { cp_wait0(); }
        __syncthreads();
        compute(kt & 1);
        __syncthreads();
    }

    #pragma unroll
    for (int mf = 0; mf < MF; mf++) {
        #pragma unroll
        for (int nf = 0; nf < NF; nf++) {
            long r0 = bm + m0 + mf * 16 + (lane >> 2);
            long r1 = r0 + 8;
            long c  = bn + n0 + nf * 8 + (lane & 3) * 2;
            float v00 = acc[mf][nf][0];
            float v01 = acc[mf][nf][1];
            float v10 = acc[mf][nf][2];
            float v11 = acc[mf][nf][3];
            if constexpr (BIAS) {
                float b0v = bias[c], b1v = bias[c + 1];
                v00 += b0v; v01 += b1v; v10 += b0v; v11 += b1v;
            }
            if constexpr (RELU) {
                v00 = fmaxf(v00, 0.f); v01 = fmaxf(v01, 0.f);
                v10 = fmaxf(v10, 0.f); v11 = fmaxf(v11, 0.f);
            }
            if constexpr (OF32) {
                float2 p0 = {v00, v01}, p1 = {v10, v11};
                *(float2*)&C[r0 * ldc + c] = p0;
                *(float2*)&C[r1 * ldc + c] = p1;
            } else {
                *(uint32_t*)&Ch[r0 * ldc + c] = pack2h(__float2half_rn(v00), __float2half_rn(v01));
                *(uint32_t*)&Ch[r1 * ldc + c] = pack2h(__float2half_rn(v10), __float2half_rn(v11));
            }
        }
    }
}

// ---------------- fused attention pass 1: column-softmax stats --------------
__global__ __launch_bounds__(256, 2)
void attn_stats_kernel(const bf* __restrict__ q_, const bf* __restrict__ k_,
                       float* __restrict__ gm, float* __restrict__ gil)
{
    constexpr int P = 72, TILE = 128 * P;
    extern __shared__ bf sm[];
    bf* sk = sm;

    int bh = blockIdx.y;
    int s0 = blockIdx.x * 128;
    long base = (long)bh * TT * DKK;
    const bf* Kp = k_ + base + (long)s0 * DKK;
    const bf* Qp = q_ + base;

    int tid = threadIdx.x, lane = tid & 31, wid = tid >> 5;
    int m0 = wid * 16;

    auto loadQ = [&](int ch, int s) {
        bf* dq = sm + TILE + (size_t)s * TILE;
        long q0 = (long)ch * 128;
        #pragma unroll
        for (int i = 0; i < 4; i++) {
            int c = tid + i * 256;
            int r = c >> 3, c8 = (c & 7) * 8;
            cpa16(smaddr(dq + r * P + c8), Qp + (q0 + r) * DKK + c8);
        }
    };

    #pragma unroll
    for (int i = 0; i < 4; i++) {
        int c = tid + i * 256;
        int r = c >> 3, c8 = (c & 7) * 8;
        cpa16(smaddr(sk + r * P + c8), Kp + (long)r * DKK + c8);
    }
    loadQ(0, 0);
    cp_commit();

    float mrow0 = -1e30f, mrow1 = -1e30f;
    float lrow0 = 0.f, lrow1 = 0.f;

    for (int ch = 0; ch < 16; ch++) {
        if (ch + 1 < 16) { loadQ(ch + 1, (ch + 1) & 1); cp_commit(); cp_wait1(); }
        else             { cp_wait0(); }
        __syncthreads();
        const bf* sq = sm + TILE + (size_t)(ch & 1) * TILE;

        float acc[16][4] = {};
        #pragma unroll
        for (int kk = 0; kk < 64; kk += 16) {
            uint32_t a[4];
            {
                int row = m0 + (lane & 15);
                int col = kk + (lane >> 4) * 8;
                ldsm4(a[0], a[1], a[2], a[3], smaddr(sk + row * P + col));
            }
            #pragma unroll
            for (int g = 0; g < 8; g++) {
                int rown = g * 16 + (lane & 7) + ((lane >> 4) & 1) * 8;
                int col = kk + ((lane >> 3) & 1) * 8;
                uint32_t b0, b1, b2, b3;
                ldsm4(b0, b1, b2, b3, smaddr(sq + rown * P + col));
                mma16816(acc[2*g],   a, b0, b1);
                mma16816(acc[2*g+1], a, b2, b3);
            }
        }
        __syncthreads();

        float cm0 = -1e30f, cm1 = -1e30f;
        #pragma unroll
        for (int nf = 0; nf < 16; nf++) {
            cm0 = fmaxf(cm0, fmaxf(acc[nf][0], acc[nf][1]));
            cm1 = fmaxf(cm1, fmaxf(acc[nf][2], acc[nf][3]));
        }
        cm0 *= 0.125f; cm1 *= 0.125f;
        cm0 = fmaxf(cm0, __shfl_xor_sync(~0u, cm0, 1));
        cm0 = fmaxf(cm0, __shfl_xor_sync(~0u, cm0, 2));
        cm1 = fmaxf(cm1, __shfl_xor_sync(~0u, cm1, 1));
        cm1 = fmaxf(cm1, __shfl_xor_sync(~0u, cm1, 2));
        float mn0 = fmaxf(mrow0, cm0), mn1 = fmaxf(mrow1, cm1);
        float sv0 = 0.f, sv1 = 0.f;
        #pragma unroll
        for (int nf = 0; nf < 16; nf++) {
            sv0 += __expf(acc[nf][0] * 0.125f - mn0) + __expf(acc[nf][1] * 0.125f - mn0);
            sv1 += __expf(acc[nf][2] * 0.125f - mn1) + __expf(acc[nf][3] * 0.125f - mn1);
        }
        sv0 += __shfl_xor_sync(~0u, sv0, 1); sv0 += __shfl_xor_sync(~0u, sv0, 2);
        sv1 += __shfl_xor_sync(~0u, sv1, 1); sv1 += __shfl_xor_sync(~0u, sv1, 2);
        lrow0 = lrow0 * __expf(mrow0 - mn0) + sv0;
        lrow1 = lrow1 * __expf(mrow1 - mn1) + sv1;
        mrow0 = mn0; mrow1 = mn1;
    }

    if ((lane & 3) == 0) {
        int r = lane >> 2;
        long o = (long)bh * TT + s0 + m0;
        gm[o + r]      = mrow0;
        gm[o + r + 8]  = mrow1;
        gil[o + r]     = 1.f / lrow0;
        gil[o + r + 8] = 1.f / lrow1;
    }
}

// ---------------- fused attention pass 2: output ----------------------------
__global__ __launch_bounds__(256, 2)
void attn_out_kernel(const bf* __restrict__ q_, const bf* __restrict__ k_,
                     const bf* __restrict__ v_,
                     const float* __restrict__ gm, const float* __restrict__ gil,
                     bf* __restrict__ oc)
{
    constexpr int P = 72, TILE = 128 * P;
    constexpr int STG = 2 * TILE + 512;
    extern __shared__ bf sm[];
    bf* sq = sm;

    int bh = blockIdx.y;
    int q0b = blockIdx.x * 128;
    int b = bh >> 4, h = bh & 15;
    long base = (long)bh * TT * DKK;
    const bf* Qp = q_ + base + (long)q0b * DKK;
    const bf* Kp = k_ + base;
    const bf* Vp = v_ + base;
    const float* Gm = gm + (long)bh * TT;
    const float* Gil = gil + (long)bh * TT;

    int tid = threadIdx.x, lane = tid & 31, wid = tid >> 5;
    int m0 = wid * 16;

    auto loadKV = [&](int ch, int s) {
        bf* st = sm + TILE + (size_t)s * STG;
        bf* dk = st;
        bf* dv = st + TILE;
        float* dml = (float*)(st + 2 * TILE);
        long r0 = (long)ch * 128;
        #pragma unroll
        for (int i = 0; i < 4; i++) {
            int c = tid + i * 256;
            int r = c >> 3, c8 = (c & 7) * 8;
            long go = (r0 + r) * DKK + c8;
            cpa16(smaddr(dk + r * P + c8), Kp + go);
            cpa16(smaddr(dv + r * P + c8), Vp + go);
        }
        if (tid < 32)      cpa16(smaddr(dml + tid * 4),          Gm  + r0 + tid * 4);
        else if (tid < 64) cpa16(smaddr(dml + 128 + (tid-32)*4), Gil + r0 + (tid - 32) * 4);
    };

    #pragma unroll
    for (int i = 0; i < 4; i++) {
        int c = tid + i * 256;
        int r = c >> 3, c8 = (c & 7) * 8;
        cpa16(smaddr(sq + r * P + c8), Qp + (long)r * DKK + c8);
    }
    loadKV(0, 0);
    cp_commit();

    float acc_o[8][4] = {};

    for (int ch = 0; ch < 16; ch++) {
        if (ch + 1 < 16) { loadKV(ch + 1, (ch + 1) & 1); cp_commit(); cp_wait1(); }
        else             { cp_wait0(); }
        __syncthreads();
        bf* st = sm + TILE + (size_t)(ch & 1) * STG;
        const bf* sk = st;
        const bf* sv = st + TILE;
        const float* sml = (const float*)(st + 2 * TILE);

        #pragma unroll
        for (int half = 0; half < 2; half++) {
            float acc8[8][4] = {};
            #pragma unroll
            for (int kk = 0; kk < 64; kk += 16) {
                uint32_t a[4];
                {
                    int row = m0 + (lane & 15);
                    int col = kk + (lane >> 4) * 8;
                    ldsm4(a[0], a[1], a[2], a[3], smaddr(sq + row * P + col));
                }
                #pragma unroll
                for (int g = 0; g < 4; g++) {
                    int rown = half * 64 + g * 16 + (lane & 7) + ((lane >> 4) & 1) * 8;
                    int col = kk + ((lane >> 3) & 1) * 8;
                    uint32_t b0, b1, b2, b3;
                    ldsm4(b0, b1, b2, b3, smaddr(sk + rown * P + col));
                    mma16816(acc8[2*g],   a, b0, b1);
                    mma16816(acc8[2*g+1], a, b2, b3);
                }
            }

            #pragma unroll
            for (int j = 0; j < 4; j++) {
                int cL = half * 64 + j * 16 + (lane & 3) * 2;
                int cH = cL + 8;
                float mL0 = sml[cL],       mL1 = sml[cL + 1];
                float mH0 = sml[cH],       mH1 = sml[cH + 1];
                float iL0 = sml[128 + cL], iL1 = sml[128 + cL + 1];
                float iH0 = sml[128 + cH], iH1 = sml[128 + cH + 1];

                float p00 = __expf(acc8[2*j][0]   * 0.125f - mL0) * iL0;
                float p01 = __expf(acc8[2*j][1]   * 0.125f - mL1) * iL1;
                float p10 = __expf(acc8[2*j][2]   * 0.125f - mL0) * iL0;
                float p11 = __expf(acc8[2*j][3]   * 0.125f - mL1) * iL1;
                float q00 = __expf(acc8[2*j+1][0] * 0.125f - mH0) * iH0;
                float q01 = __expf(acc8[2*j+1][1] * 0.125f - mH1) * iH1;
                float q10 = __expf(acc8[2*j+1][2] * 0.125f - mH0) * iH0;
                float q11 = __expf(acc8[2*j+1][3] * 0.125f - mH1) * iH1;

                uint32_t pa[4];
                pa[0] = pack2(__float2bfloat16(p00), __float2bfloat16(p01));
                pa[1] = pack2(__float2bfloat16(p10), __float2bfloat16(p11));
                pa[2] = pack2(__float2bfloat16(q00), __float2bfloat16(q01));
                pa[3] = pack2(__float2bfloat16(q10), __float2bfloat16(q11));

                #pragma unroll
                for (int g2 = 0; g2 < 4; g2++) {
                    int rowk = half * 64 + j * 16 + (lane & 7) + ((lane >> 3) & 1) * 8;
                    int coln = g2 * 16 + (lane >> 4) * 8;
                    uint32_t b0, b1, b2, b3;
                    ldsm4t(b0, b1, b2, b3, smaddr(sv + rowk * P + coln));
                    mma16816(acc_o[2*g2],   pa, b0, b1);
                    mma16816(acc_o[2*g2+1], pa, b2, b3);
                }
            }
        }
        __syncthreads();
    }

    #pragma unroll
    for (int nf = 0; nf < 8; nf++) {
        long r0 = (long)b * TT + q0b + m0 + (lane >> 2);
        long r1 = r0 + 8;
        long c = (long)h * 64 + nf * 8 + (lane & 3) * 2;
        *(uint32_t*)&oc[r0 * DD + c] =
            pack2(__float2bfloat16(acc_o[nf][0]), __float2bfloat16(acc_o[nf][1]));
        *(uint32_t*)&oc[r1 * DD + c] =
            pack2(__float2bfloat16(acc_o[nf][2]), __float2bfloat16(acc_o[nf][3]));
    }
}

// ---------------- fused conversion: all 7 tensors in one launch -------------
__global__ void cvt_all_kernel(
    const float4* __restrict__ x,  const float4* __restrict__ wq,
    const float4* __restrict__ wk, const float4* __restrict__ wv,
    const float4* __restrict__ wo, const float4* __restrict__ w1,
    const float4* __restrict__ w2,
    uint2* __restrict__ xb, uint2* __restrict__ wqb, uint2* __restrict__ wkb,
    uint2* __restrict__ wvb, uint2* __restrict__ wob,
    uint2* __restrict__ w1f, uint2* __restrict__ w2f)
{
    const long N_X  = (long)BB * TT * DD / 4;
    const long N_W  = (long)HH * DD * DKK / 4;
    const long N_WO = (long)DD * DD / 4;
    const long N_F  = (long)DD * FFF / 4;
    const long b0 = N_X, b1 = b0 + N_W, b2 = b1 + N_W, b3 = b2 + N_W;
    const long b4 = b3 + N_WO, b5 = b4 + N_F, b6 = b5 + N_F;

    long i = (long)blockIdx.x * blockDim.x + threadIdx.x;
    if (i >= b6) return;

    const float4* src;
    uint2* dst;
    long off;
    bool half_out = false;
    if (i < b0)      { src = x;  dst = xb;  off = i; }
    else if (i < b1) { src = wq; dst = wqb; off = i - b0; }
    else if (i < b2) { src = wk; dst = wkb; off = i - b1; }
    else if (i < b3) { src = wv; dst = wvb; off = i - b2; }
    else if (i < b4) { src = wo; dst = wob; off = i - b3; }
    else if (i < b5) { src = w1; dst = w1f; off = i - b4; half_out = true; }
    else             { src = w2; dst = w2f; off = i - b5; half_out = true; }

    float4 v = src[off];
    uint2 o;
    if (!half_out) {
        o.x = pack2(__float2bfloat16(v.x), __float2bfloat16(v.y));
        o.y = pack2(__float2bfloat16(v.z), __float2bfloat16(v.w));
    } else {
        o.x = pack2h(__float2half_rn(v.x), __float2half_rn(v.y));
        o.y = pack2h(__float2half_rn(v.z), __float2half_rn(v.w));
    }
    dst[off] = o;
}

// --------- out = meanstd_norm(a + b); optional fp16 copy --------------------
template <bool WHALF>
__global__ void add_norm_kernel(const float* __restrict__ a, const float* __restrict__ b,
                                float* __restrict__ out, hf* __restrict__ oh)
{
    const int D = DD;
    long r = blockIdx.x;
    const float* pa = a + r * D;
    const float* pb = b + r * D;
    int tid = threadIdx.x;

    float y[4];
    float sum = 0.f;
    #pragma unroll
    for (int i = 0; i < 4; i++) {
        y[i] = pa[tid + i * 256] + pb[tid + i * 256];
        sum += y[i];
    }

    __shared__ float red[8];
    #pragma unroll
    for (int o = 16; o > 0; o >>= 1) sum += __shfl_xor_sync(~0u, sum, o);
    if ((tid & 31) == 0) red[tid >> 5] = sum;
    __syncthreads();
    if (tid < 32) {
        float v = (tid < 8) ? red[tid] : 0.f;
        #pragma unroll
        for (int o = 4; o > 0; o >>= 1) v += __shfl_xor_sync(~0u, v, o);
        if (tid == 0) red[0] = v;
    }
    __syncthreads();
    float mean = red[0] / D;
    __syncthreads();

    float vs = 0.f;
    #pragma unroll
    for (int i = 0; i < 4; i++) {
        float d = y[i] - mean;
        vs += d * d;
    }
    #pragma unroll
    for (int o = 16; o > 0; o >>= 1) vs += __shfl_xor_sync(~0u, vs, o);
    if ((tid & 31) == 0) red[tid >> 5] = vs;
    __syncthreads();
    if (tid < 32) {
        float v = (tid < 8) ? red[tid] : 0.f;
        #pragma unroll
        for (int o = 4; o > 0; o >>= 1) v += __shfl_xor_sync(~0u, v, o);
        if (tid == 0) red[0] = v;
    }
    __syncthreads();
    float inv = rsqrtf(red[0] / (float)(D - 1));

    #pragma unroll
    for (int i = 0; i < 4; i++) {
        float v = (y[i] - mean) * inv;
        long idx = r * D + tid + i * 256;
        out[idx] = v;
        if constexpr (WHALF)
            oh[idx] = __float2half_rn(v);
    }
}

// ---------------------------------------------------------------------------
static inline void* sym(const void* s) {
    void* p = nullptr;
    cudaGetSymbolAddress(&p, s);
    return p;
}

extern "C" void kernel_launch(void* const* d_in, const int* in_sizes, int n_in,
                              void* d_out, int out_size)
{
    const float* x  = (const float*)d_in[0];
    const float* Wq = (const float*)d_in[1];
    const float* Wk = (const float*)d_in[2];
    const float* Wv = (const float*)d_in[3];
    const float* Wo = (const float*)d_in[4];
    const float* W1 = (const float*)d_in[5];
    const float* b1 = (const float*)d_in[6];
    const float* W2 = (const float*)d_in[7];
    const float* b2 = (const float*)d_in[8];
    float* out = (float*)d_out;

    float* tp = (float*)sym(g_tmp);
    float* o1 = (float*)sym(g_out1);
    float* gm = (float*)sym(g_m);
    float* gil = (float*)sym(g_il);
    bf *xb = (bf*)sym(g_xb);
    bf *wq = (bf*)sym(g_wq), *wk = (bf*)sym(g_wk), *wv = (bf*)sym(g_wv), *wo = (bf*)sym(g_wo);
    bf *q = (bf*)sym(g_q), *k = (bf*)sym(g_k), *v = (bf*)sym(g_v);
    bf *oc = (bf*)sym(g_oc);
    hf *w1f = (hf*)sym(g_w1f), *w2f = (hf*)sym(g_w2f);
    hf *o1f = (hf*)sym(g_o1f), *fhf = (hf*)sym(g_fhf);

    const long TD  = (long)TT * DD;
    const long HD  = (long)DD * DKK;
    const long HT  = (long)TT * DKK;
    const long BHT = (long)HH * HT;

    // BK=64 smem budgets (all need >48KB opt-in; all fit 2 CTAs/SM)
    constexpr int SM_B64  = (128 * 72 + 64 * 72) * 2 * 2;            // 55296
    constexpr int SM_B128 = (128 * 72 + 64 * 136) * 2 * 2;           // 71680
    constexpr int SM_H    = SM_B128;                                 // 71680
    constexpr int SM_AT1  = 3 * (128 * 72) * 2;                      // 55296
    constexpr int SM_AT2  = (128 * 72 + 2 * (2 * 128 * 72 + 512)) * 2;  // 94208
    cudaFuncSetAttribute(bgemm<64, false>,
                         cudaFuncAttributeMaxDynamicSharedMemorySize, SM_B64);
    cudaFuncSetAttribute(bgemm<128, true>,
                         cudaFuncAttributeMaxDynamicSharedMemorySize, SM_B128);
    cudaFuncSetAttribute(hgemm<true, true, false>,
                         cudaFuncAttributeMaxDynamicSharedMemorySize, SM_H);
    cudaFuncSetAttribute(hgemm<true, false, true>,
                         cudaFuncAttributeMaxDynamicSharedMemorySize, SM_H);
    cudaFuncSetAttribute(attn_stats_kernel,
                         cudaFuncAttributeMaxDynamicSharedMemorySize, SM_AT1);
    cudaFuncSetAttribute(attn_out_kernel,
                         cudaFuncAttributeMaxDynamicSharedMemorySize, SM_AT2);

    // 0) one fused conversion launch (x, Wq, Wk, Wv, Wo -> bf16; W1, W2 -> fp16)
    {
        const long total4 = ((long)BB * TT * DD + 3 * (long)HH * DD * DKK +
                             (long)DD * DD + 2 * (long)DD * FFF) / 4;
        cvt_all_kernel<<<(unsigned)((total4 + 255) / 256), 256>>>(
            (const float4*)x, (const float4*)Wq, (const float4*)Wk,
            (const float4*)Wv, (const float4*)Wo, (const float4*)W1,
            (const float4*)W2,
            (uint2*)xb, (uint2*)wq, (uint2*)wk, (uint2*)wv, (uint2*)wo,
            (uint2*)w1f, (uint2*)w2f);
    }

    // 1) Q,K,V projections (plain bf16, BK=64)
    dim3 gproj(1, TT / 128, BB * HH);
    bgemm<64, false><<<gproj, 256, SM_B64>>>(xb, wq, nullptr, q,
        DD, DD, DKK, DKK, TD, 0, 0, HD, BHT, HT, HH);
    bgemm<64, false><<<gproj, 256, SM_B64>>>(xb, wk, nullptr, k,
        DD, DD, DKK, DKK, TD, 0, 0, HD, BHT, HT, HH);
    bgemm<64, false><<<gproj, 256, SM_B64>>>(xb, wv, nullptr, v,
        DD, DD, DKK, DKK, TD, 0, 0, HD, BHT, HT, HH);

    // 2) fused attention
    dim3 gat(TT / 128, BB * HH);
    attn_stats_kernel<<<gat, 256, SM_AT1>>>(q, k, gm, gil);
    attn_out_kernel<<<gat, 256, SM_AT2>>>(q, k, v, gm, gil, oc);

    // 3) tmp = ocat @ Wo (plain bf16, BK=64)
    dim3 gwo(DD / 128, (BB * TT) / 128, 1);
    bgemm<128, true><<<gwo, 256, SM_B128>>>(oc, wo, tp, nullptr,
        DD, DD, DD, DD, 0, 0, 0, 0, 0, 0, 1);

    // 4) out1 = norm(tmp + x), plus fp16 copy for FFN
    add_norm_kernel<true><<<BB * TT, 256>>>(tp, x, o1, o1f);

    // 5) ffh = relu(out1 @ W1 + b1) (fp16, 1 MMA, BK=64)
    dim3 gf1(FFF / 128, (BB * TT) / 128, 1);
    hgemm<true, true, false><<<gf1, 256, SM_H>>>(
        o1f, w1f, nullptr, fhf, b1, DD, DD, FFF, FFF);

    // 6) tmp = ffh @ W2 + b2 (fp16, 1 MMA, BK=64)
    dim3 gf2(DD / 128, (BB * TT) / 128, 1);
    hgemm<true, false, true><<<gf2, 256, SM_H>>>(
        fhf, w2f, tp, nullptr, b2, FFF, FFF, DD, DD);

    // 7) out = norm(tmp + out1)
    add_norm_kernel<false><<<BB * TT, 256>>>(tp, o1, out, nullptr);
}

// round 13
// speedup vs baseline: 10.5796x; 1.0644x over previous
#include <cuda_runtime.h>
#include <cuda_bf16.h>
#include <cuda_fp16.h>
#include <cstdint>

#define BB 2
#define TT 2048
#define DD 1024
#define HH 16
#define DKK 64
#define FFF 4096

using bf = __nv_bfloat16;
using hf = __half;

// ---------------- scratch (static device memory; no allocs) ----------------
__device__ __align__(256) float g_tmp[(size_t)BB * TT * DD];
__device__ __align__(256) float g_out1[(size_t)BB * TT * DD];
__device__ __align__(256) float g_m[(size_t)BB * HH * TT];
__device__ __align__(256) float g_il[(size_t)BB * HH * TT];

__device__ __align__(256) bf g_xb[(size_t)BB * TT * DD];
__device__ __align__(256) bf g_wcat[(size_t)DD * 3 * HH * DKK];   // [D, 3072]
__device__ __align__(256) bf g_wo[(size_t)DD * DD];
__device__ __align__(256) bf g_q[(size_t)BB * HH * TT * DKK];
__device__ __align__(256) bf g_k[(size_t)BB * HH * TT * DKK];
__device__ __align__(256) bf g_v[(size_t)BB * HH * TT * DKK];
__device__ __align__(256) bf g_oc[(size_t)BB * TT * DD];

__device__ __align__(256) hf g_w1f[(size_t)DD * FFF];
__device__ __align__(256) hf g_w2f[(size_t)FFF * DD];
__device__ __align__(256) hf g_o1f[(size_t)BB * TT * DD];
__device__ __align__(256) hf g_fhf[(size_t)BB * TT * FFF];

// ---------------- small helpers -------------------------------------------
__device__ __forceinline__ uint32_t smaddr(const void* p) {
    return (uint32_t)__cvta_generic_to_shared(p);
}
__device__ __forceinline__ void cpa16(uint32_t s, const void* g) {
    asm volatile("cp.async.cg.shared.global [%0], [%1], 16;\n" :: "r"(s), "l"(g));
}
__device__ __forceinline__ void cp_commit() {
    asm volatile("cp.async.commit_group;\n" ::: "memory");
}
__device__ __forceinline__ void cp_wait1() {
    asm volatile("cp.async.wait_group 1;\n" ::: "memory");
}
__device__ __forceinline__ void cp_wait0() {
    asm volatile("cp.async.wait_group 0;\n" ::: "memory");
}
__device__ __forceinline__ void ldsm4(uint32_t& r0, uint32_t& r1, uint32_t& r2, uint32_t& r3, uint32_t a) {
    asm volatile("ldmatrix.sync.aligned.m8n8.x4.shared.b16 {%0,%1,%2,%3}, [%4];\n"
                 : "=r"(r0), "=r"(r1), "=r"(r2), "=r"(r3) : "r"(a));
}
__device__ __forceinline__ void ldsm4t(uint32_t& r0, uint32_t& r1, uint32_t& r2, uint32_t& r3, uint32_t a) {
    asm volatile("ldmatrix.sync.aligned.m8n8.x4.trans.shared.b16 {%0,%1,%2,%3}, [%4];\n"
                 : "=r"(r0), "=r"(r1), "=r"(r2), "=r"(r3) : "r"(a));
}
__device__ __forceinline__ void mma16816(float* d, const uint32_t* a, uint32_t b0, uint32_t b1) {
    asm volatile(
        "mma.sync.aligned.m16n8k16.row.col.f32.bf16.bf16.f32 "
        "{%0,%1,%2,%3}, {%4,%5,%6,%7}, {%8,%9}, {%0,%1,%2,%3};\n"
        : "+f"(d[0]), "+f"(d[1]), "+f"(d[2]), "+f"(d[3])
        : "r"(a[0]), "r"(a[1]), "r"(a[2]), "r"(a[3]), "r"(b0), "r"(b1));
}
__device__ __forceinline__ void mma16816h(float* d, const uint32_t* a, uint32_t b0, uint32_t b1) {
    asm volatile(
        "mma.sync.aligned.m16n8k16.row.col.f32.f16.f16.f32 "
        "{%0,%1,%2,%3}, {%4,%5,%6,%7}, {%8,%9}, {%0,%1,%2,%3};\n"
        : "+f"(d[0]), "+f"(d[1]), "+f"(d[2]), "+f"(d[3])
        : "r"(a[0]), "r"(a[1]), "r"(a[2]), "r"(a[3]), "r"(b0), "r"(b1));
}
__device__ __forceinline__ uint32_t pack2(bf a, bf b) {
    __nv_bfloat162 p; p.x = a; p.y = b;
    return *(uint32_t*)&p;
}
__device__ __forceinline__ uint32_t pack2h(hf a, hf b) {
    __half2 p; p.x = a; p.y = b;
    return *(uint32_t*)&p;
}

// ---------------- fused QKV GEMM ------------------------------------------
// C = xb[4096,1024] @ wcat[1024,3072]; epilogue scatters to q/k/v
// (B,H,T,64) layout. BM=128, BN=128, BK=64, 2 CTAs/SM.
__global__ __launch_bounds__(256, 2)
void qkv_gemm(const bf* __restrict__ A, const bf* __restrict__ B,
              bf* __restrict__ q_, bf* __restrict__ k_, bf* __restrict__ v_)
{
    constexpr int BM = 128, BN = 128, BK = 64, AP = 72, BP = BN + 8;
    constexpr int AE = BM * AP, BE = BK * BP, STG = AE + BE;
    constexpr int lda = DD, ldb = 3 * HH * DKK;   // 1024, 3072
    extern __shared__ bf sm[];

    int tid = threadIdx.x, lane = tid & 31, wid = tid >> 5;
    constexpr int MF = 4, NF = 4;
    int wm = wid >> 2, wn = wid & 3;
    int m0 = wm * MF * 16, n0 = wn * 32;

    long bm = (long)blockIdx.y * BM, bn = (long)blockIdx.x * BN;

    float acc[MF][NF][4] = {};

    auto copyStage = [&](int kt, int s) {
        int k0 = kt * BK;
        bf* sa = sm + (size_t)s * STG;
        bf* sb = sa + AE;
        #pragma unroll
        for (int i = 0; i < 4; i++) {
            int c = tid + i * 256;
            int r = c >> 3, cc = (c & 7) * 8;
            cpa16(smaddr(sa + r * AP + cc), A + (bm + r) * (long)lda + k0 + cc);
        }
        #pragma unroll
        for (int i = 0; i < 4; i++) {
            int c = tid + i * 256;
            int r = c >> 4, cc = (c & 15) * 8;
            cpa16(smaddr(sb + r * BP + cc), B + (long)(k0 + r) * ldb + bn + cc);
        }
        cp_commit();
    };

    auto compute = [&](int s) {
        const bf* sa = sm + (size_t)s * STG;
        const bf* sb = sa + AE;
        #pragma unroll
        for (int kk = 0; kk < BK; kk += 16) {
            uint32_t b2[NF][2];
            #pragma unroll
            for (int g = 0; g < 2; g++) {
                int rowk = kk + (lane & 7) + ((lane >> 3) & 1) * 8;
                int coln = n0 + g * 16 + (lane >> 4) * 8;
                ldsm4t(b2[2*g][0], b2[2*g][1], b2[2*g+1][0], b2[2*g+1][1],
                       smaddr(sb + rowk * BP + coln));
            }
            #pragma unroll
            for (int mf = 0; mf < MF; mf++) {
                uint32_t a[4];
                int row = m0 + mf * 16 + (lane & 15);
                int col = kk + (lane >> 4) * 8;
                ldsm4(a[0], a[1], a[2], a[3], smaddr(sa + row * AP + col));
                #pragma unroll
                for (int nf = 0; nf < NF; nf++)
                    mma16816(acc[mf][nf], a, b2[nf][0], b2[nf][1]);
            }
        }
    };

    constexpr int nk = DD / BK;   // 16
    copyStage(0, 0);
    for (int kt = 0; kt < nk; kt++) {
        if (kt + 1 < nk) { copyStage(kt + 1, (kt + 1) & 1); cp_wait1(); }
        else             { cp_wait0(); }
        __syncthreads();
        compute(kt & 1);
        __syncthreads();
    }

    // which is uniform per block: bn multiple of 128, 1024 cols per which
    int which = (int)(bn >> 10);
    bf* dst = (which == 0) ? q_ : (which == 1) ? k_ : v_;

    #pragma unroll
    for (int mf = 0; mf < MF; mf++) {
        #pragma unroll
        for (int nf = 0; nf < NF; nf++) {
            long r0 = bm + m0 + mf * 16 + (lane >> 2);
            long r1 = r0 + 8;
            int  c  = (int)(bn + n0 + nf * 8 + (lane & 3) * 2);
            int  h  = (c >> 6) & 15;
            int  j  = c & 63;
            long b  = r0 >> 11;
            long t0 = r0 & 2047, t1 = r1 & 2047;
            long base = ((b * HH + h) * (long)TT) * DKK + j;
            *(uint32_t*)&dst[base + t0 * DKK] =
                pack2(__float2bfloat16(acc[mf][nf][0]), __float2bfloat16(acc[mf][nf][1]));
            *(uint32_t*)&dst[base + t1 * DKK] =
                pack2(__float2bfloat16(acc[mf][nf][2]), __float2bfloat16(acc[mf][nf][3]));
        }
    }
}

// ---------------- plain-bf16 tensor-core GEMM (Wo) -------------------------
template <int BN, bool OF32>
__global__ __launch_bounds__(256, 2)
void bgemm(const bf* __restrict__ A, const bf* __restrict__ B,
           float* __restrict__ C, bf* __restrict__ Cb,
           int K, int lda, int ldb, int ldc,
           long soA, long siA, long soB, long siB, long soC, long siC, int inner)
{
    constexpr int BM = 128, BK = 64, AP = 72, BP = BN + 8;
    constexpr int AE = BM * AP, BE = BK * BP, STG = AE + BE;
    extern __shared__ bf sm[];

    int z = blockIdx.z;
    int zo = z / inner, zi = z - zo * inner;
    A += zo * soA + zi * siA;
    B += zo * soB + zi * siB;
    long coff = zo * soC + zi * siC;

    int tid = threadIdx.x, lane = tid & 31, wid = tid >> 5;
    constexpr int MF = (BN == 128) ? 4 : 2;
    constexpr int NF = 4;
    int wm = (BN == 128) ? (wid >> 2) : (wid >> 1);
    int wn = (BN == 128) ? (wid & 3) : (wid & 1);
    int m0 = wm * MF * 16, n0 = wn * 32;

    long bm = (long)blockIdx.y * BM, bn = (long)blockIdx.x * BN;

    float acc[MF][NF][4] = {};

    auto copyStage = [&](int kt, int s) {
        int k0 = kt * BK;
        bf* sa = sm + (size_t)s * STG;
        bf* sb = sa + AE;
        #pragma unroll
        for (int i = 0; i < 4; i++) {
            int c = tid + i * 256;
            int r = c >> 3, cc = (c & 7) * 8;
            cpa16(smaddr(sa + r * AP + cc), A + (bm + r) * (long)lda + k0 + cc);
        }
        constexpr int CPR = BN / 8;
        #pragma unroll
        for (int i = 0; i < (64 * CPR) / 256; i++) {
            int c = tid + i * 256;
            int r = c / CPR, cc = (c % CPR) * 8;
            cpa16(smaddr(sb + r * BP + cc), B + (long)(k0 + r) * ldb + bn + cc);
        }
        cp_commit();
    };

    auto compute = [&](int s) {
        const bf* sa = sm + (size_t)s * STG;
        const bf* sb = sa + AE;
        #pragma unroll
        for (int kk = 0; kk < BK; kk += 16) {
            uint32_t b2[NF][2];
            #pragma unroll
            for (int g = 0; g < 2; g++) {
                int rowk = kk + (lane & 7) + ((lane >> 3) & 1) * 8;
                int coln = n0 + g * 16 + (lane >> 4) * 8;
                ldsm4t(b2[2*g][0], b2[2*g][1], b2[2*g+1][0], b2[2*g+1][1],
                       smaddr(sb + rowk * BP + coln));
            }
            #pragma unroll
            for (int mf = 0; mf < MF; mf++) {
                uint32_t a[4];
                int row = m0 + mf * 16 + (lane & 15);
                int col = kk + (lane >> 4) * 8;
                ldsm4(a[0], a[1], a[2], a[3], smaddr(sa + row * AP + col));
                #pragma unroll
                for (int nf = 0; nf < NF; nf++)
                    mma16816(acc[mf][nf], a, b2[nf][0], b2[nf][1]);
            }
        }
    };

    int nk = K / BK;
    copyStage(0, 0);
    for (int kt = 0; kt < nk; kt++) {
        if (kt + 1 < nk) { copyStage(kt + 1, (kt + 1) & 1); cp_wait1(); }
        else             { cp_wait0(); }
        __syncthreads();
        compute(kt & 1);
        __syncthreads();
    }

    #pragma unroll
    for (int mf = 0; mf < MF; mf++) {
        #pragma unroll
        for (int nf = 0; nf < NF; nf++) {
            long r0 = bm + m0 + mf * 16 + (lane >> 2);
            long r1 = r0 + 8;
            long c  = bn + n0 + nf * 8 + (lane & 3) * 2;
            if constexpr (OF32) {
                float2 p0 = {acc[mf][nf][0], acc[mf][nf][1]};
                float2 p1 = {acc[mf][nf][2], acc[mf][nf][3]};
                *(float2*)&C[coff + r0 * ldc + c] = p0;
                *(float2*)&C[coff + r1 * ldc + c] = p1;
            } else {
                *(uint32_t*)&Cb[coff + r0 * ldc + c] =
                    pack2(__float2bfloat16(acc[mf][nf][0]), __float2bfloat16(acc[mf][nf][1]));
                *(uint32_t*)&Cb[coff + r1 * ldc + c] =
                    pack2(__float2bfloat16(acc[mf][nf][2]), __float2bfloat16(acc[mf][nf][3]));
            }
        }
    }
}

// ---------------- fp16 tensor-core GEMM (FFN path, 1 MMA, BK=64) -----------
template <bool BIAS, bool RELU, bool OF32>
__global__ __launch_bounds__(256, 2)
void hgemm(const hf* __restrict__ A, const hf* __restrict__ B,
           float* __restrict__ C, hf* __restrict__ Ch,
           const float* __restrict__ bias,
           int K, int lda, int ldb, int ldc)
{
    constexpr int BM = 128, BN = 128, BK = 64, AP = 72, BP = BN + 8;
    constexpr int AE = BM * AP, BE = BK * BP, STG = AE + BE;
    extern __shared__ hf smh[];

    int tid = threadIdx.x, lane = tid & 31, wid = tid >> 5;
    constexpr int MF = 4, NF = 4;
    int wm = wid >> 2, wn = wid & 3;
    int m0 = wm * MF * 16, n0 = wn * 32;

    long bm = (long)blockIdx.y * BM, bn = (long)blockIdx.x * BN;

    float acc[MF][NF][4] = {};

    auto copyStage = [&](int kt, int s) {
        int k0 = kt * BK;
        hf* sa = smh + (size_t)s * STG;
        hf* sb = sa + AE;
        #pragma unroll
        for (int i = 0; i < 4; i++) {
            int c = tid + i * 256;
            int r = c >> 3, cc = (c & 7) * 8;
            cpa16(smaddr(sa + r * AP + cc), A + (bm + r) * (long)lda + k0 + cc);
        }
        #pragma unroll
        for (int i = 0; i < 4; i++) {
            int c = tid + i * 256;
            int r = c >> 4, cc = (c & 15) * 8;
            cpa16(smaddr(sb + r * BP + cc), B + (long)(k0 + r) * ldb + bn + cc);
        }
        cp_commit();
    };

    auto compute = [&](int s) {
        const hf* sa = smh + (size_t)s * STG;
        const hf* sb = sa + AE;
        #pragma unroll
        for (int kk = 0; kk < BK; kk += 16) {
            uint32_t b2[NF][2];
            #pragma unroll
            for (int g = 0; g < 2; g++) {
                int rowk = kk + (lane & 7) + ((lane >> 3) & 1) * 8;
                int coln = n0 + g * 16 + (lane >> 4) * 8;
                ldsm4t(b2[2*g][0], b2[2*g][1], b2[2*g+1][0], b2[2*g+1][1],
                       smaddr(sb + rowk * BP + coln));
            }
            #pragma unroll
            for (int mf = 0; mf < MF; mf++) {
                uint32_t a[4];
                int row = m0 + mf * 16 + (lane & 15);
                int col = kk + (lane >> 4) * 8;
                ldsm4(a[0], a[1], a[2], a[3], smaddr(sa + row * AP + col));
                #pragma unroll
                for (int nf = 0; nf < NF; nf++)
                    mma16816h(acc[mf][nf], a, b2[nf][0], b2[nf][1]);
            }
        }
    };

    int nk = K / BK;
    copyStage(0, 0);
    for (int kt = 0; kt < nk; kt++) {
        if (kt + 1 < nk) { copyStage(kt + 1, (kt + 1) & 1); cp_wait1(); }
        else             { cp_wait0(); }
        __syncthreads();
        compute(kt & 1);
        __syncthreads();
    }

    #pragma unroll
    for (int mf = 0; mf < MF; mf++) {
        #pragma unroll
        for (int nf = 0; nf < NF; nf++) {
            long r0 = bm + m0 + mf * 16 + (lane >> 2);
            long r1 = r0 + 8;
            long c  = bn + n0 + nf * 8 + (lane & 3) * 2;
            float v00 = acc[mf][nf][0];
            float v01 = acc[mf][nf][1];
            float v10 = acc[mf][nf][2];
            float v11 = acc[mf][nf][3];
            if constexpr (BIAS) {
                float b0v = bias[c], b1v = bias[c + 1];
                v00 += b0v; v01 += b1v; v10 += b0v; v11 += b1v;
            }
            if constexpr (RELU) {
                v00 = fmaxf(v00, 0.f); v01 = fmaxf(v01, 0.f);
                v10 = fmaxf(v10, 0.f); v11 = fmaxf(v11, 0.f);
            }
            if constexpr (OF32) {
                float2 p0 = {v00, v01}, p1 = {v10, v11};
                *(float2*)&C[r0 * ldc + c] = p0;
                *(float2*)&C[r1 * ldc + c] = p1;
            } else {
                *(uint32_t*)&Ch[r0 * ldc + c] = pack2h(__float2half_rn(v00), __float2half_rn(v01));
                *(uint32_t*)&Ch[r1 * ldc + c] = pack2h(__float2half_rn(v10), __float2half_rn(v11));
            }
        }
    }
}

// ---------------- fused attention pass 1: column-softmax stats --------------
__global__ __launch_bounds__(256, 2)
void attn_stats_kernel(const bf* __restrict__ q_, const bf* __restrict__ k_,
                       float* __restrict__ gm, float* __restrict__ gil)
{
    constexpr int P = 72, TILE = 128 * P;
    extern __shared__ bf sm[];
    bf* sk = sm;

    int bh = blockIdx.y;
    int s0 = blockIdx.x * 128;
    long base = (long)bh * TT * DKK;
    const bf* Kp = k_ + base + (long)s0 * DKK;
    const bf* Qp = q_ + base;

    int tid = threadIdx.x, lane = tid & 31, wid = tid >> 5;
    int m0 = wid * 16;

    auto loadQ = [&](int ch, int s) {
        bf* dq = sm + TILE + (size_t)s * TILE;
        long q0 = (long)ch * 128;
        #pragma unroll
        for (int i = 0; i < 4; i++) {
            int c = tid + i * 256;
            int r = c >> 3, c8 = (c & 7) * 8;
            cpa16(smaddr(dq + r * P + c8), Qp + (q0 + r) * DKK + c8);
        }
    };

    #pragma unroll
    for (int i = 0; i < 4; i++) {
        int c = tid + i * 256;
        int r = c >> 3, c8 = (c & 7) * 8;
        cpa16(smaddr(sk + r * P + c8), Kp + (long)r * DKK + c8);
    }
    loadQ(0, 0);
    cp_commit();

    float mrow0 = -1e30f, mrow1 = -1e30f;
    float lrow0 = 0.f, lrow1 = 0.f;

    for (int ch = 0; ch < 16; ch++) {
        if (ch + 1 < 16) { loadQ(ch + 1, (ch + 1) & 1); cp_commit(); cp_wait1(); }
        else             { cp_wait0(); }
        __syncthreads();
        const bf* sq = sm + TILE + (size_t)(ch & 1) * TILE;

        float acc[16][4] = {};
        #pragma unroll
        for (int kk = 0; kk < 64; kk += 16) {
            uint32_t a[4];
            {
                int row = m0 + (lane & 15);
                int col = kk + (lane >> 4) * 8;
                ldsm4(a[0], a[1], a[2], a[3], smaddr(sk + row * P + col));
            }
            #pragma unroll
            for (int g = 0; g < 8; g++) {
                int rown = g * 16 + (lane & 7) + ((lane >> 4) & 1) * 8;
                int col = kk + ((lane >> 3) & 1) * 8;
                uint32_t b0, b1, b2, b3;
                ldsm4(b0, b1, b2, b3, smaddr(sq + rown * P + col));
                mma16816(acc[2*g],   a, b0, b1);
                mma16816(acc[2*g+1], a, b2, b3);
            }
        }
        __syncthreads();

        float cm0 = -1e30f, cm1 = -1e30f;
        #pragma unroll
        for (int nf = 0; nf < 16; nf++) {
            cm0 = fmaxf(cm0, fmaxf(acc[nf][0], acc[nf][1]));
            cm1 = fmaxf(cm1, fmaxf(acc[nf][2], acc[nf][3]));
        }
        cm0 *= 0.125f; cm1 *= 0.125f;
        cm0 = fmaxf(cm0, __shfl_xor_sync(~0u, cm0, 1));
        cm0 = fmaxf(cm0, __shfl_xor_sync(~0u, cm0, 2));
        cm1 = fmaxf(cm1, __shfl_xor_sync(~0u, cm1, 1));
        cm1 = fmaxf(cm1, __shfl_xor_sync(~0u, cm1, 2));
        float mn0 = fmaxf(mrow0, cm0), mn1 = fmaxf(mrow1, cm1);
        float sv0 = 0.f, sv1 = 0.f;
        #pragma unroll
        for (int nf = 0; nf < 16; nf++) {
            sv0 += __expf(acc[nf][0] * 0.125f - mn0) + __expf(acc[nf][1] * 0.125f - mn0);
            sv1 += __expf(acc[nf][2] * 0.125f - mn1) + __expf(acc[nf][3] * 0.125f - mn1);
        }
        sv0 += __shfl_xor_sync(~0u, sv0, 1); sv0 += __shfl_xor_sync(~0u, sv0, 2);
        sv1 += __shfl_xor_sync(~0u, sv1, 1); sv1 += __shfl_xor_sync(~0u, sv1, 2);
        lrow0 = lrow0 * __expf(mrow0 - mn0) + sv0;
        lrow1 = lrow1 * __expf(mrow1 - mn1) + sv1;
        mrow0 = mn0; mrow1 = mn1;
    }

    if ((lane & 3) == 0) {
        int r = lane >> 2;
        long o = (long)bh * TT + s0 + m0;
        gm[o + r]      = mrow0;
        gm[o + r + 8]  = mrow1;
        gil[o + r]     = 1.f / lrow0;
        gil[o + r + 8] = 1.f / lrow1;
    }
}

// ---------------- fused attention pass 2: output ----------------------------
__global__ __launch_bounds__(256, 2)
void attn_out_kernel(const bf* __restrict__ q_, const bf* __restrict__ k_,
                     const bf* __restrict__ v_,
                     const float* __restrict__ gm, const float* __restrict__ gil,
                     bf* __restrict__ oc)
{
    constexpr int P = 72, TILE = 128 * P;
    constexpr int STG = 2 * TILE + 512;
    extern __shared__ bf sm[];
    bf* sq = sm;

    int bh = blockIdx.y;
    int q0b = blockIdx.x * 128;
    int b = bh >> 4, h = bh & 15;
    long base = (long)bh * TT * DKK;
    const bf* Qp = q_ + base + (long)q0b * DKK;
    const bf* Kp = k_ + base;
    const bf* Vp = v_ + base;
    const float* Gm = gm + (long)bh * TT;
    const float* Gil = gil + (long)bh * TT;

    int tid = threadIdx.x, lane = tid & 31, wid = tid >> 5;
    int m0 = wid * 16;

    auto loadKV = [&](int ch, int s) {
        bf* st = sm + TILE + (size_t)s * STG;
        bf* dk = st;
        bf* dv = st + TILE;
        float* dml = (float*)(st + 2 * TILE);
        long r0 = (long)ch * 128;
        #pragma unroll
        for (int i = 0; i < 4; i++) {
            int c = tid + i * 256;
            int r = c >> 3, c8 = (c & 7) * 8;
            long go = (r0 + r) * DKK + c8;
            cpa16(smaddr(dk + r * P + c8), Kp + go);
            cpa16(smaddr(dv + r * P + c8), Vp + go);
        }
        if (tid < 32)      cpa16(smaddr(dml + tid * 4),          Gm  + r0 + tid * 4);
        else if (tid < 64) cpa16(smaddr(dml + 128 + (tid-32)*4), Gil + r0 + (tid - 32) * 4);
    };

    #pragma unroll
    for (int i = 0; i < 4; i++) {
        int c = tid + i * 256;
        int r = c >> 3, c8 = (c & 7) * 8;
        cpa16(smaddr(sq + r * P + c8), Qp + (long)r * DKK + c8);
    }
    loadKV(0, 0);
    cp_commit();

    float acc_o[8][4] = {};

    for (int ch = 0; ch < 16; ch++) {
        if (ch + 1 < 16) { loadKV(ch + 1, (ch + 1) & 1); cp_commit(); cp_wait1(); }
        else             { cp_wait0(); }
        __syncthreads();
        bf* st = sm + TILE + (size_t)(ch & 1) * STG;
        const bf* sk = st;
        const bf* sv = st + TILE;
        const float* sml = (const float*)(st + 2 * TILE);

        #pragma unroll
        for (int half = 0; half < 2; half++) {
            float acc8[8][4] = {};
            #pragma unroll
            for (int kk = 0; kk < 64; kk += 16) {
                uint32_t a[4];
                {
                    int row = m0 + (lane & 15);
                    int col = kk + (lane >> 4) * 8;
                    ldsm4(a[0], a[1], a[2], a[3], smaddr(sq + row * P + col));
                }
                #pragma unroll
                for (int g = 0; g < 4; g++) {
                    int rown = half * 64 + g * 16 + (lane & 7) + ((lane >> 4) & 1) * 8;
                    int col = kk + ((lane >> 3) & 1) * 8;
                    uint32_t b0, b1, b2, b3;
                    ldsm4(b0, b1, b2, b3, smaddr(sk + rown * P + col));
                    mma16816(acc8[2*g],   a, b0, b1);
                    mma16816(acc8[2*g+1], a, b2, b3);
                }
            }

            #pragma unroll
            for (int j = 0; j < 4; j++) {
                int cL = half * 64 + j * 16 + (lane & 3) * 2;
                int cH = cL + 8;
                float mL0 = sml[cL],       mL1 = sml[cL + 1];
                float mH0 = sml[cH],       mH1 = sml[cH + 1];
                float iL0 = sml[128 + cL], iL1 = sml[128 + cL + 1];
                float iH0 = sml[128 + cH], iH1 = sml[128 + cH + 1];

                float p00 = __expf(acc8[2*j][0]   * 0.125f - mL0) * iL0;
                float p01 = __expf(acc8[2*j][1]   * 0.125f - mL1) * iL1;
                float p10 = __expf(acc8[2*j][2]   * 0.125f - mL0) * iL0;
                float p11 = __expf(acc8[2*j][3]   * 0.125f - mL1) * iL1;
                float q00 = __expf(acc8[2*j+1][0] * 0.125f - mH0) * iH0;
                float q01 = __expf(acc8[2*j+1][1] * 0.125f - mH1) * iH1;
                float q10 = __expf(acc8[2*j+1][2] * 0.125f - mH0) * iH0;
                float q11 = __expf(acc8[2*j+1][3] * 0.125f - mH1) * iH1;

                uint32_t pa[4];
                pa[0] = pack2(__float2bfloat16(p00), __float2bfloat16(p01));
                pa[1] = pack2(__float2bfloat16(p10), __float2bfloat16(p11));
                pa[2] = pack2(__float2bfloat16(q00), __float2bfloat16(q01));
                pa[3] = pack2(__float2bfloat16(q10), __float2bfloat16(q11));

                #pragma unroll
                for (int g2 = 0; g2 < 4; g2++) {
                    int rowk = half * 64 + j * 16 + (lane & 7) + ((lane >> 3) & 1) * 8;
                    int coln = g2 * 16 + (lane >> 4) * 8;
                    uint32_t b0, b1, b2, b3;
                    ldsm4t(b0, b1, b2, b3, smaddr(sv + rowk * P + coln));
                    mma16816(acc_o[2*g2],   pa, b0, b1);
                    mma16816(acc_o[2*g2+1], pa, b2, b3);
                }
            }
        }
        __syncthreads();
    }

    #pragma unroll
    for (int nf = 0; nf < 8; nf++) {
        long r0 = (long)b * TT + q0b + m0 + (lane >> 2);
        long r1 = r0 + 8;
        long c = (long)h * 64 + nf * 8 + (lane & 3) * 2;
        *(uint32_t*)&oc[r0 * DD + c] =
            pack2(__float2bfloat16(acc_o[nf][0]), __float2bfloat16(acc_o[nf][1]));
        *(uint32_t*)&oc[r1 * DD + c] =
            pack2(__float2bfloat16(acc_o[nf][2]), __float2bfloat16(acc_o[nf][3]));
    }
}

// ---------------- fused conversion: all tensors in one launch --------------
// x -> bf16; Wq/Wk/Wv -> wcat[D,3072] (which-major) bf16; Wo -> bf16;
// W1, W2 -> fp16.
__global__ void cvt_all_kernel(
    const float4* __restrict__ x,  const float4* __restrict__ wq,
    const float4* __restrict__ wk, const float4* __restrict__ wv,
    const float4* __restrict__ wo, const float4* __restrict__ w1,
    const float4* __restrict__ w2,
    uint2* __restrict__ xb, uint2* __restrict__ wcat, uint2* __restrict__ wob,
    uint2* __restrict__ w1f, uint2* __restrict__ w2f)
{
    const long N_X  = (long)BB * TT * DD / 4;
    const long N_W  = (long)HH * DD * DKK / 4;      // 262144
    const long N_WO = (long)DD * DD / 4;
    const long N_F  = (long)DD * FFF / 4;
    const long b0 = N_X, b1 = b0 + N_W, b2 = b1 + N_W, b3 = b2 + N_W;
    const long b4 = b3 + N_WO, b5 = b4 + N_F, b6 = b5 + N_F;

    long i = (long)blockIdx.x * blockDim.x + threadIdx.x;
    if (i >= b6) return;

    if (i < b0) {
        float4 v = x[i];
        uint2 o;
        o.x = pack2(__float2bfloat16(v.x), __float2bfloat16(v.y));
        o.y = pack2(__float2bfloat16(v.z), __float2bfloat16(v.w));
        xb[i] = o;
    } else if (i < b3) {
        // Wq/Wk/Wv element range: off in [0, N_W); src layout [H][D][64]
        int which;
        const float4* src;
        long off;
        if (i < b1)      { which = 0; src = wq; off = i - b0; }
        else if (i < b2) { which = 1; src = wk; off = i - b1; }
        else             { which = 2; src = wv; off = i - b2; }
        float4 v = src[off];
        // 4*off = h*(D*64) + d*64 + j ; off units of 4 elems
        long h = off >> 14;               // off / 16384
        long rem = off & 16383;
        long d = rem >> 4;                // rem / 16
        long j = (rem & 15) * 4;
        long dstCol = (long)which * 1024 + h * 64 + j;   // [0,3072)
        uint2 o;
        o.x = pack2(__float2bfloat16(v.x), __float2bfloat16(v.y));
        o.y = pack2(__float2bfloat16(v.z), __float2bfloat16(v.w));
        wcat[(d * 3072 + dstCol) >> 2] = o;
    } else if (i < b4) {
        long off = i - b3;
        float4 v = wo[off];
        uint2 o;
        o.x = pack2(__float2bfloat16(v.x), __float2bfloat16(v.y));
        o.y = pack2(__float2bfloat16(v.z), __float2bfloat16(v.w));
        wob[off] = o;
    } else {
        const float4* src = (i < b5) ? w1 : w2;
        uint2* dst = (i < b5) ? w1f : w2f;
        long off = (i < b5) ? (i - b4) : (i - b5);
        float4 v = src[off];
        uint2 o;
        o.x = pack2h(__float2half_rn(v.x), __float2half_rn(v.y));
        o.y = pack2h(__float2half_rn(v.z), __float2half_rn(v.w));
        dst[off] = o;
    }
}

// --------- out = meanstd_norm(a + b); optional fp16 copy --------------------
template <bool WHALF>
__global__ void add_norm_kernel(const float* __restrict__ a, const float* __restrict__ b,
                                float* __restrict__ out, hf* __restrict__ oh)
{
    const int D = DD;
    long r = blockIdx.x;
    const float* pa = a + r * D;
    const float* pb = b + r * D;
    int tid = threadIdx.x;

    float y[4];
    float sum = 0.f;
    #pragma unroll
    for (int i = 0; i < 4; i++) {
        y[i] = pa[tid + i * 256] + pb[tid + i * 256];
        sum += y[i];
    }

    __shared__ float red[8];
    #pragma unroll
    for (int o = 16; o > 0; o >>= 1) sum += __shfl_xor_sync(~0u, sum, o);
    if ((tid & 31) == 0) red[tid >> 5] = sum;
    __syncthreads();
    if (tid < 32) {
        float v = (tid < 8) ? red[tid] : 0.f;
        #pragma unroll
        for (int o = 4; o > 0; o >>= 1) v += __shfl_xor_sync(~0u, v, o);
        if (tid == 0) red[0] = v;
    }
    __syncthreads();
    float mean = red[0] / D;
    __syncthreads();

    float vs = 0.f;
    #pragma unroll
    for (int i = 0; i < 4; i++) {
        float d = y[i] - mean;
        vs += d * d;
    }
    #pragma unroll
    for (int o = 16; o > 0; o >>= 1) vs += __shfl_xor_sync(~0u, vs, o);
    if ((tid & 31) == 0) red[tid >> 5] = vs;
    __syncthreads();
    if (tid < 32) {
        float v = (tid < 8) ? red[tid] : 0.f;
        #pragma unroll
        for (int o = 4; o > 0; o >>= 1) v += __shfl_xor_sync(~0u, v, o);
        if (tid == 0) red[0] = v;
    }
    __syncthreads();
    float inv = rsqrtf(red[0] / (float)(D - 1));

    #pragma unroll
    for (int i = 0; i < 4; i++) {
        float v = (y[i] - mean) * inv;
        long idx = r * D + tid + i * 256;
        out[idx] = v;
        if constexpr (WHALF)
            oh[idx] = __float2half_rn(v);
    }
}

// ---------------------------------------------------------------------------
static inline void* sym(const void* s) {
    void* p = nullptr;
    cudaGetSymbolAddress(&p, s);
    return p;
}

extern "C" void kernel_launch(void* const* d_in, const int* in_sizes, int n_in,
                              void* d_out, int out_size)
{
    const float* x  = (const float*)d_in[0];
    const float* Wq = (const float*)d_in[1];
    const float* Wk = (const float*)d_in[2];
    const float* Wv = (const float*)d_in[3];
    const float* Wo = (const float*)d_in[4];
    const float* W1 = (const float*)d_in[5];
    const float* b1 = (const float*)d_in[6];
    const float* W2 = (const float*)d_in[7];
    const float* b2 = (const float*)d_in[8];
    float* out = (float*)d_out;

    float* tp = (float*)sym(g_tmp);
    float* o1 = (float*)sym(g_out1);
    float* gm = (float*)sym(g_m);
    float* gil = (float*)sym(g_il);
    bf *xb = (bf*)sym(g_xb);
    bf *wcat = (bf*)sym(g_wcat), *wo = (bf*)sym(g_wo);
    bf *q = (bf*)sym(g_q), *k = (bf*)sym(g_k), *v = (bf*)sym(g_v);
    bf *oc = (bf*)sym(g_oc);
    hf *w1f = (hf*)sym(g_w1f), *w2f = (hf*)sym(g_w2f);
    hf *o1f = (hf*)sym(g_o1f), *fhf = (hf*)sym(g_fhf);

    // BK=64 smem budgets (all need >48KB opt-in; all fit 2 CTAs/SM)
    constexpr int SM_B128 = (128 * 72 + 64 * 136) * 2 * 2;           // 71680
    constexpr int SM_H    = SM_B128;
    constexpr int SM_AT1  = 3 * (128 * 72) * 2;                      // 55296
    constexpr int SM_AT2  = (128 * 72 + 2 * (2 * 128 * 72 + 512)) * 2;  // 94208
    cudaFuncSetAttribute(qkv_gemm,
                         cudaFuncAttributeMaxDynamicSharedMemorySize, SM_B128);
    cudaFuncSetAttribute(bgemm<128, true>,
                         cudaFuncAttributeMaxDynamicSharedMemorySize, SM_B128);
    cudaFuncSetAttribute(hgemm<true, true, false>,
                         cudaFuncAttributeMaxDynamicSharedMemorySize, SM_H);
    cudaFuncSetAttribute(hgemm<true, false, true>,
                         cudaFuncAttributeMaxDynamicSharedMemorySize, SM_H);
    cudaFuncSetAttribute(attn_stats_kernel,
                         cudaFuncAttributeMaxDynamicSharedMemorySize, SM_AT1);
    cudaFuncSetAttribute(attn_out_kernel,
                         cudaFuncAttributeMaxDynamicSharedMemorySize, SM_AT2);

    // 0) one fused conversion launch
    {
        const long total4 = ((long)BB * TT * DD + 3 * (long)HH * DD * DKK +
                             (long)DD * DD + 2 * (long)DD * FFF) / 4;
        cvt_all_kernel<<<(unsigned)((total4 + 255) / 256), 256>>>(
            (const float4*)x, (const float4*)Wq, (const float4*)Wk,
            (const float4*)Wv, (const float4*)Wo, (const float4*)W1,
            (const float4*)W2,
            (uint2*)xb, (uint2*)wcat, (uint2*)wo, (uint2*)w1f, (uint2*)w2f);
    }

    // 1) fused QKV projection: xb[4096,1024] @ wcat[1024,3072]
    {
        dim3 g(3 * HH * DKK / 128, (BB * TT) / 128, 1);   // 24 x 32
        qkv_gemm<<<g, 256, SM_B128>>>(xb, wcat, q, k, v);
    }

    // 2) fused attention
    dim3 gat(TT / 128, BB * HH);
    attn_stats_kernel<<<gat, 256, SM_AT1>>>(q, k, gm, gil);
    attn_out_kernel<<<gat, 256, SM_AT2>>>(q, k, v, gm, gil, oc);

    // 3) tmp = ocat @ Wo (plain bf16, BK=64)
    dim3 gwo(DD / 128, (BB * TT) / 128, 1);
    bgemm<128, true><<<gwo, 256, SM_B128>>>(oc, wo, tp, nullptr,
        DD, DD, DD, DD, 0, 0, 0, 0, 0, 0, 1);

    // 4) out1 = norm(tmp + x), plus fp16 copy for FFN
    add_norm_kernel<true><<<BB * TT, 256>>>(tp, x, o1, o1f);

    // 5) ffh = relu(out1 @ W1 + b1) (fp16, 1 MMA, BK=64)
    dim3 gf1(FFF / 128, (BB * TT) / 128, 1);
    hgemm<true, true, false><<<gf1, 256, SM_H>>>(
        o1f, w1f, nullptr, fhf, b1, DD, DD, FFF, FFF);

    // 6) tmp = ffh @ W2 + b2 (fp16, 1 MMA, BK=64)
    dim3 gf2(DD / 128, (BB * TT) / 128, 1);
    hgemm<true, false, true><<<gf2, 256, SM_H>>>(
        fhf, w2f, tp, nullptr, b2, FFF, FFF, DD, DD);

    // 7) out = norm(tmp + out1)
    add_norm_kernel<false><<<BB * TT, 256>>>(tp, o1, out, nullptr);
}